// round 3
// baseline (speedup 1.0000x reference)
#include <cuda_runtime.h>
#include <cuda_fp16.h>
#include <math.h>

// Fixed shapes
#define Bq 4
#define Sq 1024
#define Dq 256
#define Hq 6
#define HDq 64
#define NHq 384          // H*Hd
#define BSq 4096         // B*S
#define BSDq (BSq*Dq)
#define NEXP 4           // slot 0 = main, 1..3 = deputies

// ---------------- scratch ----------------
__device__ float  g_h  [(size_t)NEXP*BSq*NHq];   // [exp][bs][h*64+o]
__device__ __half g_hh [(size_t)NEXP*BSq*NHq];   // fp16 gather copy
__device__ float  g_h1 [(size_t)NEXP*BSq*NHq];
__device__ float  g_h2 [(size_t)NEXP*BSq*Dq];
__device__ __half g_h2h[(size_t)NEXP*BSq*Dq];
__device__ float  g_es [NEXP*BSq*8];
__device__ float  g_ed [NEXP*BSq*8];
__device__ float  g_hsum [NEXP*Bq*NHq];
__device__ float  g_h2sum[NEXP*Bq*Dq];
__device__ float  g_gs [NEXP*BSq];
__device__ float  g_gd [NEXP*BSq];
__device__ float  g_W1t[NEXP*Dq*NHq];
__device__ float  g_main[BSDq];
__device__ float  g_dep [BSDq];
__device__ float  g_bw  [BSDq];
__device__ float  g_bwsum;
__device__ unsigned char  g_rmask[3*BSq];
__device__ unsigned short g_lst[(size_t)BSq*Sq];
__device__ int g_cnt[BSq*4];

__device__ __forceinline__ float leaky02(float x){ return x > 0.f ? x : 0.2f*x; }
__device__ __forceinline__ float elu1(float x){ return x > 0.f ? x : expm1f(x); }
__device__ __forceinline__ unsigned f2tf(float x){ unsigned u; asm("cvt.rna.tf32.f32 %0, %1;":"=r"(u):"f"(x)); return u; }
__device__ __forceinline__ void mma_tf32(float c[4], unsigned a0,unsigned a1,unsigned a2,unsigned a3,
                                         unsigned b0,unsigned b1){
    asm volatile("mma.sync.aligned.m16n8k8.row.col.f32.tf32.tf32.f32 "
        "{%0,%1,%2,%3},{%4,%5,%6,%7},{%8,%9},{%0,%1,%2,%3};"
        : "+f"(c[0]),"+f"(c[1]),"+f"(c[2]),"+f"(c[3])
        : "r"(a0),"r"(a1),"r"(a2),"r"(a3),"r"(b0),"r"(b1));
}

// ---------------- zero init ----------------
__global__ void k_zero(){
    int i = blockIdx.x*256 + threadIdx.x;
    if (i < BSDq) g_dep[i] = 0.f;
    if (i < NEXP*Bq*NHq) g_hsum[i] = 0.f;
    if (i < NEXP*Bq*Dq)  g_h2sum[i] = 0.f;
    if (i == 0) g_bwsum = 0.f;
}

// ---------------- neighbor lists (one adj pass, sorted, with segment counts) -------
__global__ void k_nbr(const float* __restrict__ adj, const int* __restrict__ dnum,
                      const int* __restrict__ snum){
    __shared__ int sc[256];
    __shared__ int ra[256], rb[256];
    int bs = blockIdx.x, tid = threadIdx.x;
    int doc = dnum[0], sect = snum[0];
    int lim1 = Sq - sect - doc, lim2 = Sq - doc;
    const float* arow = adj + (size_t)bs*Sq;
    float4 a = *(const float4*)(arow + tid*4);
    unsigned short loc[4]; int c=0, ca=0, cb=0;
    float av[4] = {a.x,a.y,a.z,a.w};
    #pragma unroll
    for (int i=0;i<4;i++){
        int col = tid*4+i;
        if (av[i] > 0.f){ loc[c++] = (unsigned short)col; ca += (col<lim1); cb += (col<lim2); }
    }
    sc[tid]=c; ra[tid]=ca; rb[tid]=cb;
    __syncthreads();
    for (int off=1; off<256; off<<=1){
        int v = (tid>=off)? sc[tid-off] : 0;
        __syncthreads();
        sc[tid]+=v;
        __syncthreads();
    }
    int base = sc[tid]-c;
    for (int i=0;i<c;i++) g_lst[(size_t)bs*Sq + base + i] = loc[i];
    for (int st=128; st>0; st>>=1){
        if (tid<st){ ra[tid]+=ra[tid+st]; rb[tid]+=rb[tid+st]; }
        __syncthreads();
    }
    if (tid==0){
        g_cnt[bs*4+0]=ra[0]; g_cnt[bs*4+1]=rb[0]; g_cnt[bs*4+2]=sc[255]; g_cnt[bs*4+3]=0;
    }
}

// ---------------- router ----------------
__global__ void k_router(const float* __restrict__ x, const float* __restrict__ Wr){
    int gw   = (blockIdx.x*blockDim.x + threadIdx.x) >> 5;
    int lane = threadIdx.x & 31;
    if (gw >= BSq) return;
    const float* xr = x + (size_t)gw*Dq;
    float a0=0.f,a1=0.f,a2=0.f;
    for (int k=lane;k<Dq;k+=32){
        float xv = xr[k];
        a0 += xv*Wr[k*3+0]; a1 += xv*Wr[k*3+1]; a2 += xv*Wr[k*3+2];
    }
    #pragma unroll
    for (int o=16;o>0;o>>=1){
        a0 += __shfl_down_sync(0xffffffffu,a0,o);
        a1 += __shfl_down_sync(0xffffffffu,a1,o);
        a2 += __shfl_down_sync(0xffffffffu,a2,o);
    }
    if (lane==0){
        float v[3]={a0,a1,a2};
        int ex=0; float mv=v[0];
        #pragma unroll
        for (int e=1;e<3;e++) if (v[e]<=mv){ mv=v[e]; ex=e; }
        #pragma unroll
        for (int e=0;e<3;e++) g_rmask[e*BSq+gw] = (e==ex)?0:1;
    }
}

// ---------------- transpose W1 -> [exp][k][h*64+o] ----------------
__global__ void k_prepw(const float* __restrict__ mainW1, const float* __restrict__ depW1){
    int e = blockIdx.y;
    int i = blockIdx.x*256 + threadIdx.x;
    const float* src = (e==0)? mainW1 : depW1 + (size_t)(e-1)*Hq*Dq*HDq;
    int k = i/NHq, n = i%NHq, h = n>>6, o = n&63;
    g_W1t[(size_t)e*Dq*NHq + i] = src[(size_t)h*Dq*HDq + (size_t)k*HDq + o];
}

// ---------------- tf32 GEMM, single-sync double buffered; optional fp16 copy out ----
template<int KD, int ND, bool MASK>
__global__ void __launch_bounds__(256) k_mm(const float* __restrict__ Abase, size_t astride,
                                            const float* __restrict__ Bmain,
                                            const float* __restrict__ Bdep, size_t bstride,
                                            float* __restrict__ Cbase, __half* __restrict__ Chbase){
    int e = blockIdx.z;
    const float* A = Abase + astride*e;
    const float* B = (e==0)? Bmain : Bdep + bstride*(e-1);
    float* C = Cbase + (size_t)e*BSq*ND;
    __half* Ch = Chbase ? Chbase + (size_t)e*BSq*ND : (__half*)0;
    int m0 = blockIdx.y*128, n0 = blockIdx.x*128;
    __shared__ unsigned As[2][128][17];
    __shared__ unsigned Bs[2][16][132];
    int tid=threadIdx.x, lane=tid&31, wid=tid>>5;
    int wm=(wid&1)*64, wn=(wid>>1)*32;
    int gid=lane>>2, qid=lane&3;
    float c[4][4][4];
    #pragma unroll
    for (int mt=0;mt<4;mt++)
        #pragma unroll
        for (int nt=0;nt<4;nt++)
            #pragma unroll
            for (int r=0;r<4;r++) c[mt][nt][r]=0.f;
    int arow=tid>>1, acol=(tid&1)*8;
    int brow=tid>>4, bcol=(tid&15)*8;
    float am = 1.f;
    if (MASK){ if (e>0 && g_rmask[(size_t)(e-1)*BSq + m0 + arow]==0) am = 0.f; }
    const float* Ap = A + (size_t)(m0+arow)*KD + acol;
    const float* Bp = B + (size_t)brow*ND + n0+bcol;

    float4 a0,a1,b0,b1;
#define LDREGS(K0) { a0 = *(const float4*)(Ap + (K0)); a1 = *(const float4*)(Ap + (K0)+4); \
                     b0 = *(const float4*)(Bp + (size_t)(K0)*ND); b1 = *(const float4*)(Bp + (size_t)(K0)*ND + 4); }
#define STREGS(P) { As[P][arow][acol+0]=f2tf(a0.x*am); As[P][arow][acol+1]=f2tf(a0.y*am); \
                    As[P][arow][acol+2]=f2tf(a0.z*am); As[P][arow][acol+3]=f2tf(a0.w*am); \
                    As[P][arow][acol+4]=f2tf(a1.x*am); As[P][arow][acol+5]=f2tf(a1.y*am); \
                    As[P][arow][acol+6]=f2tf(a1.z*am); As[P][arow][acol+7]=f2tf(a1.w*am); \
                    Bs[P][brow][bcol+0]=f2tf(b0.x); Bs[P][brow][bcol+1]=f2tf(b0.y); \
                    Bs[P][brow][bcol+2]=f2tf(b0.z); Bs[P][brow][bcol+3]=f2tf(b0.w); \
                    Bs[P][brow][bcol+4]=f2tf(b1.x); Bs[P][brow][bcol+5]=f2tf(b1.y); \
                    Bs[P][brow][bcol+6]=f2tf(b1.z); Bs[P][brow][bcol+7]=f2tf(b1.w); }
#define COMPUTE(P) { _Pragma("unroll") \
    for (int kk=0;kk<16;kk+=8){ \
        unsigned af[4][4], bf[4][2]; \
        _Pragma("unroll") \
        for (int mt=0;mt<4;mt++){ int r = wm + mt*16 + gid; \
            af[mt][0]=As[P][r][kk+qid];   af[mt][1]=As[P][r+8][kk+qid]; \
            af[mt][2]=As[P][r][kk+qid+4]; af[mt][3]=As[P][r+8][kk+qid+4]; } \
        _Pragma("unroll") \
        for (int nt=0;nt<4;nt++){ int cc = wn + nt*8 + gid; \
            bf[nt][0]=Bs[P][kk+qid][cc]; bf[nt][1]=Bs[P][kk+qid+4][cc]; } \
        _Pragma("unroll") \
        for (int mt=0;mt<4;mt++) \
            _Pragma("unroll") \
            for (int nt=0;nt<4;nt++) \
                mma_tf32(c[mt][nt], af[mt][0],af[mt][1],af[mt][2],af[mt][3], bf[nt][0],bf[nt][1]); } }

    LDREGS(0);
    STREGS(0);
    __syncthreads();
    int p = 0;
    #pragma unroll 2
    for (int it=1; it<KD/16; it++){
        LDREGS(it*16);
        COMPUTE(p);
        STREGS(1-p);
        __syncthreads();
        p ^= 1;
    }
    COMPUTE(p);
#undef LDREGS
#undef STREGS
#undef COMPUTE
    #pragma unroll
    for (int mt=0;mt<4;mt++){
        int row = m0 + wm + mt*16 + gid;
        #pragma unroll
        for (int nt=0;nt<4;nt++){
            int col = n0 + wn + nt*8 + qid*2;
            float2 v0 = make_float2(c[mt][nt][0], c[mt][nt][1]);
            float2 v1 = make_float2(c[mt][nt][2], c[mt][nt][3]);
            *(float2*)&C[(size_t)row*ND + col]     = v0;
            *(float2*)&C[(size_t)(row+8)*ND + col] = v1;
            if (Ch){
                *(__half2*)&Ch[(size_t)row*ND + col]     = __float22half2_rn(v0);
                *(__half2*)&Ch[(size_t)(row+8)*ND + col] = __float22half2_rn(v1);
            }
        }
    }
}

// ---------------- sigmoid + mean accumulation ----------------
__global__ void k_sig(const float* __restrict__ bias){
    __shared__ float red[256];
    int i = blockIdx.x*256 + threadIdx.x;
    float v = 1.f/(1.f + expf(-(g_bw[i] + bias[i & (Dq-1)])));
    g_bw[i] = v;
    red[threadIdx.x] = v;
    __syncthreads();
    for (int st=128; st>0; st>>=1){ if (threadIdx.x<st) red[threadIdx.x]+=red[threadIdx.x+st]; __syncthreads(); }
    if (threadIdx.x==0) atomicAdd(&g_bwsum, red[0]);
}

// ---------------- es/ed per (exp,bs,h) ----------------
__global__ void k_esed(const float* __restrict__ a1s_m, const float* __restrict__ a1d_m,
                       const float* __restrict__ a1s_d, const float* __restrict__ a1d_d){
    int gw   = (blockIdx.x*blockDim.x + threadIdx.x) >> 5;
    int lane = threadIdx.x & 31;
    if (gw >= NEXP*BSq*Hq) return;
    int h = gw % Hq, be = gw / Hq;
    int e = be / BSq;
    const float* as = ((e==0)? a1s_m : a1s_d + (size_t)(e-1)*NHq) + h*HDq;
    const float* ad = ((e==0)? a1d_m : a1d_d + (size_t)(e-1)*NHq) + h*HDq;
    const float* hr = g_h + (size_t)be*NHq + h*HDq;
    float s=0.f, d=0.f;
    #pragma unroll
    for (int o=lane;o<HDq;o+=32){
        float v = hr[o];
        s += v*as[o]; d += v*ad[o];
    }
    #pragma unroll
    for (int o=16;o>0;o>>=1){
        s += __shfl_down_sync(0xffffffffu,s,o);
        d += __shfl_down_sync(0xffffffffu,d,o);
    }
    if (lane==0){ g_es[be*8+h]=s; g_ed[be*8+h]=d; }
}

// ---------------- hsum (deputies only, chunked + atomic) ----------------
__global__ void k_hsum(){
    int eb = blockIdx.x + Bq;            // skip expert 0 (always has self-loop)
    int chunk = blockIdx.y;
    int e = eb>>2, b = eb&3;
    const float* base = g_h + ((size_t)e*BSq + ((size_t)b<<10) + chunk*128)*NHq;
    int t = threadIdx.x;
    float acc = 0.f;
    for (int s=0;s<128;s++) acc += base[(size_t)s*NHq + t];
    atomicAdd(&g_hsum[(size_t)eb*NHq + t], acc);
}

// ---------------- attention layer 1 (6 heads, fp16 gather) ----------------
__global__ void __launch_bounds__(128) k_att1(){
    __shared__ unsigned short lst[1024];
    __shared__ unsigned char  ok[1024];
    __shared__ float w[6*1024];
    __shared__ float red[6*128];
    __shared__ float es6[6];
    int bs = blockIdx.x, ex = blockIdx.y, b = bs>>10;
    int tid = threadIdx.x;
    int c1 = g_cnt[bs*4+0], c2 = g_cnt[bs*4+1], ct = g_cnt[bs*4+2];
    int lo, hi;
    if      (ex==0){ lo=0;  hi=ct; }
    else if (ex==1){ lo=0;  hi=c1; }
    else if (ex==2){ lo=c1; hi=c2; }
    else           { lo=c2; hi=ct; }
    int n = hi-lo;
    float* h1row = g_h1 + ((size_t)ex*BSq + bs)*NHq;
    if (n==0){
        if (tid<96){
            float4 hv = *(const float4*)&g_hsum[(size_t)((ex<<2)|b)*NHq + tid*4];
            float4 o;
            o.x=elu1(hv.x*(1.f/Sq)); o.y=elu1(hv.y*(1.f/Sq));
            o.z=elu1(hv.z*(1.f/Sq)); o.w=elu1(hv.w*(1.f/Sq));
            *(float4*)&h1row[tid*4]=o;
        }
        return;
    }
    for (int j=tid;j<n;j+=128) lst[j] = g_lst[(size_t)bs*Sq + lo + j];
    if (tid<6) es6[tid] = g_es[((size_t)ex*BSq + bs)*8 + tid];
    __syncthreads();
    const float* edb = g_ed + ((size_t)ex*BSq + ((size_t)b<<10))*8;
    const unsigned char* rm = (ex>0)? g_rmask + (size_t)(ex-1)*BSq + (b<<10) : nullptr;
    float mx[6];
    #pragma unroll
    for (int h=0;h<6;h++) mx[h] = -1e30f;
    for (int j=tid;j<n;j+=128){
        int nb = lst[j];
        float4 e0 = *(const float4*)&edb[nb*8];
        float2 e1 = *(const float2*)&edb[nb*8+4];
        ok[j] = rm ? rm[nb] : 1;
        float ev[6] = {e0.x,e0.y,e0.z,e0.w,e1.x,e1.y};
        #pragma unroll
        for (int h=0;h<6;h++){
            float e = leaky02(es6[h] + ev[h]);
            w[h*1024+j] = e;
            mx[h] = fmaxf(mx[h], e);
        }
    }
    #pragma unroll
    for (int h=0;h<6;h++) red[h*128+tid]=mx[h];
    __syncthreads();
    for (int st=64;st>0;st>>=1){
        if (tid<st){
            #pragma unroll
            for (int h=0;h<6;h++) red[h*128+tid]=fmaxf(red[h*128+tid], red[h*128+tid+st]);
        }
        __syncthreads();
    }
    float mxv[6];
    #pragma unroll
    for (int h=0;h<6;h++) mxv[h]=red[h*128];
    __syncthreads();
    float sm[6] = {0.f,0.f,0.f,0.f,0.f,0.f};
    for (int j=tid;j<n;j+=128){
        #pragma unroll
        for (int h=0;h<6;h++){
            float ww = expf(w[h*1024+j]-mxv[h]);
            w[h*1024+j]=ww;
            sm[h]+=ww;
        }
    }
    #pragma unroll
    for (int h=0;h<6;h++) red[h*128+tid]=sm[h];
    __syncthreads();
    for (int st=64;st>0;st>>=1){
        if (tid<st){
            #pragma unroll
            for (int h=0;h<6;h++) red[h*128+tid]+=red[h*128+tid+st];
        }
        __syncthreads();
    }
    if (tid<96){
        int h = tid>>4;
        float inv = 1.f/red[h*128];
        const __half* hb = g_hh + ((size_t)ex*BSq + ((size_t)b<<10))*NHq;
        float ax=0.f, ay=0.f, az=0.f, aw=0.f;
        for (int j=0;j<n;j++){
            if (!ok[j]) continue;
            float wv = w[h*1024+j];
            uint2 raw = *(const uint2*)&hb[(size_t)lst[j]*NHq + tid*4];
            float2 p0 = __half22float2(*(__half2*)&raw.x);
            float2 p1 = __half22float2(*(__half2*)&raw.y);
            ax += wv*p0.x; ay += wv*p0.y; az += wv*p1.x; aw += wv*p1.y;
        }
        float4 o;
        o.x=elu1(ax*inv); o.y=elu1(ay*inv); o.z=elu1(az*inv); o.w=elu1(aw*inv);
        *(float4*)&h1row[tid*4]=o;
    }
}

// ---------------- gs/gd per (exp,bs) ----------------
__global__ void k_gsgd(const float* __restrict__ a2s_m, const float* __restrict__ a2d_m,
                       const float* __restrict__ a2s_d, const float* __restrict__ a2d_d){
    int gw   = (blockIdx.x*blockDim.x + threadIdx.x) >> 5;
    int lane = threadIdx.x & 31;
    if (gw >= NEXP*BSq) return;
    int e = gw / BSq;
    const float* as = (e==0)? a2s_m : a2s_d + (size_t)(e-1)*Dq;
    const float* ad = (e==0)? a2d_m : a2d_d + (size_t)(e-1)*Dq;
    const float* hr = g_h2 + (size_t)gw*Dq;
    float s=0.f, d=0.f;
    #pragma unroll
    for (int k=lane;k<Dq;k+=32){
        float v = hr[k];
        s += v*as[k]; d += v*ad[k];
    }
    #pragma unroll
    for (int o=16;o>0;o>>=1){
        s += __shfl_down_sync(0xffffffffu,s,o);
        d += __shfl_down_sync(0xffffffffu,d,o);
    }
    if (lane==0){ g_gs[gw]=s; g_gd[gw]=d; }
}

// ---------------- h2sum (deputies only, chunked + atomic) ----------------
__global__ void k_h2sum(){
    int eb = blockIdx.x + Bq;
    int chunk = blockIdx.y;
    int e = eb>>2, b = eb&3;
    const float* base = g_h2 + ((size_t)e*BSq + ((size_t)b<<10) + chunk*128)*Dq;
    int t = threadIdx.x;
    float acc = 0.f;
    for (int s=0;s<128;s++) acc += base[(size_t)s*Dq + t];
    atomicAdd(&g_h2sum[(size_t)eb*Dq + t], acc);
}

// ---------------- attention layer 2 (fp16 gather) ----------------
__global__ void __launch_bounds__(256) k_att2(){
    __shared__ unsigned short lst[1024];
    __shared__ float w[1024];
    __shared__ float red[256];
    __shared__ float4 sacc[4][64];
    int bs = blockIdx.x, ex = blockIdx.y, b = bs>>10;
    int tid = threadIdx.x;
    if (ex>0 && g_rmask[(size_t)(ex-1)*BSq + bs]==0) return;
    int c1 = g_cnt[bs*4+0], c2 = g_cnt[bs*4+1], ct = g_cnt[bs*4+2];
    int lo, hi;
    if      (ex==0){ lo=0;  hi=ct; }
    else if (ex==1){ lo=0;  hi=c1; }
    else if (ex==2){ lo=c1; hi=c2; }
    else           { lo=c2; hi=ct; }
    int n = hi-lo;
    if (n==0){
        if (tid<64){
            float4 hv = *(const float4*)&g_h2sum[(size_t)((ex<<2)|b)*Dq + tid*4];
            float4 o = make_float4(hv.x*(1.f/Sq), hv.y*(1.f/Sq), hv.z*(1.f/Sq), hv.w*(1.f/Sq));
            if (ex==0) *(float4*)&g_main[(size_t)bs*Dq + tid*4] = o;
            else {
                float* dp = &g_dep[(size_t)bs*Dq + tid*4];
                atomicAdd(dp+0,o.x); atomicAdd(dp+1,o.y); atomicAdd(dp+2,o.z); atomicAdd(dp+3,o.w);
            }
        }
        return;
    }
    for (int j=tid;j<n;j+=256) lst[j] = g_lst[(size_t)bs*Sq + lo + j];
    __syncthreads();
    float gsv = g_gs[(size_t)ex*BSq + bs];
    const float* gdb = g_gd + (size_t)ex*BSq + (b<<10);
    float mloc = -1e30f;
    for (int j=tid;j<n;j+=256){
        float e = leaky02(gsv + gdb[lst[j]]);
        w[j]=e;
        mloc = fmaxf(mloc,e);
    }
    red[tid]=mloc; __syncthreads();
    for (int st=128;st>0;st>>=1){ if (tid<st) red[tid]=fmaxf(red[tid],red[tid+st]); __syncthreads(); }
    float m = red[0]; __syncthreads();
    float sloc = 0.f;
    for (int j=tid;j<n;j+=256){ float ww=expf(w[j]-m); w[j]=ww; sloc+=ww; }
    red[tid]=sloc; __syncthreads();
    for (int st=128;st>0;st>>=1){ if (tid<st) red[tid]+=red[tid+st]; __syncthreads(); }
    float inv = 1.f/red[0];
    int grp = tid>>6, q = tid&63;
    const __half* h2b = g_h2h + ((size_t)ex*BSq + ((size_t)b<<10))*Dq;
    float ax=0.f, ay=0.f, az=0.f, aw=0.f;
    for (int j=grp;j<n;j+=4){
        float wv = w[j];
        uint2 raw = *(const uint2*)&h2b[(size_t)lst[j]*Dq + q*4];
        float2 p0 = __half22float2(*(__half2*)&raw.x);
        float2 p1 = __half22float2(*(__half2*)&raw.y);
        ax += wv*p0.x; ay += wv*p0.y; az += wv*p1.x; aw += wv*p1.y;
    }
    sacc[grp][q] = make_float4(ax,ay,az,aw);
    __syncthreads();
    if (tid<64){
        float4 a0=sacc[0][tid], a1=sacc[1][tid], a2=sacc[2][tid], a3=sacc[3][tid];
        float4 o = make_float4((a0.x+a1.x+a2.x+a3.x)*inv, (a0.y+a1.y+a2.y+a3.y)*inv,
                               (a0.z+a1.z+a2.z+a3.z)*inv, (a0.w+a1.w+a2.w+a3.w)*inv);
        if (ex==0) *(float4*)&g_main[(size_t)bs*Dq + tid*4] = o;
        else {
            float* dp = &g_dep[(size_t)bs*Dq + tid*4];
            atomicAdd(dp+0,o.x); atomicAdd(dp+1,o.y); atomicAdd(dp+2,o.z); atomicAdd(dp+3,o.w);
        }
    }
}

// ---------------- final blend + scalars ----------------
__global__ void k_final(float* __restrict__ out){
    size_t i = (size_t)blockIdx.x*256 + threadIdx.x;
    if (i < BSDq){
        float bw = g_bw[i];
        out[i] = bw*g_main[i] + (1.f-bw)*g_dep[i];
    }
    if (i == 0){
        float mc = g_bwsum * (1.f/(float)BSDq);
        out[BSDq]   = fabsf(mc - 0.6f) * 0.01f;
        out[BSDq+1] = mc;
    }
}

// ---------------- host launcher ----------------
extern "C" void kernel_launch(void* const* d_in, const int* in_sizes, int n_in,
                              void* d_out, int out_size){
    const float* feature  = (const float*)d_in[0];
    const float* adj      = (const float*)d_in[1];
    const float* main_W1  = (const float*)d_in[2];
    const float* main_a1s = (const float*)d_in[3];
    const float* main_a1d = (const float*)d_in[4];
    const float* main_W2  = (const float*)d_in[5];
    const float* main_a2s = (const float*)d_in[6];
    const float* main_a2d = (const float*)d_in[7];
    const float* dep_W1   = (const float*)d_in[8];
    const float* dep_a1s  = (const float*)d_in[9];
    const float* dep_a1d  = (const float*)d_in[10];
    const float* dep_W2   = (const float*)d_in[11];
    const float* dep_a2s  = (const float*)d_in[12];
    const float* dep_a2d  = (const float*)d_in[13];
    const float* router_W = (const float*)d_in[14];
    const float* blend_W  = (const float*)d_in[15];
    const float* blend_b  = (const float*)d_in[16];
    const int*   doc_num  = (const int*)d_in[17];
    const int*   sect_num = (const int*)d_in[18];
    float* out = (float*)d_out;

    float* g_W1t_p;  cudaGetSymbolAddress((void**)&g_W1t_p,  g_W1t);
    float* g_h1_p;   cudaGetSymbolAddress((void**)&g_h1_p,   g_h1);
    float* g_h_p;    cudaGetSymbolAddress((void**)&g_h_p,    g_h);
    float* g_h2_p;   cudaGetSymbolAddress((void**)&g_h2_p,   g_h2);
    float* g_bw_p;   cudaGetSymbolAddress((void**)&g_bw_p,   g_bw);
    __half* g_hh_p;  cudaGetSymbolAddress((void**)&g_hh_p,   g_hh);
    __half* g_h2h_p; cudaGetSymbolAddress((void**)&g_h2h_p,  g_h2h);

    k_zero<<<(BSDq+255)/256, 256>>>();
    k_nbr<<<BSq, 256>>>(adj, doc_num, sect_num);
    k_router<<<BSq/4, 128>>>(feature, router_W);
    k_prepw<<<dim3(Dq*NHq/256, NEXP), 256>>>(main_W1, dep_W1);

    k_mm<Dq, Dq, false><<<dim3(2,32,1), 256>>>(feature, 0, blend_W, blend_W, 0, g_bw_p, (__half*)0);
    k_sig<<<BSDq/256, 256>>>(blend_b);

    k_mm<Dq, NHq, true><<<dim3(3,32,NEXP), 256>>>(feature, 0, g_W1t_p,
                                                  g_W1t_p + (size_t)Dq*NHq, (size_t)Dq*NHq,
                                                  g_h_p, g_hh_p);
    k_esed<<<(NEXP*BSq*Hq)/8, 256>>>(main_a1s, main_a1d, dep_a1s, dep_a1d);
    k_hsum<<<dim3((NEXP-1)*Bq, 8), NHq>>>();
    k_att1<<<dim3(BSq, NEXP), 128>>>();

    k_mm<NHq, Dq, false><<<dim3(2,32,NEXP), 256>>>(g_h1_p, (size_t)BSq*NHq, main_W2,
                                                   dep_W2, (size_t)NHq*Dq, g_h2_p, g_h2h_p);
    k_gsgd<<<(NEXP*BSq)/8, 256>>>(main_a2s, main_a2d, dep_a2s, dep_a2d);
    k_h2sum<<<dim3((NEXP-1)*Bq, 8), Dq>>>();
    k_att2<<<dim3(BSq, NEXP), 256>>>();

    k_final<<<(BSDq+255)/256, 256>>>(out);
}

// round 4
// speedup vs baseline: 1.4702x; 1.4702x over previous
#include <cuda_runtime.h>
#include <cuda_fp16.h>
#include <math.h>

// Fixed shapes
#define Bq 4
#define Sq 1024
#define Dq 256
#define Hq 6
#define HDq 64
#define NHq 384          // H*Hd
#define BSq 4096         // B*S
#define BSDq (BSq*Dq)
#define NEXP 4           // slot 0 = main, 1..3 = deputies

// ---------------- scratch ----------------
__device__ float  g_h  [(size_t)NEXP*BSq*NHq];   // [exp][bs][h*64+o]
__device__ __half g_hh [(size_t)NEXP*BSq*NHq];   // fp16 gather copy
__device__ float  g_h1 [(size_t)NEXP*BSq*NHq];
__device__ float  g_h2 [(size_t)NEXP*BSq*Dq];
__device__ __half g_h2h[(size_t)NEXP*BSq*Dq];
__device__ float  g_es [NEXP*BSq*8];
__device__ float  g_ed [NEXP*BSq*8];
__device__ float  g_hsum [NEXP*Bq*NHq];
__device__ float  g_h2sum[NEXP*Bq*Dq];
__device__ float  g_gs [NEXP*BSq];
__device__ float  g_gd [NEXP*BSq];
__device__ float  g_W1t[NEXP*Dq*NHq];
__device__ float  g_main[BSDq];
__device__ float  g_dep [BSDq];
__device__ float  g_bw  [BSDq];
__device__ float  g_bwsum;
__device__ unsigned char  g_rmask[3*BSq];
__device__ unsigned short g_lst[(size_t)BSq*Sq];
__device__ int g_cnt[BSq*4];

__device__ __forceinline__ float leaky02(float x){ return x > 0.f ? x : 0.2f*x; }
__device__ __forceinline__ float elu1(float x){ return x > 0.f ? x : expm1f(x); }
__device__ __forceinline__ unsigned f2tf(float x){ unsigned u; asm("cvt.rna.tf32.f32 %0, %1;":"=r"(u):"f"(x)); return u; }
__device__ __forceinline__ void mma_tf32(float c[4], unsigned a0,unsigned a1,unsigned a2,unsigned a3,
                                         unsigned b0,unsigned b1){
    asm volatile("mma.sync.aligned.m16n8k8.row.col.f32.tf32.tf32.f32 "
        "{%0,%1,%2,%3},{%4,%5,%6,%7},{%8,%9},{%0,%1,%2,%3};"
        : "+f"(c[0]),"+f"(c[1]),"+f"(c[2]),"+f"(c[3])
        : "r"(a0),"r"(a1),"r"(a2),"r"(a3),"r"(b0),"r"(b1));
}

// ---------------- zero init ----------------
__global__ void k_zero(){
    int i = blockIdx.x*256 + threadIdx.x;
    if (i < BSDq) g_dep[i] = 0.f;
    if (i < NEXP*Bq*NHq) g_hsum[i] = 0.f;
    if (i < NEXP*Bq*Dq)  g_h2sum[i] = 0.f;
    if (i == 0) g_bwsum = 0.f;
}

// ---------------- neighbor lists (one adj pass, sorted, with segment counts) -------
__global__ void k_nbr(const float* __restrict__ adj, const int* __restrict__ dnum,
                      const int* __restrict__ snum){
    __shared__ int sc[256];
    __shared__ int ra[256], rb[256];
    int bs = blockIdx.x, tid = threadIdx.x;
    int doc = dnum[0], sect = snum[0];
    int lim1 = Sq - sect - doc, lim2 = Sq - doc;
    const float* arow = adj + (size_t)bs*Sq;
    float4 a = *(const float4*)(arow + tid*4);
    unsigned short loc[4]; int c=0, ca=0, cb=0;
    float av[4] = {a.x,a.y,a.z,a.w};
    #pragma unroll
    for (int i=0;i<4;i++){
        int col = tid*4+i;
        if (av[i] > 0.f){ loc[c++] = (unsigned short)col; ca += (col<lim1); cb += (col<lim2); }
    }
    sc[tid]=c; ra[tid]=ca; rb[tid]=cb;
    __syncthreads();
    for (int off=1; off<256; off<<=1){
        int v = (tid>=off)? sc[tid-off] : 0;
        __syncthreads();
        sc[tid]+=v;
        __syncthreads();
    }
    int base = sc[tid]-c;
    for (int i=0;i<c;i++) g_lst[(size_t)bs*Sq + base + i] = loc[i];
    for (int st=128; st>0; st>>=1){
        if (tid<st){ ra[tid]+=ra[tid+st]; rb[tid]+=rb[tid+st]; }
        __syncthreads();
    }
    if (tid==0){
        g_cnt[bs*4+0]=ra[0]; g_cnt[bs*4+1]=rb[0]; g_cnt[bs*4+2]=sc[255]; g_cnt[bs*4+3]=0;
    }
}

// ---------------- router ----------------
__global__ void k_router(const float* __restrict__ x, const float* __restrict__ Wr){
    int gw   = (blockIdx.x*blockDim.x + threadIdx.x) >> 5;
    int lane = threadIdx.x & 31;
    if (gw >= BSq) return;
    const float* xr = x + (size_t)gw*Dq;
    float a0=0.f,a1=0.f,a2=0.f;
    for (int k=lane;k<Dq;k+=32){
        float xv = xr[k];
        a0 += xv*Wr[k*3+0]; a1 += xv*Wr[k*3+1]; a2 += xv*Wr[k*3+2];
    }
    #pragma unroll
    for (int o=16;o>0;o>>=1){
        a0 += __shfl_down_sync(0xffffffffu,a0,o);
        a1 += __shfl_down_sync(0xffffffffu,a1,o);
        a2 += __shfl_down_sync(0xffffffffu,a2,o);
    }
    if (lane==0){
        float v[3]={a0,a1,a2};
        int ex=0; float mv=v[0];
        #pragma unroll
        for (int e=1;e<3;e++) if (v[e]<=mv){ mv=v[e]; ex=e; }
        #pragma unroll
        for (int e=0;e<3;e++) g_rmask[e*BSq+gw] = (e==ex)?0:1;
    }
}

// ---------------- transpose W1 -> [exp][k][h*64+o] ----------------
__global__ void k_prepw(const float* __restrict__ mainW1, const float* __restrict__ depW1){
    int e = blockIdx.y;
    int i = blockIdx.x*256 + threadIdx.x;
    const float* src = (e==0)? mainW1 : depW1 + (size_t)(e-1)*Hq*Dq*HDq;
    int k = i/NHq, n = i%NHq, h = n>>6, o = n&63;
    g_W1t[(size_t)e*Dq*NHq + i] = src[(size_t)h*Dq*HDq + (size_t)k*HDq + o];
}

// ---------------- tf32 tensor-core GEMM (R2-proven 2-sync structure) + fp16 copy ----
template<int KD, int ND, bool MASK>
__global__ void __launch_bounds__(256) k_mm(const float* __restrict__ Abase, size_t astride,
                                            const float* __restrict__ Bmain,
                                            const float* __restrict__ Bdep, size_t bstride,
                                            float* __restrict__ Cbase, __half* __restrict__ Chbase){
    int e = blockIdx.z;
    const float* A = Abase + astride*e;
    const float* B = (e==0)? Bmain : Bdep + bstride*(e-1);
    float* C = Cbase + (size_t)e*BSq*ND;
    __half* Ch = Chbase ? Chbase + (size_t)e*BSq*ND : (__half*)0;
    int m0 = blockIdx.y*128, n0 = blockIdx.x*128;
    __shared__ unsigned As[128][17];
    __shared__ unsigned Bs[16][132];
    int tid=threadIdx.x, lane=tid&31, wid=tid>>5;
    int wm=(wid&1)*64, wn=(wid>>1)*32;
    int gid=lane>>2, qid=lane&3;
    float c[4][4][4];
    #pragma unroll
    for (int mt=0;mt<4;mt++)
        #pragma unroll
        for (int nt=0;nt<4;nt++)
            #pragma unroll
            for (int r=0;r<4;r++) c[mt][nt][r]=0.f;
    int arow=tid>>1, acol=(tid&1)*8;
    int brow=tid>>4, bcol=(tid&15)*8;
    float am = 1.f;
    if (MASK){ if (e>0 && g_rmask[(size_t)(e-1)*BSq + m0 + arow]==0) am = 0.f; }
    for (int k0=0;k0<KD;k0+=16){
        float4 a0 = *(const float4*)(A + (size_t)(m0+arow)*KD + k0+acol);
        float4 a1 = *(const float4*)(A + (size_t)(m0+arow)*KD + k0+acol+4);
        float4 b0 = *(const float4*)(B + (size_t)(k0+brow)*ND + n0+bcol);
        float4 b1 = *(const float4*)(B + (size_t)(k0+brow)*ND + n0+bcol+4);
        __syncthreads();
        As[arow][acol+0]=f2tf(a0.x*am); As[arow][acol+1]=f2tf(a0.y*am);
        As[arow][acol+2]=f2tf(a0.z*am); As[arow][acol+3]=f2tf(a0.w*am);
        As[arow][acol+4]=f2tf(a1.x*am); As[arow][acol+5]=f2tf(a1.y*am);
        As[arow][acol+6]=f2tf(a1.z*am); As[arow][acol+7]=f2tf(a1.w*am);
        Bs[brow][bcol+0]=f2tf(b0.x); Bs[brow][bcol+1]=f2tf(b0.y);
        Bs[brow][bcol+2]=f2tf(b0.z); Bs[brow][bcol+3]=f2tf(b0.w);
        Bs[brow][bcol+4]=f2tf(b1.x); Bs[brow][bcol+5]=f2tf(b1.y);
        Bs[brow][bcol+6]=f2tf(b1.z); Bs[brow][bcol+7]=f2tf(b1.w);
        __syncthreads();
        #pragma unroll
        for (int kk=0;kk<16;kk+=8){
            unsigned af[4][4], bf[4][2];
            #pragma unroll
            for (int mt=0;mt<4;mt++){
                int r = wm + mt*16 + gid;
                af[mt][0]=As[r][kk+qid];   af[mt][1]=As[r+8][kk+qid];
                af[mt][2]=As[r][kk+qid+4]; af[mt][3]=As[r+8][kk+qid+4];
            }
            #pragma unroll
            for (int nt=0;nt<4;nt++){
                int cc = wn + nt*8 + gid;
                bf[nt][0]=Bs[kk+qid][cc]; bf[nt][1]=Bs[kk+qid+4][cc];
            }
            #pragma unroll
            for (int mt=0;mt<4;mt++)
                #pragma unroll
                for (int nt=0;nt<4;nt++)
                    mma_tf32(c[mt][nt], af[mt][0],af[mt][1],af[mt][2],af[mt][3],
                             bf[nt][0],bf[nt][1]);
        }
    }
    #pragma unroll
    for (int mt=0;mt<4;mt++){
        int row = m0 + wm + mt*16 + gid;
        #pragma unroll
        for (int nt=0;nt<4;nt++){
            int col = n0 + wn + nt*8 + qid*2;
            float2 v0 = make_float2(c[mt][nt][0], c[mt][nt][1]);
            float2 v1 = make_float2(c[mt][nt][2], c[mt][nt][3]);
            *(float2*)&C[(size_t)row*ND + col]     = v0;
            *(float2*)&C[(size_t)(row+8)*ND + col] = v1;
            if (Ch){
                *(__half2*)&Ch[(size_t)row*ND + col]     = __float22half2_rn(v0);
                *(__half2*)&Ch[(size_t)(row+8)*ND + col] = __float22half2_rn(v1);
            }
        }
    }
}

// ---------------- sigmoid + mean accumulation ----------------
__global__ void k_sig(const float* __restrict__ bias){
    __shared__ float red[256];
    int i = blockIdx.x*256 + threadIdx.x;
    float v = 1.f/(1.f + expf(-(g_bw[i] + bias[i & (Dq-1)])));
    g_bw[i] = v;
    red[threadIdx.x] = v;
    __syncthreads();
    for (int st=128; st>0; st>>=1){ if (threadIdx.x<st) red[threadIdx.x]+=red[threadIdx.x+st]; __syncthreads(); }
    if (threadIdx.x==0) atomicAdd(&g_bwsum, red[0]);
}

// ---------------- es/ed per (exp,bs,h) ----------------
__global__ void k_esed(const float* __restrict__ a1s_m, const float* __restrict__ a1d_m,
                       const float* __restrict__ a1s_d, const float* __restrict__ a1d_d){
    int gw   = (blockIdx.x*blockDim.x + threadIdx.x) >> 5;
    int lane = threadIdx.x & 31;
    if (gw >= NEXP*BSq*Hq) return;
    int h = gw % Hq, be = gw / Hq;
    int e = be / BSq;
    const float* as = ((e==0)? a1s_m : a1s_d + (size_t)(e-1)*NHq) + h*HDq;
    const float* ad = ((e==0)? a1d_m : a1d_d + (size_t)(e-1)*NHq) + h*HDq;
    const float* hr = g_h + (size_t)be*NHq + h*HDq;
    float s=0.f, d=0.f;
    #pragma unroll
    for (int o=lane;o<HDq;o+=32){
        float v = hr[o];
        s += v*as[o]; d += v*ad[o];
    }
    #pragma unroll
    for (int o=16;o>0;o>>=1){
        s += __shfl_down_sync(0xffffffffu,s,o);
        d += __shfl_down_sync(0xffffffffu,d,o);
    }
    if (lane==0){ g_es[be*8+h]=s; g_ed[be*8+h]=d; }
}

// ---------------- hsum (deputies only, chunked + atomic) ----------------
__global__ void k_hsum(){
    int eb = blockIdx.x + Bq;            // skip expert 0 (always has self-loop)
    int chunk = blockIdx.y;
    int e = eb>>2, b = eb&3;
    const float* base = g_h + ((size_t)e*BSq + ((size_t)b<<10) + chunk*128)*NHq;
    int t = threadIdx.x;
    float acc = 0.f;
    for (int s=0;s<128;s++) acc += base[(size_t)s*NHq + t];
    atomicAdd(&g_hsum[(size_t)eb*NHq + t], acc);
}

// ---------------- attention layer 1 (6 heads, fp16 gather) ----------------
__global__ void __launch_bounds__(128) k_att1(){
    __shared__ unsigned short lst[1024];
    __shared__ unsigned char  ok[1024];
    __shared__ float w[6*1024];
    __shared__ float red[6*128];
    __shared__ float es6[6];
    int bs = blockIdx.x, ex = blockIdx.y, b = bs>>10;
    int tid = threadIdx.x;
    int c1 = g_cnt[bs*4+0], c2 = g_cnt[bs*4+1], ct = g_cnt[bs*4+2];
    int lo, hi;
    if      (ex==0){ lo=0;  hi=ct; }
    else if (ex==1){ lo=0;  hi=c1; }
    else if (ex==2){ lo=c1; hi=c2; }
    else           { lo=c2; hi=ct; }
    int n = hi-lo;
    float* h1row = g_h1 + ((size_t)ex*BSq + bs)*NHq;
    if (n==0){
        if (tid<96){
            float4 hv = *(const float4*)&g_hsum[(size_t)((ex<<2)|b)*NHq + tid*4];
            float4 o;
            o.x=elu1(hv.x*(1.f/Sq)); o.y=elu1(hv.y*(1.f/Sq));
            o.z=elu1(hv.z*(1.f/Sq)); o.w=elu1(hv.w*(1.f/Sq));
            *(float4*)&h1row[tid*4]=o;
        }
        return;
    }
    for (int j=tid;j<n;j+=128) lst[j] = g_lst[(size_t)bs*Sq + lo + j];
    if (tid<6) es6[tid] = g_es[((size_t)ex*BSq + bs)*8 + tid];
    __syncthreads();
    const float* edb = g_ed + ((size_t)ex*BSq + ((size_t)b<<10))*8;
    const unsigned char* rm = (ex>0)? g_rmask + (size_t)(ex-1)*BSq + (b<<10) : nullptr;
    float mx[6];
    #pragma unroll
    for (int h=0;h<6;h++) mx[h] = -1e30f;
    for (int j=tid;j<n;j+=128){
        int nb = lst[j];
        float4 e0 = *(const float4*)&edb[nb*8];
        float2 e1 = *(const float2*)&edb[nb*8+4];
        ok[j] = rm ? rm[nb] : 1;
        float ev[6] = {e0.x,e0.y,e0.z,e0.w,e1.x,e1.y};
        #pragma unroll
        for (int h=0;h<6;h++){
            float e = leaky02(es6[h] + ev[h]);
            w[h*1024+j] = e;
            mx[h] = fmaxf(mx[h], e);
        }
    }
    #pragma unroll
    for (int h=0;h<6;h++) red[h*128+tid]=mx[h];
    __syncthreads();
    for (int st=64;st>0;st>>=1){
        if (tid<st){
            #pragma unroll
            for (int h=0;h<6;h++) red[h*128+tid]=fmaxf(red[h*128+tid], red[h*128+tid+st]);
        }
        __syncthreads();
    }
    float mxv[6];
    #pragma unroll
    for (int h=0;h<6;h++) mxv[h]=red[h*128];
    __syncthreads();
    float sm[6] = {0.f,0.f,0.f,0.f,0.f,0.f};
    for (int j=tid;j<n;j+=128){
        #pragma unroll
        for (int h=0;h<6;h++){
            float ww = expf(w[h*1024+j]-mxv[h]);
            w[h*1024+j]=ww;
            sm[h]+=ww;
        }
    }
    #pragma unroll
    for (int h=0;h<6;h++) red[h*128+tid]=sm[h];
    __syncthreads();
    for (int st=64;st>0;st>>=1){
        if (tid<st){
            #pragma unroll
            for (int h=0;h<6;h++) red[h*128+tid]+=red[h*128+tid+st];
        }
        __syncthreads();
    }
    if (tid<96){
        int h = tid>>4;
        float inv = 1.f/red[h*128];
        const __half* hb = g_hh + ((size_t)ex*BSq + ((size_t)b<<10))*NHq;
        float ax=0.f, ay=0.f, az=0.f, aw=0.f;
        for (int j=0;j<n;j++){
            if (!ok[j]) continue;
            float wv = w[h*1024+j];
            uint2 raw = *(const uint2*)&hb[(size_t)lst[j]*NHq + tid*4];
            float2 p0 = __half22float2(*(__half2*)&raw.x);
            float2 p1 = __half22float2(*(__half2*)&raw.y);
            ax += wv*p0.x; ay += wv*p0.y; az += wv*p1.x; aw += wv*p1.y;
        }
        float4 o;
        o.x=elu1(ax*inv); o.y=elu1(ay*inv); o.z=elu1(az*inv); o.w=elu1(aw*inv);
        *(float4*)&h1row[tid*4]=o;
    }
}

// ---------------- gs/gd per (exp,bs) ----------------
__global__ void k_gsgd(const float* __restrict__ a2s_m, const float* __restrict__ a2d_m,
                       const float* __restrict__ a2s_d, const float* __restrict__ a2d_d){
    int gw   = (blockIdx.x*blockDim.x + threadIdx.x) >> 5;
    int lane = threadIdx.x & 31;
    if (gw >= NEXP*BSq) return;
    int e = gw / BSq;
    const float* as = (e==0)? a2s_m : a2s_d + (size_t)(e-1)*Dq;
    const float* ad = (e==0)? a2d_m : a2d_d + (size_t)(e-1)*Dq;
    const float* hr = g_h2 + (size_t)gw*Dq;
    float s=0.f, d=0.f;
    #pragma unroll
    for (int k=lane;k<Dq;k+=32){
        float v = hr[k];
        s += v*as[k]; d += v*ad[k];
    }
    #pragma unroll
    for (int o=16;o>0;o>>=1){
        s += __shfl_down_sync(0xffffffffu,s,o);
        d += __shfl_down_sync(0xffffffffu,d,o);
    }
    if (lane==0){ g_gs[gw]=s; g_gd[gw]=d; }
}

// ---------------- h2sum (deputies only, chunked + atomic) ----------------
__global__ void k_h2sum(){
    int eb = blockIdx.x + Bq;
    int chunk = blockIdx.y;
    int e = eb>>2, b = eb&3;
    const float* base = g_h2 + ((size_t)e*BSq + ((size_t)b<<10) + chunk*128)*Dq;
    int t = threadIdx.x;
    float acc = 0.f;
    for (int s=0;s<128;s++) acc += base[(size_t)s*Dq + t];
    atomicAdd(&g_h2sum[(size_t)eb*Dq + t], acc);
}

// ---------------- attention layer 2 (fp16 gather) ----------------
__global__ void __launch_bounds__(256) k_att2(){
    __shared__ unsigned short lst[1024];
    __shared__ float w[1024];
    __shared__ float red[256];
    __shared__ float4 sacc[4][64];
    int bs = blockIdx.x, ex = blockIdx.y, b = bs>>10;
    int tid = threadIdx.x;
    if (ex>0 && g_rmask[(size_t)(ex-1)*BSq + bs]==0) return;
    int c1 = g_cnt[bs*4+0], c2 = g_cnt[bs*4+1], ct = g_cnt[bs*4+2];
    int lo, hi;
    if      (ex==0){ lo=0;  hi=ct; }
    else if (ex==1){ lo=0;  hi=c1; }
    else if (ex==2){ lo=c1; hi=c2; }
    else           { lo=c2; hi=ct; }
    int n = hi-lo;
    if (n==0){
        if (tid<64){
            float4 hv = *(const float4*)&g_h2sum[(size_t)((ex<<2)|b)*Dq + tid*4];
            float4 o = make_float4(hv.x*(1.f/Sq), hv.y*(1.f/Sq), hv.z*(1.f/Sq), hv.w*(1.f/Sq));
            if (ex==0) *(float4*)&g_main[(size_t)bs*Dq + tid*4] = o;
            else {
                float* dp = &g_dep[(size_t)bs*Dq + tid*4];
                atomicAdd(dp+0,o.x); atomicAdd(dp+1,o.y); atomicAdd(dp+2,o.z); atomicAdd(dp+3,o.w);
            }
        }
        return;
    }
    for (int j=tid;j<n;j+=256) lst[j] = g_lst[(size_t)bs*Sq + lo + j];
    __syncthreads();
    float gsv = g_gs[(size_t)ex*BSq + bs];
    const float* gdb = g_gd + (size_t)ex*BSq + (b<<10);
    float mloc = -1e30f;
    for (int j=tid;j<n;j+=256){
        float e = leaky02(gsv + gdb[lst[j]]);
        w[j]=e;
        mloc = fmaxf(mloc,e);
    }
    red[tid]=mloc; __syncthreads();
    for (int st=128;st>0;st>>=1){ if (tid<st) red[tid]=fmaxf(red[tid],red[tid+st]); __syncthreads(); }
    float m = red[0]; __syncthreads();
    float sloc = 0.f;
    for (int j=tid;j<n;j+=256){ float ww=expf(w[j]-m); w[j]=ww; sloc+=ww; }
    red[tid]=sloc; __syncthreads();
    for (int st=128;st>0;st>>=1){ if (tid<st) red[tid]+=red[tid+st]; __syncthreads(); }
    float inv = 1.f/red[0];
    int grp = tid>>6, q = tid&63;
    const __half* h2b = g_h2h + ((size_t)ex*BSq + ((size_t)b<<10))*Dq;
    float ax=0.f, ay=0.f, az=0.f, aw=0.f;
    for (int j=grp;j<n;j+=4){
        float wv = w[j];
        uint2 raw = *(const uint2*)&h2b[(size_t)lst[j]*Dq + q*4];
        float2 p0 = __half22float2(*(__half2*)&raw.x);
        float2 p1 = __half22float2(*(__half2*)&raw.y);
        ax += wv*p0.x; ay += wv*p0.y; az += wv*p1.x; aw += wv*p1.y;
    }
    sacc[grp][q] = make_float4(ax,ay,az,aw);
    __syncthreads();
    if (tid<64){
        float4 a0=sacc[0][tid], a1=sacc[1][tid], a2=sacc[2][tid], a3=sacc[3][tid];
        float4 o = make_float4((a0.x+a1.x+a2.x+a3.x)*inv, (a0.y+a1.y+a2.y+a3.y)*inv,
                               (a0.z+a1.z+a2.z+a3.z)*inv, (a0.w+a1.w+a2.w+a3.w)*inv);
        if (ex==0) *(float4*)&g_main[(size_t)bs*Dq + tid*4] = o;
        else {
            float* dp = &g_dep[(size_t)bs*Dq + tid*4];
            atomicAdd(dp+0,o.x); atomicAdd(dp+1,o.y); atomicAdd(dp+2,o.z); atomicAdd(dp+3,o.w);
        }
    }
}

// ---------------- final blend + scalars ----------------
__global__ void k_final(float* __restrict__ out){
    size_t i = (size_t)blockIdx.x*256 + threadIdx.x;
    if (i < BSDq){
        float bw = g_bw[i];
        out[i] = bw*g_main[i] + (1.f-bw)*g_dep[i];
    }
    if (i == 0){
        float mc = g_bwsum * (1.f/(float)BSDq);
        out[BSDq]   = fabsf(mc - 0.6f) * 0.01f;
        out[BSDq+1] = mc;
    }
}

// ---------------- host launcher ----------------
extern "C" void kernel_launch(void* const* d_in, const int* in_sizes, int n_in,
                              void* d_out, int out_size){
    const float* feature  = (const float*)d_in[0];
    const float* adj      = (const float*)d_in[1];
    const float* main_W1  = (const float*)d_in[2];
    const float* main_a1s = (const float*)d_in[3];
    const float* main_a1d = (const float*)d_in[4];
    const float* main_W2  = (const float*)d_in[5];
    const float* main_a2s = (const float*)d_in[6];
    const float* main_a2d = (const float*)d_in[7];
    const float* dep_W1   = (const float*)d_in[8];
    const float* dep_a1s  = (const float*)d_in[9];
    const float* dep_a1d  = (const float*)d_in[10];
    const float* dep_W2   = (const float*)d_in[11];
    const float* dep_a2s  = (const float*)d_in[12];
    const float* dep_a2d  = (const float*)d_in[13];
    const float* router_W = (const float*)d_in[14];
    const float* blend_W  = (const float*)d_in[15];
    const float* blend_b  = (const float*)d_in[16];
    const int*   doc_num  = (const int*)d_in[17];
    const int*   sect_num = (const int*)d_in[18];
    float* out = (float*)d_out;

    float* g_W1t_p;  cudaGetSymbolAddress((void**)&g_W1t_p,  g_W1t);
    float* g_h1_p;   cudaGetSymbolAddress((void**)&g_h1_p,   g_h1);
    float* g_h_p;    cudaGetSymbolAddress((void**)&g_h_p,    g_h);
    float* g_h2_p;   cudaGetSymbolAddress((void**)&g_h2_p,   g_h2);
    float* g_bw_p;   cudaGetSymbolAddress((void**)&g_bw_p,   g_bw);
    __half* g_hh_p;  cudaGetSymbolAddress((void**)&g_hh_p,   g_hh);
    __half* g_h2h_p; cudaGetSymbolAddress((void**)&g_h2h_p,  g_h2h);

    k_zero<<<(BSDq+255)/256, 256>>>();
    k_nbr<<<BSq, 256>>>(adj, doc_num, sect_num);
    k_router<<<BSq/4, 128>>>(feature, router_W);
    k_prepw<<<dim3(Dq*NHq/256, NEXP), 256>>>(main_W1, dep_W1);

    k_mm<Dq, Dq, false><<<dim3(2,32,1), 256>>>(feature, 0, blend_W, blend_W, 0, g_bw_p, (__half*)0);
    k_sig<<<BSDq/256, 256>>>(blend_b);

    k_mm<Dq, NHq, true><<<dim3(3,32,NEXP), 256>>>(feature, 0, g_W1t_p,
                                                  g_W1t_p + (size_t)Dq*NHq, (size_t)Dq*NHq,
                                                  g_h_p, g_hh_p);
    k_esed<<<(NEXP*BSq*Hq)/8, 256>>>(main_a1s, main_a1d, dep_a1s, dep_a1d);
    k_hsum<<<dim3((NEXP-1)*Bq, 8), NHq>>>();
    k_att1<<<dim3(BSq, NEXP), 128>>>();

    k_mm<NHq, Dq, false><<<dim3(2,32,NEXP), 256>>>(g_h1_p, (size_t)BSq*NHq, main_W2,
                                                   dep_W2, (size_t)NHq*Dq, g_h2_p, g_h2h_p);
    k_gsgd<<<(NEXP*BSq)/8, 256>>>(main_a2s, main_a2d, dep_a2s, dep_a2d);
    k_h2sum<<<dim3((NEXP-1)*Bq, 8), Dq>>>();
    k_att2<<<dim3(BSq, NEXP), 256>>>();

    k_final<<<(BSDq+255)/256, 256>>>(out);
}

// round 5
// speedup vs baseline: 1.7743x; 1.2068x over previous
#include <cuda_runtime.h>
#include <cuda_fp16.h>
#include <math.h>

// Fixed shapes
#define Bq 4
#define Sq 1024
#define Dq 256
#define Hq 6
#define HDq 64
#define NHq 384          // H*Hd
#define BSq 4096         // B*S
#define BSDq (BSq*Dq)
#define NEXP 4           // slot 0 = main, 1..3 = deputies

// ---------------- scratch ----------------
__device__ float  g_h  [(size_t)NEXP*BSq*NHq];   // fp32 layer-1 features (esed/hsum)
__device__ __half g_hh [(size_t)NEXP*BSq*NHq];   // fp16 gather copy
__device__ __half g_h1h[(size_t)NEXP*BSq*NHq];   // fp16 layer-1 output (GEMM2 A operand)
__device__ float  g_h2 [(size_t)NEXP*BSq*Dq];
__device__ __half g_h2h[(size_t)NEXP*BSq*Dq];
__device__ float  g_es [NEXP*BSq*8];
__device__ float  g_ed [NEXP*BSq*8];
__device__ float  g_hsum [NEXP*Bq*NHq];
__device__ float  g_h2sum[NEXP*Bq*Dq];
__device__ float  g_gs [NEXP*BSq];
__device__ float  g_gd [NEXP*BSq];
__device__ __half g_feat_h[(size_t)BSq*Dq];
__device__ __half g_W1t_h[(size_t)NEXP*NHq*Dq];  // [e][n][k]
__device__ __half g_W2t_h[(size_t)NEXP*Dq*NHq];  // [e][n][k]
__device__ __half g_bWt_h[(size_t)Dq*Dq];        // [n][k]
__device__ float  g_main[BSDq];
__device__ float  g_dep [BSDq];
__device__ float  g_bw  [BSDq];
__device__ float  g_bwsum;
__device__ unsigned char  g_rmask[3*BSq];
__device__ unsigned short g_lst[(size_t)BSq*Sq];
__device__ int g_cnt[BSq*4];

__device__ __forceinline__ float leaky02(float x){ return x > 0.f ? x : 0.2f*x; }
__device__ __forceinline__ float elu1(float x){ return x > 0.f ? x : expm1f(x); }
__device__ __forceinline__ void mma_f16(float c[4], unsigned a0,unsigned a1,unsigned a2,unsigned a3,
                                        unsigned b0,unsigned b1){
    asm volatile("mma.sync.aligned.m16n8k16.row.col.f32.f16.f16.f32 "
        "{%0,%1,%2,%3},{%4,%5,%6,%7},{%8,%9},{%0,%1,%2,%3};"
        : "+f"(c[0]),"+f"(c[1]),"+f"(c[2]),"+f"(c[3])
        : "r"(a0),"r"(a1),"r"(a2),"r"(a3),"r"(b0),"r"(b1));
}

// ---------------- zero init ----------------
__global__ void k_zero(){
    int i = blockIdx.x*256 + threadIdx.x;
    if (i < BSDq) g_dep[i] = 0.f;
    if (i < NEXP*Bq*NHq) g_hsum[i] = 0.f;
    if (i < NEXP*Bq*Dq)  g_h2sum[i] = 0.f;
    if (i == 0) g_bwsum = 0.f;
}

// ---------------- fp16 operand prep (feature, W1t, W2t, blendWt) ----------------
__global__ void k_prep(const float* __restrict__ feature,
                       const float* __restrict__ mainW1, const float* __restrict__ depW1,
                       const float* __restrict__ mainW2, const float* __restrict__ depW2,
                       const float* __restrict__ blendW){
    int task = blockIdx.y;
    int i = blockIdx.x*256 + threadIdx.x;
    if (task == 0){
        g_feat_h[i] = __float2half(feature[i]);           // exactly BSq*Dq = grid.x*256
    } else if (task == 1){
        if (i < NEXP*NHq*Dq){
            int e = i/(NHq*Dq), r = i%(NHq*Dq), n = r/Dq, k = r%Dq;
            int h = n>>6, o = n&63;
            const float* src = (e==0)? mainW1 : depW1 + (size_t)(e-1)*Hq*Dq*HDq;
            g_W1t_h[i] = __float2half(src[(size_t)h*Dq*HDq + (size_t)k*HDq + o]);
        }
    } else if (task == 2){
        if (i < NEXP*Dq*NHq){
            int e = i/(Dq*NHq), r = i%(Dq*NHq), n = r/NHq, k = r%NHq;
            const float* src = (e==0)? mainW2 : depW2 + (size_t)(e-1)*NHq*Dq;
            g_W2t_h[i] = __float2half(src[(size_t)k*Dq + n]);
        }
    } else {
        if (i < Dq*Dq){
            int n = i/Dq, k = i%Dq;
            g_bWt_h[i] = __float2half(blendW[(size_t)k*Dq + n]);
        }
    }
}

// ---------------- neighbor lists (one adj pass, sorted, with segment counts) -------
__global__ void k_nbr(const float* __restrict__ adj, const int* __restrict__ dnum,
                      const int* __restrict__ snum){
    __shared__ int sc[256];
    __shared__ int ra[256], rb[256];
    int bs = blockIdx.x, tid = threadIdx.x;
    int doc = dnum[0], sect = snum[0];
    int lim1 = Sq - sect - doc, lim2 = Sq - doc;
    const float* arow = adj + (size_t)bs*Sq;
    float4 a = *(const float4*)(arow + tid*4);
    unsigned short loc[4]; int c=0, ca=0, cb=0;
    float av[4] = {a.x,a.y,a.z,a.w};
    #pragma unroll
    for (int i=0;i<4;i++){
        int col = tid*4+i;
        if (av[i] > 0.f){ loc[c++] = (unsigned short)col; ca += (col<lim1); cb += (col<lim2); }
    }
    sc[tid]=c; ra[tid]=ca; rb[tid]=cb;
    __syncthreads();
    for (int off=1; off<256; off<<=1){
        int v = (tid>=off)? sc[tid-off] : 0;
        __syncthreads();
        sc[tid]+=v;
        __syncthreads();
    }
    int base = sc[tid]-c;
    for (int i=0;i<c;i++) g_lst[(size_t)bs*Sq + base + i] = loc[i];
    for (int st=128; st>0; st>>=1){
        if (tid<st){ ra[tid]+=ra[tid+st]; rb[tid]+=rb[tid+st]; }
        __syncthreads();
    }
    if (tid==0){
        g_cnt[bs*4+0]=ra[0]; g_cnt[bs*4+1]=rb[0]; g_cnt[bs*4+2]=sc[255]; g_cnt[bs*4+3]=0;
    }
}

// ---------------- router ----------------
__global__ void k_router(const float* __restrict__ x, const float* __restrict__ Wr){
    int gw   = (blockIdx.x*blockDim.x + threadIdx.x) >> 5;
    int lane = threadIdx.x & 31;
    if (gw >= BSq) return;
    const float* xr = x + (size_t)gw*Dq;
    float a0=0.f,a1=0.f,a2=0.f;
    for (int k=lane;k<Dq;k+=32){
        float xv = xr[k];
        a0 += xv*Wr[k*3+0]; a1 += xv*Wr[k*3+1]; a2 += xv*Wr[k*3+2];
    }
    #pragma unroll
    for (int o=16;o>0;o>>=1){
        a0 += __shfl_down_sync(0xffffffffu,a0,o);
        a1 += __shfl_down_sync(0xffffffffu,a1,o);
        a2 += __shfl_down_sync(0xffffffffu,a2,o);
    }
    if (lane==0){
        float v[3]={a0,a1,a2};
        int ex=0; float mv=v[0];
        #pragma unroll
        for (int e=1;e<3;e++) if (v[e]<=mv){ mv=v[e]; ex=e; }
        #pragma unroll
        for (int e=0;e<3;e++) g_rmask[e*BSq+gw] = (e==ex)?0:1;
    }
}

// ---------------- fp16 tensor-core GEMM (2-sync, m16n8k16) ----------------
// A: [e][M][KD] fp16 row-major. Bt: [e][ND][KD] fp16 (n-major). C: fp32 (+opt fp16 copy).
// SIG: apply sigmoid(c+bias[col]) in epilogue, accumulate global mean sum.
template<int KD, int ND, bool MASK, bool SIG>
__global__ void __launch_bounds__(256) k_mmh(const __half* __restrict__ Abase, size_t astride,
                                             const __half* __restrict__ Btbase,
                                             float* __restrict__ Cbase, __half* __restrict__ Chbase,
                                             const float* __restrict__ bias){
    int e = blockIdx.z;
    const __half* A  = Abase + astride*e;
    const __half* Bt = Btbase + (size_t)e*ND*KD;
    float* C = Cbase + (size_t)e*BSq*ND;
    __half* Ch = Chbase ? Chbase + (size_t)e*BSq*ND : (__half*)0;
    int m0 = blockIdx.y*128, n0 = blockIdx.x*128;
    __shared__ __half2 As2[128][20];   // 16 used, stride 20 (conflict-free, 16B-aligned)
    __shared__ __half2 Bs2[128][20];
    __shared__ float sred[256];
    int tid=threadIdx.x, lane=tid&31, wid=tid>>5;
    int wm=(wid&1)*64, wn=(wid>>1)*32;
    int gid=lane>>2, qid=lane&3;
    float c[4][4][4];
    #pragma unroll
    for (int mt=0;mt<4;mt++)
        #pragma unroll
        for (int nt=0;nt<4;nt++)
            #pragma unroll
            for (int r=0;r<4;r++) c[mt][nt][r]=0.f;
    int row = tid>>1;
    int kh  = (tid&1)*16;            // halves offset within 32-k tile
    int kc2 = (tid&1)*8;             // half2 offset in smem
    bool amask = true;
    if (MASK){ if (e>0 && g_rmask[(size_t)(e-1)*BSq + m0 + row]==0) amask = false; }
    const __half* Ap  = A  + (size_t)(m0+row)*KD + kh;
    const __half* Btp = Bt + (size_t)(n0+row)*KD + kh;

    for (int k0=0; k0<KD; k0+=32){
        uint4 va0 = *(const uint4*)(Ap + k0);
        uint4 va1 = *(const uint4*)(Ap + k0 + 8);
        uint4 vb0 = *(const uint4*)(Btp + k0);
        uint4 vb1 = *(const uint4*)(Btp + k0 + 8);
        if (MASK && !amask){ va0 = make_uint4(0,0,0,0); va1 = make_uint4(0,0,0,0); }
        __syncthreads();
        *(uint4*)&As2[row][kc2]   = va0;
        *(uint4*)&As2[row][kc2+4] = va1;
        *(uint4*)&Bs2[row][kc2]   = vb0;
        *(uint4*)&Bs2[row][kc2+4] = vb1;
        __syncthreads();
        #pragma unroll
        for (int sub=0; sub<2; sub++){
            unsigned af[4][4], bf[4][2];
            #pragma unroll
            for (int mt=0;mt<4;mt++){
                int r = wm + mt*16 + gid;
                af[mt][0]=*(unsigned*)&As2[r  ][sub*8+qid];
                af[mt][1]=*(unsigned*)&As2[r+8][sub*8+qid];
                af[mt][2]=*(unsigned*)&As2[r  ][sub*8+4+qid];
                af[mt][3]=*(unsigned*)&As2[r+8][sub*8+4+qid];
            }
            #pragma unroll
            for (int nt=0;nt<4;nt++){
                int cc = wn + nt*8 + gid;
                bf[nt][0]=*(unsigned*)&Bs2[cc][sub*8+qid];
                bf[nt][1]=*(unsigned*)&Bs2[cc][sub*8+4+qid];
            }
            #pragma unroll
            for (int mt=0;mt<4;mt++)
                #pragma unroll
                for (int nt=0;nt<4;nt++)
                    mma_f16(c[mt][nt], af[mt][0],af[mt][1],af[mt][2],af[mt][3],
                            bf[nt][0],bf[nt][1]);
        }
    }
    float lsum = 0.f;
    #pragma unroll
    for (int mt=0;mt<4;mt++){
        int orow = m0 + wm + mt*16 + gid;
        #pragma unroll
        for (int nt=0;nt<4;nt++){
            int col = n0 + wn + nt*8 + qid*2;
            float2 v0 = make_float2(c[mt][nt][0], c[mt][nt][1]);
            float2 v1 = make_float2(c[mt][nt][2], c[mt][nt][3]);
            if (SIG){
                float b0v = bias[col], b1v = bias[col+1];
                v0.x = 1.f/(1.f+expf(-(v0.x+b0v))); v0.y = 1.f/(1.f+expf(-(v0.y+b1v)));
                v1.x = 1.f/(1.f+expf(-(v1.x+b0v))); v1.y = 1.f/(1.f+expf(-(v1.y+b1v)));
                lsum += v0.x+v0.y+v1.x+v1.y;
            }
            *(float2*)&C[(size_t)orow*ND + col]     = v0;
            *(float2*)&C[(size_t)(orow+8)*ND + col] = v1;
            if (Ch){
                *(__half2*)&Ch[(size_t)orow*ND + col]     = __float22half2_rn(v0);
                *(__half2*)&Ch[(size_t)(orow+8)*ND + col] = __float22half2_rn(v1);
            }
        }
    }
    if (SIG){
        sred[tid] = lsum;
        __syncthreads();
        for (int st=128; st>0; st>>=1){ if (tid<st) sred[tid]+=sred[tid+st]; __syncthreads(); }
        if (tid==0) atomicAdd(&g_bwsum, sred[0]);
    }
}

// ---------------- es/ed per (exp,bs,h) ----------------
__global__ void k_esed(const float* __restrict__ a1s_m, const float* __restrict__ a1d_m,
                       const float* __restrict__ a1s_d, const float* __restrict__ a1d_d){
    int gw   = (blockIdx.x*blockDim.x + threadIdx.x) >> 5;
    int lane = threadIdx.x & 31;
    if (gw >= NEXP*BSq*Hq) return;
    int h = gw % Hq, be = gw / Hq;
    int e = be / BSq;
    const float* as = ((e==0)? a1s_m : a1s_d + (size_t)(e-1)*NHq) + h*HDq;
    const float* ad = ((e==0)? a1d_m : a1d_d + (size_t)(e-1)*NHq) + h*HDq;
    const float* hr = g_h + (size_t)be*NHq + h*HDq;
    float s=0.f, d=0.f;
    #pragma unroll
    for (int o=lane;o<HDq;o+=32){
        float v = hr[o];
        s += v*as[o]; d += v*ad[o];
    }
    #pragma unroll
    for (int o=16;o>0;o>>=1){
        s += __shfl_down_sync(0xffffffffu,s,o);
        d += __shfl_down_sync(0xffffffffu,d,o);
    }
    if (lane==0){ g_es[be*8+h]=s; g_ed[be*8+h]=d; }
}

// ---------------- hsum (deputies only, chunked + atomic) ----------------
__global__ void k_hsum(){
    int eb = blockIdx.x + Bq;
    int chunk = blockIdx.y;
    int e = eb>>2, b = eb&3;
    const float* base = g_h + ((size_t)e*BSq + ((size_t)b<<10) + chunk*128)*NHq;
    int t = threadIdx.x;
    float acc = 0.f;
    for (int s=0;s<128;s++) acc += base[(size_t)s*NHq + t];
    atomicAdd(&g_hsum[(size_t)eb*NHq + t], acc);
}

// ---------------- attention layer 1 (6 heads, fp16 gather, fp16 output) ----------
__global__ void __launch_bounds__(128) k_att1(){
    __shared__ unsigned short lst[1024];
    __shared__ unsigned char  ok[1024];
    __shared__ float w[6*1024];
    __shared__ float red[6*128];
    __shared__ float es6[6];
    int bs = blockIdx.x, ex = blockIdx.y, b = bs>>10;
    int tid = threadIdx.x;
    int c1 = g_cnt[bs*4+0], c2 = g_cnt[bs*4+1], ct = g_cnt[bs*4+2];
    int lo, hi;
    if      (ex==0){ lo=0;  hi=ct; }
    else if (ex==1){ lo=0;  hi=c1; }
    else if (ex==2){ lo=c1; hi=c2; }
    else           { lo=c2; hi=ct; }
    int n = hi-lo;
    __half* h1row = g_h1h + ((size_t)ex*BSq + bs)*NHq;
    if (n==0){
        if (tid<96){
            float4 hv = *(const float4*)&g_hsum[(size_t)((ex<<2)|b)*NHq + tid*4];
            *(__half2*)&h1row[tid*4]   = __float22half2_rn(make_float2(elu1(hv.x*(1.f/Sq)), elu1(hv.y*(1.f/Sq))));
            *(__half2*)&h1row[tid*4+2] = __float22half2_rn(make_float2(elu1(hv.z*(1.f/Sq)), elu1(hv.w*(1.f/Sq))));
        }
        return;
    }
    for (int j=tid;j<n;j+=128) lst[j] = g_lst[(size_t)bs*Sq + lo + j];
    if (tid<6) es6[tid] = g_es[((size_t)ex*BSq + bs)*8 + tid];
    __syncthreads();
    const float* edb = g_ed + ((size_t)ex*BSq + ((size_t)b<<10))*8;
    const unsigned char* rm = (ex>0)? g_rmask + (size_t)(ex-1)*BSq + (b<<10) : nullptr;
    float mx[6];
    #pragma unroll
    for (int h=0;h<6;h++) mx[h] = -1e30f;
    for (int j=tid;j<n;j+=128){
        int nb = lst[j];
        float4 e0 = *(const float4*)&edb[nb*8];
        float2 e1 = *(const float2*)&edb[nb*8+4];
        ok[j] = rm ? rm[nb] : 1;
        float ev[6] = {e0.x,e0.y,e0.z,e0.w,e1.x,e1.y};
        #pragma unroll
        for (int h=0;h<6;h++){
            float e = leaky02(es6[h] + ev[h]);
            w[h*1024+j] = e;
            mx[h] = fmaxf(mx[h], e);
        }
    }
    #pragma unroll
    for (int h=0;h<6;h++) red[h*128+tid]=mx[h];
    __syncthreads();
    for (int st=64;st>0;st>>=1){
        if (tid<st){
            #pragma unroll
            for (int h=0;h<6;h++) red[h*128+tid]=fmaxf(red[h*128+tid], red[h*128+tid+st]);
        }
        __syncthreads();
    }
    float mxv[6];
    #pragma unroll
    for (int h=0;h<6;h++) mxv[h]=red[h*128];
    __syncthreads();
    float sm[6] = {0.f,0.f,0.f,0.f,0.f,0.f};
    for (int j=tid;j<n;j+=128){
        #pragma unroll
        for (int h=0;h<6;h++){
            float ww = expf(w[h*1024+j]-mxv[h]);
            w[h*1024+j]=ww;
            sm[h]+=ww;
        }
    }
    #pragma unroll
    for (int h=0;h<6;h++) red[h*128+tid]=sm[h];
    __syncthreads();
    for (int st=64;st>0;st>>=1){
        if (tid<st){
            #pragma unroll
            for (int h=0;h<6;h++) red[h*128+tid]+=red[h*128+tid+st];
        }
        __syncthreads();
    }
    if (tid<96){
        int h = tid>>4;
        float inv = 1.f/red[h*128];
        const __half* hb = g_hh + ((size_t)ex*BSq + ((size_t)b<<10))*NHq;
        float ax=0.f, ay=0.f, az=0.f, aw=0.f;
        for (int j=0;j<n;j++){
            if (!ok[j]) continue;
            float wv = w[h*1024+j];
            uint2 raw = *(const uint2*)&hb[(size_t)lst[j]*NHq + tid*4];
            float2 p0 = __half22float2(*(__half2*)&raw.x);
            float2 p1 = __half22float2(*(__half2*)&raw.y);
            ax += wv*p0.x; ay += wv*p0.y; az += wv*p1.x; aw += wv*p1.y;
        }
        *(__half2*)&h1row[tid*4]   = __float22half2_rn(make_float2(elu1(ax*inv), elu1(ay*inv)));
        *(__half2*)&h1row[tid*4+2] = __float22half2_rn(make_float2(elu1(az*inv), elu1(aw*inv)));
    }
}

// ---------------- gs/gd per (exp,bs) ----------------
__global__ void k_gsgd(const float* __restrict__ a2s_m, const float* __restrict__ a2d_m,
                       const float* __restrict__ a2s_d, const float* __restrict__ a2d_d){
    int gw   = (blockIdx.x*blockDim.x + threadIdx.x) >> 5;
    int lane = threadIdx.x & 31;
    if (gw >= NEXP*BSq) return;
    int e = gw / BSq;
    const float* as = (e==0)? a2s_m : a2s_d + (size_t)(e-1)*Dq;
    const float* ad = (e==0)? a2d_m : a2d_d + (size_t)(e-1)*Dq;
    const float* hr = g_h2 + (size_t)gw*Dq;
    float s=0.f, d=0.f;
    #pragma unroll
    for (int k=lane;k<Dq;k+=32){
        float v = hr[k];
        s += v*as[k]; d += v*ad[k];
    }
    #pragma unroll
    for (int o=16;o>0;o>>=1){
        s += __shfl_down_sync(0xffffffffu,s,o);
        d += __shfl_down_sync(0xffffffffu,d,o);
    }
    if (lane==0){ g_gs[gw]=s; g_gd[gw]=d; }
}

// ---------------- h2sum (deputies only, chunked + atomic) ----------------
__global__ void k_h2sum(){
    int eb = blockIdx.x + Bq;
    int chunk = blockIdx.y;
    int e = eb>>2, b = eb&3;
    const float* base = g_h2 + ((size_t)e*BSq + ((size_t)b<<10) + chunk*128)*Dq;
    int t = threadIdx.x;
    float acc = 0.f;
    for (int s=0;s<128;s++) acc += base[(size_t)s*Dq + t];
    atomicAdd(&g_h2sum[(size_t)eb*Dq + t], acc);
}

// ---------------- attention layer 2 (fp16 gather) ----------------
__global__ void __launch_bounds__(256) k_att2(){
    __shared__ unsigned short lst[1024];
    __shared__ float w[1024];
    __shared__ float red[256];
    __shared__ float4 sacc[4][64];
    int bs = blockIdx.x, ex = blockIdx.y, b = bs>>10;
    int tid = threadIdx.x;
    if (ex>0 && g_rmask[(size_t)(ex-1)*BSq + bs]==0) return;
    int c1 = g_cnt[bs*4+0], c2 = g_cnt[bs*4+1], ct = g_cnt[bs*4+2];
    int lo, hi;
    if      (ex==0){ lo=0;  hi=ct; }
    else if (ex==1){ lo=0;  hi=c1; }
    else if (ex==2){ lo=c1; hi=c2; }
    else           { lo=c2; hi=ct; }
    int n = hi-lo;
    if (n==0){
        if (tid<64){
            float4 hv = *(const float4*)&g_h2sum[(size_t)((ex<<2)|b)*Dq + tid*4];
            float4 o = make_float4(hv.x*(1.f/Sq), hv.y*(1.f/Sq), hv.z*(1.f/Sq), hv.w*(1.f/Sq));
            if (ex==0) *(float4*)&g_main[(size_t)bs*Dq + tid*4] = o;
            else {
                float* dp = &g_dep[(size_t)bs*Dq + tid*4];
                atomicAdd(dp+0,o.x); atomicAdd(dp+1,o.y); atomicAdd(dp+2,o.z); atomicAdd(dp+3,o.w);
            }
        }
        return;
    }
    for (int j=tid;j<n;j+=256) lst[j] = g_lst[(size_t)bs*Sq + lo + j];
    __syncthreads();
    float gsv = g_gs[(size_t)ex*BSq + bs];
    const float* gdb = g_gd + (size_t)ex*BSq + (b<<10);
    float mloc = -1e30f;
    for (int j=tid;j<n;j+=256){
        float e = leaky02(gsv + gdb[lst[j]]);
        w[j]=e;
        mloc = fmaxf(mloc,e);
    }
    red[tid]=mloc; __syncthreads();
    for (int st=128;st>0;st>>=1){ if (tid<st) red[tid]=fmaxf(red[tid],red[tid+st]); __syncthreads(); }
    float m = red[0]; __syncthreads();
    float sloc = 0.f;
    for (int j=tid;j<n;j+=256){ float ww=expf(w[j]-m); w[j]=ww; sloc+=ww; }
    red[tid]=sloc; __syncthreads();
    for (int st=128;st>0;st>>=1){ if (tid<st) red[tid]+=red[tid+st]; __syncthreads(); }
    float inv = 1.f/red[0];
    int grp = tid>>6, q = tid&63;
    const __half* h2b = g_h2h + ((size_t)ex*BSq + ((size_t)b<<10))*Dq;
    float ax=0.f, ay=0.f, az=0.f, aw=0.f;
    for (int j=grp;j<n;j+=4){
        float wv = w[j];
        uint2 raw = *(const uint2*)&h2b[(size_t)lst[j]*Dq + q*4];
        float2 p0 = __half22float2(*(__half2*)&raw.x);
        float2 p1 = __half22float2(*(__half2*)&raw.y);
        ax += wv*p0.x; ay += wv*p0.y; az += wv*p1.x; aw += wv*p1.y;
    }
    sacc[grp][q] = make_float4(ax,ay,az,aw);
    __syncthreads();
    if (tid<64){
        float4 a0=sacc[0][tid], a1=sacc[1][tid], a2=sacc[2][tid], a3=sacc[3][tid];
        float4 o = make_float4((a0.x+a1.x+a2.x+a3.x)*inv, (a0.y+a1.y+a2.y+a3.y)*inv,
                               (a0.z+a1.z+a2.z+a3.z)*inv, (a0.w+a1.w+a2.w+a3.w)*inv);
        if (ex==0) *(float4*)&g_main[(size_t)bs*Dq + tid*4] = o;
        else {
            float* dp = &g_dep[(size_t)bs*Dq + tid*4];
            atomicAdd(dp+0,o.x); atomicAdd(dp+1,o.y); atomicAdd(dp+2,o.z); atomicAdd(dp+3,o.w);
        }
    }
}

// ---------------- final blend + scalars ----------------
__global__ void k_final(float* __restrict__ out){
    size_t i = (size_t)blockIdx.x*256 + threadIdx.x;
    if (i < BSDq){
        float bw = g_bw[i];
        out[i] = bw*g_main[i] + (1.f-bw)*g_dep[i];
    }
    if (i == 0){
        float mc = g_bwsum * (1.f/(float)BSDq);
        out[BSDq]   = fabsf(mc - 0.6f) * 0.01f;
        out[BSDq+1] = mc;
    }
}

// ---------------- host launcher ----------------
extern "C" void kernel_launch(void* const* d_in, const int* in_sizes, int n_in,
                              void* d_out, int out_size){
    const float* feature  = (const float*)d_in[0];
    const float* adj      = (const float*)d_in[1];
    const float* main_W1  = (const float*)d_in[2];
    const float* main_a1s = (const float*)d_in[3];
    const float* main_a1d = (const float*)d_in[4];
    const float* main_W2  = (const float*)d_in[5];
    const float* main_a2s = (const float*)d_in[6];
    const float* main_a2d = (const float*)d_in[7];
    const float* dep_W1   = (const float*)d_in[8];
    const float* dep_a1s  = (const float*)d_in[9];
    const float* dep_a1d  = (const float*)d_in[10];
    const float* dep_W2   = (const float*)d_in[11];
    const float* dep_a2s  = (const float*)d_in[12];
    const float* dep_a2d  = (const float*)d_in[13];
    const float* router_W = (const float*)d_in[14];
    const float* blend_W  = (const float*)d_in[15];
    const float* blend_b  = (const float*)d_in[16];
    const int*   doc_num  = (const int*)d_in[17];
    const int*   sect_num = (const int*)d_in[18];
    float* out = (float*)d_out;

    __half* feat_h;  cudaGetSymbolAddress((void**)&feat_h,  g_feat_h);
    __half* W1t_h;   cudaGetSymbolAddress((void**)&W1t_h,   g_W1t_h);
    __half* W2t_h;   cudaGetSymbolAddress((void**)&W2t_h,   g_W2t_h);
    __half* bWt_h;   cudaGetSymbolAddress((void**)&bWt_h,   g_bWt_h);
    __half* h1h_p;   cudaGetSymbolAddress((void**)&h1h_p,   g_h1h);
    float*  h_p;     cudaGetSymbolAddress((void**)&h_p,     g_h);
    float*  h2_p;    cudaGetSymbolAddress((void**)&h2_p,    g_h2);
    float*  bw_p;    cudaGetSymbolAddress((void**)&bw_p,    g_bw);
    __half* hh_p;    cudaGetSymbolAddress((void**)&hh_p,    g_hh);
    __half* h2h_p;   cudaGetSymbolAddress((void**)&h2h_p,   g_h2h);

    k_zero<<<(BSDq+255)/256, 256>>>();
    k_prep<<<dim3(BSq*Dq/256, 4), 256>>>(feature, main_W1, dep_W1, main_W2, dep_W2, blend_W);
    k_nbr<<<BSq, 256>>>(adj, doc_num, sect_num);
    k_router<<<BSq/4, 128>>>(feature, router_W);

    // blend: sigmoid fused into epilogue
    k_mmh<Dq, Dq, false, true><<<dim3(2,32,1), 256>>>(feat_h, 0, bWt_h, bw_p, (__half*)0, blend_b);

    // layer-1 GEMM all experts
    k_mmh<Dq, NHq, true, false><<<dim3(3,32,NEXP), 256>>>(feat_h, 0, W1t_h, h_p, hh_p, (const float*)0);
    k_esed<<<(NEXP*BSq*Hq)/8, 256>>>(main_a1s, main_a1d, dep_a1s, dep_a1d);
    k_hsum<<<dim3((NEXP-1)*Bq, 8), NHq>>>();
    k_att1<<<dim3(BSq, NEXP), 128>>>();

    // layer-2 GEMM all experts
    k_mmh<NHq, Dq, false, false><<<dim3(2,32,NEXP), 256>>>(h1h_p, (size_t)BSq*NHq, W2t_h, h2_p, h2h_p, (const float*)0);
    k_gsgd<<<(NEXP*BSq)/8, 256>>>(main_a2s, main_a2d, dep_a2s, dep_a2d);
    k_h2sum<<<dim3((NEXP-1)*Bq, 8), Dq>>>();
    k_att2<<<dim3(BSq, NEXP), 256>>>();

    k_final<<<(BSDq+255)/256, 256>>>(out);
}

// round 6
// speedup vs baseline: 1.8509x; 1.0432x over previous
#include <cuda_runtime.h>
#include <cuda_fp16.h>
#include <math.h>

// Fixed shapes
#define Bq 4
#define Sq 1024
#define Dq 256
#define Hq 6
#define HDq 64
#define NHq 384          // H*Hd
#define BSq 4096         // B*S
#define BSDq (BSq*Dq)
#define NEXP 4           // slot 0 = main, 1..3 = deputies

// ---------------- scratch ----------------
__device__ __half g_hh [(size_t)NEXP*BSq*NHq];   // layer-1 features (fp16)
__device__ __half g_h1h[(size_t)NEXP*BSq*NHq];   // layer-1 att output (fp16)
__device__ __half g_h2h[(size_t)NEXP*BSq*Dq];    // layer-2 features (fp16)
__device__ float  g_es [NEXP*BSq*8];
__device__ float  g_ed [NEXP*BSq*8];
__device__ float  g_hsum [NEXP*Bq*NHq];
__device__ float  g_h2sum[NEXP*Bq*Dq];
__device__ float  g_gs [NEXP*BSq];
__device__ float  g_gd [NEXP*BSq];
__device__ __half g_feat_h[(size_t)BSq*Dq];
__device__ __half g_W1t_h[(size_t)NEXP*NHq*Dq];  // [e][n][k]
__device__ __half g_W2t_h[(size_t)NEXP*Dq*NHq];  // [e][n][k]
__device__ __half g_bWt_h[(size_t)Dq*Dq];        // [n][k]
__device__ float  g_main[BSDq];
__device__ float  g_depE[3*(size_t)BSDq];        // per-deputy outputs (no atomics)
__device__ float  g_bw  [BSDq];
__device__ float  g_bwsum;
__device__ unsigned char  g_rmask[3*BSq];
__device__ unsigned short g_lst[(size_t)BSq*Sq];
__device__ int g_cnt[BSq*4];

__device__ __forceinline__ float leaky02(float x){ return x > 0.f ? x : 0.2f*x; }
__device__ __forceinline__ float elu1(float x){ return x > 0.f ? x : expm1f(x); }
__device__ __forceinline__ void mma_f16(float c[4], unsigned a0,unsigned a1,unsigned a2,unsigned a3,
                                        unsigned b0,unsigned b1){
    asm volatile("mma.sync.aligned.m16n8k16.row.col.f32.f16.f16.f32 "
        "{%0,%1,%2,%3},{%4,%5,%6,%7},{%8,%9},{%0,%1,%2,%3};"
        : "+f"(c[0]),"+f"(c[1]),"+f"(c[2]),"+f"(c[3])
        : "r"(a0),"r"(a1),"r"(a2),"r"(a3),"r"(b0),"r"(b1));
}

// ---------------- zero init (small accumulators only) ----------------
__global__ void k_zero(){
    int i = blockIdx.x*256 + threadIdx.x;
    if (i < NEXP*Bq*NHq) g_hsum[i] = 0.f;
    if (i < NEXP*Bq*Dq)  g_h2sum[i] = 0.f;
    if (i == 0) g_bwsum = 0.f;
}

// ---------------- fp16 operand prep ----------------
__global__ void k_prep(const float* __restrict__ feature,
                       const float* __restrict__ mainW1, const float* __restrict__ depW1,
                       const float* __restrict__ mainW2, const float* __restrict__ depW2,
                       const float* __restrict__ blendW){
    int task = blockIdx.y;
    int i = blockIdx.x*256 + threadIdx.x;
    if (task == 0){
        g_feat_h[i] = __float2half(feature[i]);
    } else if (task == 1){
        if (i < NEXP*NHq*Dq){
            int e = i/(NHq*Dq), r = i%(NHq*Dq), n = r/Dq, k = r%Dq;
            int h = n>>6, o = n&63;
            const float* src = (e==0)? mainW1 : depW1 + (size_t)(e-1)*Hq*Dq*HDq;
            g_W1t_h[i] = __float2half(src[(size_t)h*Dq*HDq + (size_t)k*HDq + o]);
        }
    } else if (task == 2){
        if (i < NEXP*Dq*NHq){
            int e = i/(Dq*NHq), r = i%(Dq*NHq), n = r/NHq, k = r%NHq;
            const float* src = (e==0)? mainW2 : depW2 + (size_t)(e-1)*NHq*Dq;
            g_W2t_h[i] = __float2half(src[(size_t)k*Dq + n]);
        }
    } else {
        if (i < Dq*Dq){
            int n = i/Dq, k = i%Dq;
            g_bWt_h[i] = __float2half(blendW[(size_t)k*Dq + n]);
        }
    }
}

// ---------------- neighbor lists ----------------
__global__ void k_nbr(const float* __restrict__ adj, const int* __restrict__ dnum,
                      const int* __restrict__ snum){
    __shared__ int sc[256];
    __shared__ int ra[256], rb[256];
    int bs = blockIdx.x, tid = threadIdx.x;
    int doc = dnum[0], sect = snum[0];
    int lim1 = Sq - sect - doc, lim2 = Sq - doc;
    const float* arow = adj + (size_t)bs*Sq;
    float4 a = *(const float4*)(arow + tid*4);
    unsigned short loc[4]; int c=0, ca=0, cb=0;
    float av[4] = {a.x,a.y,a.z,a.w};
    #pragma unroll
    for (int i=0;i<4;i++){
        int col = tid*4+i;
        if (av[i] > 0.f){ loc[c++] = (unsigned short)col; ca += (col<lim1); cb += (col<lim2); }
    }
    sc[tid]=c; ra[tid]=ca; rb[tid]=cb;
    __syncthreads();
    for (int off=1; off<256; off<<=1){
        int v = (tid>=off)? sc[tid-off] : 0;
        __syncthreads();
        sc[tid]+=v;
        __syncthreads();
    }
    int base = sc[tid]-c;
    for (int i=0;i<c;i++) g_lst[(size_t)bs*Sq + base + i] = loc[i];
    for (int st=128; st>0; st>>=1){
        if (tid<st){ ra[tid]+=ra[tid+st]; rb[tid]+=rb[tid+st]; }
        __syncthreads();
    }
    if (tid==0){
        g_cnt[bs*4+0]=ra[0]; g_cnt[bs*4+1]=rb[0]; g_cnt[bs*4+2]=sc[255]; g_cnt[bs*4+3]=0;
    }
}

// ---------------- router ----------------
__global__ void k_router(const float* __restrict__ x, const float* __restrict__ Wr){
    int gw   = (blockIdx.x*blockDim.x + threadIdx.x) >> 5;
    int lane = threadIdx.x & 31;
    if (gw >= BSq) return;
    const float* xr = x + (size_t)gw*Dq;
    float a0=0.f,a1=0.f,a2=0.f;
    for (int k=lane;k<Dq;k+=32){
        float xv = xr[k];
        a0 += xv*Wr[k*3+0]; a1 += xv*Wr[k*3+1]; a2 += xv*Wr[k*3+2];
    }
    #pragma unroll
    for (int o=16;o>0;o>>=1){
        a0 += __shfl_down_sync(0xffffffffu,a0,o);
        a1 += __shfl_down_sync(0xffffffffu,a1,o);
        a2 += __shfl_down_sync(0xffffffffu,a2,o);
    }
    if (lane==0){
        float v[3]={a0,a1,a2};
        int ex=0; float mv=v[0];
        #pragma unroll
        for (int e=1;e<3;e++) if (v[e]<=mv){ mv=v[e]; ex=e; }
        #pragma unroll
        for (int e=0;e<3;e++) g_rmask[e*BSq+gw] = (e==ex)?0:1;
    }
}

// ---------------- fp16 tensor-core GEMM (2-sync, m16n8k16) ----------------
template<int KD, int ND, bool MASK, bool SIG>
__global__ void __launch_bounds__(256) k_mmh(const __half* __restrict__ Abase, size_t astride,
                                             const __half* __restrict__ Btbase,
                                             float* __restrict__ Cbase, __half* __restrict__ Chbase,
                                             const float* __restrict__ bias){
    int e = blockIdx.z;
    const __half* A  = Abase + astride*e;
    const __half* Bt = Btbase + (size_t)e*ND*KD;
    float* Cf = Cbase ? Cbase + (size_t)e*BSq*ND : (float*)0;
    __half* Ch = Chbase ? Chbase + (size_t)e*BSq*ND : (__half*)0;
    int m0 = blockIdx.y*128, n0 = blockIdx.x*128;
    __shared__ __half2 As2[128][20];
    __shared__ __half2 Bs2[128][20];
    __shared__ float sred[256];
    int tid=threadIdx.x, lane=tid&31, wid=tid>>5;
    int wm=(wid&1)*64, wn=(wid>>1)*32;
    int gid=lane>>2, qid=lane&3;
    float c[4][4][4];
    #pragma unroll
    for (int mt=0;mt<4;mt++)
        #pragma unroll
        for (int nt=0;nt<4;nt++)
            #pragma unroll
            for (int r=0;r<4;r++) c[mt][nt][r]=0.f;
    int row = tid>>1;
    int kh  = (tid&1)*16;
    int kc2 = (tid&1)*8;
    bool amask = true;
    if (MASK){ if (e>0 && g_rmask[(size_t)(e-1)*BSq + m0 + row]==0) amask = false; }
    const __half* Ap  = A  + (size_t)(m0+row)*KD + kh;
    const __half* Btp = Bt + (size_t)(n0+row)*KD + kh;

    for (int k0=0; k0<KD; k0+=32){
        uint4 va0 = *(const uint4*)(Ap + k0);
        uint4 va1 = *(const uint4*)(Ap + k0 + 8);
        uint4 vb0 = *(const uint4*)(Btp + k0);
        uint4 vb1 = *(const uint4*)(Btp + k0 + 8);
        if (MASK && !amask){ va0 = make_uint4(0,0,0,0); va1 = make_uint4(0,0,0,0); }
        __syncthreads();
        *(uint4*)&As2[row][kc2]   = va0;
        *(uint4*)&As2[row][kc2+4] = va1;
        *(uint4*)&Bs2[row][kc2]   = vb0;
        *(uint4*)&Bs2[row][kc2+4] = vb1;
        __syncthreads();
        #pragma unroll
        for (int sub=0; sub<2; sub++){
            unsigned af[4][4], bf[4][2];
            #pragma unroll
            for (int mt=0;mt<4;mt++){
                int r = wm + mt*16 + gid;
                af[mt][0]=*(unsigned*)&As2[r  ][sub*8+qid];
                af[mt][1]=*(unsigned*)&As2[r+8][sub*8+qid];
                af[mt][2]=*(unsigned*)&As2[r  ][sub*8+4+qid];
                af[mt][3]=*(unsigned*)&As2[r+8][sub*8+4+qid];
            }
            #pragma unroll
            for (int nt=0;nt<4;nt++){
                int cc = wn + nt*8 + gid;
                bf[nt][0]=*(unsigned*)&Bs2[cc][sub*8+qid];
                bf[nt][1]=*(unsigned*)&Bs2[cc][sub*8+4+qid];
            }
            #pragma unroll
            for (int mt=0;mt<4;mt++)
                #pragma unroll
                for (int nt=0;nt<4;nt++)
                    mma_f16(c[mt][nt], af[mt][0],af[mt][1],af[mt][2],af[mt][3],
                            bf[nt][0],bf[nt][1]);
        }
    }
    float lsum = 0.f;
    #pragma unroll
    for (int mt=0;mt<4;mt++){
        int orow = m0 + wm + mt*16 + gid;
        #pragma unroll
        for (int nt=0;nt<4;nt++){
            int col = n0 + wn + nt*8 + qid*2;
            float2 v0 = make_float2(c[mt][nt][0], c[mt][nt][1]);
            float2 v1 = make_float2(c[mt][nt][2], c[mt][nt][3]);
            if (SIG){
                float b0v = bias[col], b1v = bias[col+1];
                v0.x = 1.f/(1.f+expf(-(v0.x+b0v))); v0.y = 1.f/(1.f+expf(-(v0.y+b1v)));
                v1.x = 1.f/(1.f+expf(-(v1.x+b0v))); v1.y = 1.f/(1.f+expf(-(v1.y+b1v)));
                lsum += v0.x+v0.y+v1.x+v1.y;
            }
            if (Cf){
                *(float2*)&Cf[(size_t)orow*ND + col]     = v0;
                *(float2*)&Cf[(size_t)(orow+8)*ND + col] = v1;
            }
            if (Ch){
                *(__half2*)&Ch[(size_t)orow*ND + col]     = __float22half2_rn(v0);
                *(__half2*)&Ch[(size_t)(orow+8)*ND + col] = __float22half2_rn(v1);
            }
        }
    }
    if (SIG){
        sred[tid] = lsum;
        __syncthreads();
        for (int st=128; st>0; st>>=1){ if (tid<st) sred[tid]+=sred[tid+st]; __syncthreads(); }
        if (tid==0) atomicAdd(&g_bwsum, sred[0]);
    }
}

// ---------------- es/ed per (exp,bs,h) from fp16 h ----------------
__global__ void k_esed(const float* __restrict__ a1s_m, const float* __restrict__ a1d_m,
                       const float* __restrict__ a1s_d, const float* __restrict__ a1d_d){
    int gw   = (blockIdx.x*blockDim.x + threadIdx.x) >> 5;
    int lane = threadIdx.x & 31;
    if (gw >= NEXP*BSq*Hq) return;
    int h = gw % Hq, be = gw / Hq;
    int e = be / BSq;
    const float* as = ((e==0)? a1s_m : a1s_d + (size_t)(e-1)*NHq) + h*HDq;
    const float* ad = ((e==0)? a1d_m : a1d_d + (size_t)(e-1)*NHq) + h*HDq;
    const __half* hr = g_hh + (size_t)be*NHq + h*HDq;
    float2 hv = __half22float2(*(const __half2*)&hr[lane*2]);
    float s = hv.x*as[lane*2] + hv.y*as[lane*2+1];
    float d = hv.x*ad[lane*2] + hv.y*ad[lane*2+1];
    #pragma unroll
    for (int o=16;o>0;o>>=1){
        s += __shfl_down_sync(0xffffffffu,s,o);
        d += __shfl_down_sync(0xffffffffu,d,o);
    }
    if (lane==0){ g_es[be*8+h]=s; g_ed[be*8+h]=d; }
}

// ---------------- hsum (deputies only, chunked + atomic, fp16 src) ----------------
__global__ void k_hsum(){
    int eb = blockIdx.x + Bq;
    int chunk = blockIdx.y;
    int e = eb>>2, b = eb&3;
    const __half* base = g_hh + ((size_t)e*BSq + ((size_t)b<<10) + chunk*128)*NHq;
    int t = threadIdx.x;
    float acc = 0.f;
    for (int s=0;s<128;s++) acc += __half2float(base[(size_t)s*NHq + t]);
    atomicAdd(&g_hsum[(size_t)eb*NHq + t], acc);
}

// ---------------- attention layer 1 (192 thr, fp16 logits, 2-way gather) ----------
__global__ void __launch_bounds__(192) k_att1(){
    __shared__ unsigned short lst[1024];
    __shared__ unsigned char  ok[1024];
    __shared__ __half wh[6*1024];
    __shared__ float sred[6][8];
    __shared__ float ssum[6];
    __shared__ float es6[6];
    __shared__ float4 sacc[2][96];
    int bs = blockIdx.x, ex = blockIdx.y, b = bs>>10;
    int tid = threadIdx.x, lane = tid&31, wid = tid>>5;   // 6 warps
    int c1 = g_cnt[bs*4+0], c2 = g_cnt[bs*4+1], ct = g_cnt[bs*4+2];
    int lo, hi;
    if      (ex==0){ lo=0;  hi=ct; }
    else if (ex==1){ lo=0;  hi=c1; }
    else if (ex==2){ lo=c1; hi=c2; }
    else           { lo=c2; hi=ct; }
    int n = hi-lo;
    __half* h1row = g_h1h + ((size_t)ex*BSq + bs)*NHq;
    if (n==0){
        if (tid<96){
            float4 hv = *(const float4*)&g_hsum[(size_t)((ex<<2)|b)*NHq + tid*4];
            *(__half2*)&h1row[tid*4]   = __float22half2_rn(make_float2(elu1(hv.x*(1.f/Sq)), elu1(hv.y*(1.f/Sq))));
            *(__half2*)&h1row[tid*4+2] = __float22half2_rn(make_float2(elu1(hv.z*(1.f/Sq)), elu1(hv.w*(1.f/Sq))));
        }
        return;
    }
    for (int j=tid;j<n;j+=192) lst[j] = g_lst[(size_t)bs*Sq + lo + j];
    if (tid<6) es6[tid] = g_es[((size_t)ex*BSq + bs)*8 + tid];
    __syncthreads();
    const float* edb = g_ed + ((size_t)ex*BSq + ((size_t)b<<10))*8;
    const unsigned char* rm = (ex>0)? g_rmask + (size_t)(ex-1)*BSq + (b<<10) : nullptr;
    // phase A: logits + max
    float mx[6];
    #pragma unroll
    for (int h=0;h<6;h++) mx[h] = -1e30f;
    for (int j=tid;j<n;j+=192){
        int nb = lst[j];
        float4 e0 = *(const float4*)&edb[nb*8];
        float2 e1 = *(const float2*)&edb[nb*8+4];
        ok[j] = rm ? rm[nb] : 1;
        float ev[6] = {e0.x,e0.y,e0.z,e0.w,e1.x,e1.y};
        #pragma unroll
        for (int h=0;h<6;h++){
            float e = leaky02(es6[h] + ev[h]);
            wh[h*1024+j] = __float2half(e);
            mx[h] = fmaxf(mx[h], e);
        }
    }
    #pragma unroll
    for (int h=0;h<6;h++){
        #pragma unroll
        for (int o=16;o>0;o>>=1) mx[h] = fmaxf(mx[h], __shfl_xor_sync(0xffffffffu, mx[h], o));
    }
    if (lane==0){
        #pragma unroll
        for (int h=0;h<6;h++) sred[h][wid] = mx[h];
    }
    __syncthreads();
    float mxv[6];
    #pragma unroll
    for (int h=0;h<6;h++){
        float m = sred[h][0];
        #pragma unroll
        for (int wdx=1; wdx<6; wdx++) m = fmaxf(m, sred[h][wdx]);
        mxv[h] = m;
    }
    __syncthreads();
    // phase B: exp + sum
    float sm[6] = {0.f,0.f,0.f,0.f,0.f,0.f};
    for (int j=tid;j<n;j+=192){
        #pragma unroll
        for (int h=0;h<6;h++){
            float ww = expf(__half2float(wh[h*1024+j]) - mxv[h]);
            wh[h*1024+j] = __float2half(ww);
            sm[h] += ww;
        }
    }
    #pragma unroll
    for (int h=0;h<6;h++){
        #pragma unroll
        for (int o=16;o>0;o>>=1) sm[h] += __shfl_xor_sync(0xffffffffu, sm[h], o);
    }
    if (lane==0){
        #pragma unroll
        for (int h=0;h<6;h++) sred[h][wid] = sm[h];
    }
    __syncthreads();
    if (tid<6){
        float s = sred[tid][0];
        #pragma unroll
        for (int wdx=1; wdx<6; wdx++) s += sred[tid][wdx];
        ssum[tid] = s;
    }
    __syncthreads();
    // phase C: 2-way neighbor-split gather
    {
        int col = tid % 96, grp = tid / 96;   // grp 0/1
        int h = col >> 4;
        const __half* hb = g_hh + ((size_t)ex*BSq + ((size_t)b<<10))*NHq;
        float ax=0.f, ay=0.f, az=0.f, aw=0.f;
        for (int j=grp; j<n; j+=2){
            if (!ok[j]) continue;
            float wv = __half2float(wh[h*1024+j]);
            uint2 raw = *(const uint2*)&hb[(size_t)lst[j]*NHq + col*4];
            float2 p0 = __half22float2(*(__half2*)&raw.x);
            float2 p1 = __half22float2(*(__half2*)&raw.y);
            ax += wv*p0.x; ay += wv*p0.y; az += wv*p1.x; aw += wv*p1.y;
        }
        sacc[grp][col] = make_float4(ax,ay,az,aw);
    }
    __syncthreads();
    if (tid<96){
        int h = tid >> 4;
        float inv = 1.f/ssum[h];
        float4 a0 = sacc[0][tid], a1 = sacc[1][tid];
        *(__half2*)&h1row[tid*4]   = __float22half2_rn(make_float2(elu1((a0.x+a1.x)*inv), elu1((a0.y+a1.y)*inv)));
        *(__half2*)&h1row[tid*4+2] = __float22half2_rn(make_float2(elu1((a0.z+a1.z)*inv), elu1((a0.w+a1.w)*inv)));
    }
}

// ---------------- gs/gd per (exp,bs) from fp16 h2 ----------------
__global__ void k_gsgd(const float* __restrict__ a2s_m, const float* __restrict__ a2d_m,
                       const float* __restrict__ a2s_d, const float* __restrict__ a2d_d){
    int gw   = (blockIdx.x*blockDim.x + threadIdx.x) >> 5;
    int lane = threadIdx.x & 31;
    if (gw >= NEXP*BSq) return;
    int e = gw / BSq;
    const float* as = (e==0)? a2s_m : a2s_d + (size_t)(e-1)*Dq;
    const float* ad = (e==0)? a2d_m : a2d_d + (size_t)(e-1)*Dq;
    const __half* hr = g_h2h + (size_t)gw*Dq;
    float s=0.f, d=0.f;
    #pragma unroll
    for (int k=lane*4; k<Dq; k+=128){
        uint2 raw = *(const uint2*)&hr[k];
        float2 p0 = __half22float2(*(__half2*)&raw.x);
        float2 p1 = __half22float2(*(__half2*)&raw.y);
        s += p0.x*as[k] + p0.y*as[k+1] + p1.x*as[k+2] + p1.y*as[k+3];
        d += p0.x*ad[k] + p0.y*ad[k+1] + p1.x*ad[k+2] + p1.y*ad[k+3];
    }
    #pragma unroll
    for (int o=16;o>0;o>>=1){
        s += __shfl_down_sync(0xffffffffu,s,o);
        d += __shfl_down_sync(0xffffffffu,d,o);
    }
    if (lane==0){ g_gs[gw]=s; g_gd[gw]=d; }
}

// ---------------- h2sum (deputies only, chunked + atomic, fp16 src) ----------------
__global__ void k_h2sum(){
    int eb = blockIdx.x + Bq;
    int chunk = blockIdx.y;
    int e = eb>>2, b = eb&3;
    const __half* base = g_h2h + ((size_t)e*BSq + ((size_t)b<<10) + chunk*128)*Dq;
    int t = threadIdx.x;
    float acc = 0.f;
    for (int s=0;s<128;s++) acc += __half2float(base[(size_t)s*Dq + t]);
    atomicAdd(&g_h2sum[(size_t)eb*Dq + t], acc);
}

// ---------------- attention layer 2 (fp16 gather, plain stores) ----------------
__global__ void __launch_bounds__(256) k_att2(){
    __shared__ unsigned short lst[1024];
    __shared__ float w[1024];
    __shared__ float red[256];
    __shared__ float4 sacc[4][64];
    int bs = blockIdx.x, ex = blockIdx.y, b = bs>>10;
    int tid = threadIdx.x;
    if (ex>0 && g_rmask[(size_t)(ex-1)*BSq + bs]==0) return;
    float* outb = (ex==0)? g_main : g_depE + (size_t)(ex-1)*BSDq;
    int c1 = g_cnt[bs*4+0], c2 = g_cnt[bs*4+1], ct = g_cnt[bs*4+2];
    int lo, hi;
    if      (ex==0){ lo=0;  hi=ct; }
    else if (ex==1){ lo=0;  hi=c1; }
    else if (ex==2){ lo=c1; hi=c2; }
    else           { lo=c2; hi=ct; }
    int n = hi-lo;
    if (n==0){
        if (tid<64){
            float4 hv = *(const float4*)&g_h2sum[(size_t)((ex<<2)|b)*Dq + tid*4];
            *(float4*)&outb[(size_t)bs*Dq + tid*4] =
                make_float4(hv.x*(1.f/Sq), hv.y*(1.f/Sq), hv.z*(1.f/Sq), hv.w*(1.f/Sq));
        }
        return;
    }
    for (int j=tid;j<n;j+=256) lst[j] = g_lst[(size_t)bs*Sq + lo + j];
    __syncthreads();
    float gsv = g_gs[(size_t)ex*BSq + bs];
    const float* gdb = g_gd + (size_t)ex*BSq + (b<<10);
    float mloc = -1e30f;
    for (int j=tid;j<n;j+=256){
        float e = leaky02(gsv + gdb[lst[j]]);
        w[j]=e;
        mloc = fmaxf(mloc,e);
    }
    red[tid]=mloc; __syncthreads();
    for (int st=128;st>0;st>>=1){ if (tid<st) red[tid]=fmaxf(red[tid],red[tid+st]); __syncthreads(); }
    float m = red[0]; __syncthreads();
    float sloc = 0.f;
    for (int j=tid;j<n;j+=256){ float ww=expf(w[j]-m); w[j]=ww; sloc+=ww; }
    red[tid]=sloc; __syncthreads();
    for (int st=128;st>0;st>>=1){ if (tid<st) red[tid]+=red[tid+st]; __syncthreads(); }
    float inv = 1.f/red[0];
    int grp = tid>>6, q = tid&63;
    const __half* h2b = g_h2h + ((size_t)ex*BSq + ((size_t)b<<10))*Dq;
    float ax=0.f, ay=0.f, az=0.f, aw=0.f;
    for (int j=grp;j<n;j+=4){
        float wv = w[j];
        uint2 raw = *(const uint2*)&h2b[(size_t)lst[j]*Dq + q*4];
        float2 p0 = __half22float2(*(__half2*)&raw.x);
        float2 p1 = __half22float2(*(__half2*)&raw.y);
        ax += wv*p0.x; ay += wv*p0.y; az += wv*p1.x; aw += wv*p1.y;
    }
    sacc[grp][q] = make_float4(ax,ay,az,aw);
    __syncthreads();
    if (tid<64){
        float4 a0=sacc[0][tid], a1=sacc[1][tid], a2=sacc[2][tid], a3=sacc[3][tid];
        *(float4*)&outb[(size_t)bs*Dq + tid*4] =
            make_float4((a0.x+a1.x+a2.x+a3.x)*inv, (a0.y+a1.y+a2.y+a3.y)*inv,
                        (a0.z+a1.z+a2.z+a3.z)*inv, (a0.w+a1.w+a2.w+a3.w)*inv);
    }
}

// ---------------- final blend (one block per row, rmask-gated deputy sum) ----------
__global__ void k_final(float* __restrict__ out){
    __shared__ unsigned char msk[3];
    int bs = blockIdx.x, d = threadIdx.x;
    if (d<3) msk[d] = g_rmask[d*BSq+bs];
    __syncthreads();
    size_t i = (size_t)bs*Dq + d;
    float dep = 0.f;
    if (msk[0]) dep += g_depE[i];
    if (msk[1]) dep += g_depE[BSDq + i];
    if (msk[2]) dep += g_depE[2*(size_t)BSDq + i];
    float bw = g_bw[i];
    out[i] = bw*g_main[i] + (1.f-bw)*dep;
    if (bs==0 && d==0){
        float mc = g_bwsum * (1.f/(float)BSDq);
        out[BSDq]   = fabsf(mc - 0.6f) * 0.01f;
        out[BSDq+1] = mc;
    }
}

// ---------------- host launcher ----------------
extern "C" void kernel_launch(void* const* d_in, const int* in_sizes, int n_in,
                              void* d_out, int out_size){
    const float* feature  = (const float*)d_in[0];
    const float* adj      = (const float*)d_in[1];
    const float* main_W1  = (const float*)d_in[2];
    const float* main_a1s = (const float*)d_in[3];
    const float* main_a1d = (const float*)d_in[4];
    const float* main_W2  = (const float*)d_in[5];
    const float* main_a2s = (const float*)d_in[6];
    const float* main_a2d = (const float*)d_in[7];
    const float* dep_W1   = (const float*)d_in[8];
    const float* dep_a1s  = (const float*)d_in[9];
    const float* dep_a1d  = (const float*)d_in[10];
    const float* dep_W2   = (const float*)d_in[11];
    const float* dep_a2s  = (const float*)d_in[12];
    const float* dep_a2d  = (const float*)d_in[13];
    const float* router_W = (const float*)d_in[14];
    const float* blend_W  = (const float*)d_in[15];
    const float* blend_b  = (const float*)d_in[16];
    const int*   doc_num  = (const int*)d_in[17];
    const int*   sect_num = (const int*)d_in[18];
    float* out = (float*)d_out;

    __half* feat_h;  cudaGetSymbolAddress((void**)&feat_h,  g_feat_h);
    __half* W1t_h;   cudaGetSymbolAddress((void**)&W1t_h,   g_W1t_h);
    __half* W2t_h;   cudaGetSymbolAddress((void**)&W2t_h,   g_W2t_h);
    __half* bWt_h;   cudaGetSymbolAddress((void**)&bWt_h,   g_bWt_h);
    __half* h1h_p;   cudaGetSymbolAddress((void**)&h1h_p,   g_h1h);
    float*  bw_p;    cudaGetSymbolAddress((void**)&bw_p,    g_bw);
    __half* hh_p;    cudaGetSymbolAddress((void**)&hh_p,    g_hh);
    __half* h2h_p;   cudaGetSymbolAddress((void**)&h2h_p,   g_h2h);

    k_zero<<<(NEXP*Bq*NHq+255)/256, 256>>>();
    k_prep<<<dim3(BSq*Dq/256, 4), 256>>>(feature, main_W1, dep_W1, main_W2, dep_W2, blend_W);
    k_nbr<<<BSq, 256>>>(adj, doc_num, sect_num);
    k_router<<<BSq/4, 128>>>(feature, router_W);

    // blend: sigmoid fused into epilogue (fp32 out)
    k_mmh<Dq, Dq, false, true><<<dim3(2,32,1), 256>>>(feat_h, 0, bWt_h, bw_p, (__half*)0, blend_b);

    // layer-1 GEMM all experts (fp16 out only)
    k_mmh<Dq, NHq, true, false><<<dim3(3,32,NEXP), 256>>>(feat_h, 0, W1t_h, (float*)0, hh_p, (const float*)0);
    k_esed<<<(NEXP*BSq*Hq)/8, 256>>>(main_a1s, main_a1d, dep_a1s, dep_a1d);
    k_hsum<<<dim3((NEXP-1)*Bq, 8), NHq>>>();
    k_att1<<<dim3(BSq, NEXP), 192>>>();

    // layer-2 GEMM all experts (fp16 out only)
    k_mmh<NHq, Dq, false, false><<<dim3(2,32,NEXP), 256>>>(h1h_p, (size_t)BSq*NHq, W2t_h, (float*)0, h2h_p, (const float*)0);
    k_gsgd<<<(NEXP*BSq)/8, 256>>>(main_a2s, main_a2d, dep_a2s, dep_a2d);
    k_h2sum<<<dim3((NEXP-1)*Bq, 8), Dq>>>();
    k_att2<<<dim3(BSq, NEXP), 256>>>();

    k_final<<<BSq, Dq>>>(out);
}

// round 7
// speedup vs baseline: 1.9516x; 1.0545x over previous
#include <cuda_runtime.h>
#include <cuda_fp16.h>
#include <math.h>

// Fixed shapes
#define Bq 4
#define Sq 1024
#define Dq 256
#define Hq 6
#define HDq 64
#define NHq 384          // H*Hd
#define BSq 4096         // B*S
#define BSDq (BSq*Dq)
#define NEXP 4           // slot 0 = main, 1..3 = deputies

// ---------------- scratch ----------------
__device__ __half g_hh [(size_t)NEXP*BSq*NHq];   // layer-1 features (fp16)
__device__ __half g_h1h[(size_t)NEXP*BSq*NHq];   // layer-1 att output (fp16)
__device__ __half g_h2h[(size_t)NEXP*BSq*Dq];    // layer-2 features (fp16)
__device__ float  g_es [NEXP*BSq*8];
__device__ float  g_ed [NEXP*BSq*8];
__device__ float  g_hsum [NEXP*Bq*NHq];
__device__ float  g_h2sum[NEXP*Bq*Dq];
__device__ float  g_gs [NEXP*BSq];
__device__ float  g_gd [NEXP*BSq];
__device__ __half g_feat_h[(size_t)BSq*Dq];
__device__ __half g_W1t_h[(size_t)NEXP*NHq*Dq];  // [e][n][k]
__device__ __half g_W2t_h[(size_t)NEXP*Dq*NHq];  // [e][n][k]
__device__ __half g_bWt_h[(size_t)Dq*Dq];        // [n][k]
__device__ float  g_main[BSDq];
__device__ float  g_depE[3*(size_t)BSDq];
__device__ float  g_bw  [BSDq];
__device__ float  g_bwsum;
__device__ unsigned char  g_rmask[3*BSq];
__device__ unsigned short g_lst[(size_t)BSq*Sq];
__device__ int g_cnt[BSq*4];

__device__ __forceinline__ float leaky02(float x){ return x > 0.f ? x : 0.2f*x; }
__device__ __forceinline__ float elu1(float x){ return x > 0.f ? x : expm1f(x); }
__device__ __forceinline__ void mma_f16(float c[4], unsigned a0,unsigned a1,unsigned a2,unsigned a3,
                                        unsigned b0,unsigned b1){
    asm volatile("mma.sync.aligned.m16n8k16.row.col.f32.f16.f16.f32 "
        "{%0,%1,%2,%3},{%4,%5,%6,%7},{%8,%9},{%0,%1,%2,%3};"
        : "+f"(c[0]),"+f"(c[1]),"+f"(c[2]),"+f"(c[3])
        : "r"(a0),"r"(a1),"r"(a2),"r"(a3),"r"(b0),"r"(b1));
}

// ---------------- setup: fp16 operand prep + router + zeroing ----------------
__global__ void k_prep(const float* __restrict__ feature,
                       const float* __restrict__ mainW1, const float* __restrict__ depW1,
                       const float* __restrict__ mainW2, const float* __restrict__ depW2,
                       const float* __restrict__ blendW, const float* __restrict__ Wr){
    int task = blockIdx.y;
    int tid  = threadIdx.x;
    int i = blockIdx.x*256 + tid;
    if (task == 0){
        g_feat_h[i] = __float2half(feature[i]);
    } else if (task == 1){
        if (i < NEXP*NHq*Dq){
            int e = i/(NHq*Dq), r = i%(NHq*Dq), n = r/Dq, k = r%Dq;
            int h = n>>6, o = n&63;
            const float* src = (e==0)? mainW1 : depW1 + (size_t)(e-1)*Hq*Dq*HDq;
            g_W1t_h[i] = __float2half(src[(size_t)h*Dq*HDq + (size_t)k*HDq + o]);
        }
    } else if (task == 2){
        if (i < NEXP*Dq*NHq){
            int e = i/(Dq*NHq), r = i%(Dq*NHq), n = r/NHq, k = r%NHq;
            const float* src = (e==0)? mainW2 : depW2 + (size_t)(e-1)*NHq*Dq;
            g_W2t_h[i] = __float2half(src[(size_t)k*Dq + n]);
        }
    } else if (task == 3){
        if (i < Dq*Dq){
            int n = i/Dq, k = i%Dq;
            g_bWt_h[i] = __float2half(blendW[(size_t)k*Dq + n]);
        }
    } else if (task == 4){
        // router: 8 warps per block, one node each
        int gw = blockIdx.x*8 + (tid>>5);
        int lane = tid & 31;
        if (gw >= BSq) return;
        const float* xr = feature + (size_t)gw*Dq;
        float a0=0.f,a1=0.f,a2=0.f;
        for (int k=lane;k<Dq;k+=32){
            float xv = xr[k];
            a0 += xv*Wr[k*3+0]; a1 += xv*Wr[k*3+1]; a2 += xv*Wr[k*3+2];
        }
        #pragma unroll
        for (int o=16;o>0;o>>=1){
            a0 += __shfl_down_sync(0xffffffffu,a0,o);
            a1 += __shfl_down_sync(0xffffffffu,a1,o);
            a2 += __shfl_down_sync(0xffffffffu,a2,o);
        }
        if (lane==0){
            float v[3]={a0,a1,a2};
            int ex=0; float mv=v[0];
            #pragma unroll
            for (int e=1;e<3;e++) if (v[e]<=mv){ mv=v[e]; ex=e; }
            #pragma unroll
            for (int e=0;e<3;e++) g_rmask[e*BSq+gw] = (e==ex)?0:1;
        }
    } else {
        // zeroing of accumulators
        if (i < NEXP*BSq){ g_gs[i]=0.f; g_gd[i]=0.f; }
        if (i < NEXP*Bq*NHq) g_hsum[i]=0.f;
        if (i < NEXP*Bq*Dq)  g_h2sum[i]=0.f;
        if (i==0) g_bwsum = 0.f;
    }
}

// ---------------- neighbor lists ----------------
__global__ void k_nbr(const float* __restrict__ adj, const int* __restrict__ dnum,
                      const int* __restrict__ snum){
    __shared__ int sc[256];
    __shared__ int ra[256], rb[256];
    int bs = blockIdx.x, tid = threadIdx.x;
    int doc = dnum[0], sect = snum[0];
    int lim1 = Sq - sect - doc, lim2 = Sq - doc;
    const float* arow = adj + (size_t)bs*Sq;
    float4 a = *(const float4*)(arow + tid*4);
    unsigned short loc[4]; int c=0, ca=0, cb=0;
    float av[4] = {a.x,a.y,a.z,a.w};
    #pragma unroll
    for (int i=0;i<4;i++){
        int col = tid*4+i;
        if (av[i] > 0.f){ loc[c++] = (unsigned short)col; ca += (col<lim1); cb += (col<lim2); }
    }
    sc[tid]=c; ra[tid]=ca; rb[tid]=cb;
    __syncthreads();
    for (int off=1; off<256; off<<=1){
        int v = (tid>=off)? sc[tid-off] : 0;
        __syncthreads();
        sc[tid]+=v;
        __syncthreads();
    }
    int base = sc[tid]-c;
    for (int i=0;i<c;i++) g_lst[(size_t)bs*Sq + base + i] = loc[i];
    for (int st=128; st>0; st>>=1){
        if (tid<st){ ra[tid]+=ra[tid+st]; rb[tid]+=rb[tid+st]; }
        __syncthreads();
    }
    if (tid==0){
        g_cnt[bs*4+0]=ra[0]; g_cnt[bs*4+1]=rb[0]; g_cnt[bs*4+2]=sc[255]; g_cnt[bs*4+3]=0;
    }
}

// ---------------- fp16 tensor-core GEMM + fused row-dot epilogues ----------------
// DOT=0: none. DOT=1: per-head 64-col dots -> g_es/g_ed (plain store; block owns 2 heads).
// DOT=2: full-ND dots -> g_gs/g_gd (atomicAdd across 2 blocks).
template<int KD, int ND, bool MASK, bool SIG, int DOT>
__global__ void __launch_bounds__(256) k_mmh(const __half* __restrict__ Abase, size_t astride,
                                             const __half* __restrict__ Btbase,
                                             float* __restrict__ Cbase, __half* __restrict__ Chbase,
                                             const float* __restrict__ bias,
                                             const float* __restrict__ asM, const float* __restrict__ asD,
                                             const float* __restrict__ adM, const float* __restrict__ adD){
    int e = blockIdx.z;
    const __half* A  = Abase + astride*e;
    const __half* Bt = Btbase + (size_t)e*ND*KD;
    float* Cf = Cbase ? Cbase + (size_t)e*BSq*ND : (float*)0;
    __half* Ch = Chbase ? Chbase + (size_t)e*BSq*ND : (__half*)0;
    int m0 = blockIdx.y*128, n0 = blockIdx.x*128;
    __shared__ __half2 As2[128][20];
    __shared__ __half2 Bs2[128][20];
    __shared__ float sred[256];
    __shared__ float sAs[128], sAd[128];
    __shared__ float sdot[512];          // [row][head(2)] or [row] x2 quantities
    int tid=threadIdx.x, lane=tid&31, wid=tid>>5;
    int wm=(wid&1)*64, wn=(wid>>1)*32;
    int gid=lane>>2, qid=lane&3;
    if (DOT){
        if (tid<128){
            const float* as = (e==0)? asM : asD + (size_t)(e-1)*ND;
            const float* ad = (e==0)? adM : adD + (size_t)(e-1)*ND;
            sAs[tid] = as[n0+tid];
            sAd[tid] = ad[n0+tid];
        }
        sdot[tid] = 0.f; sdot[tid+256] = 0.f;
    }
    float c[4][4][4];
    #pragma unroll
    for (int mt=0;mt<4;mt++)
        #pragma unroll
        for (int nt=0;nt<4;nt++)
            #pragma unroll
            for (int r=0;r<4;r++) c[mt][nt][r]=0.f;
    int row = tid>>1;
    int kh  = (tid&1)*16;
    int kc2 = (tid&1)*8;
    bool amask = true;
    if (MASK){ if (e>0 && g_rmask[(size_t)(e-1)*BSq + m0 + row]==0) amask = false; }
    const __half* Ap  = A  + (size_t)(m0+row)*KD + kh;
    const __half* Btp = Bt + (size_t)(n0+row)*KD + kh;

    for (int k0=0; k0<KD; k0+=32){
        uint4 va0 = *(const uint4*)(Ap + k0);
        uint4 va1 = *(const uint4*)(Ap + k0 + 8);
        uint4 vb0 = *(const uint4*)(Btp + k0);
        uint4 vb1 = *(const uint4*)(Btp + k0 + 8);
        if (MASK && !amask){ va0 = make_uint4(0,0,0,0); va1 = make_uint4(0,0,0,0); }
        __syncthreads();
        *(uint4*)&As2[row][kc2]   = va0;
        *(uint4*)&As2[row][kc2+4] = va1;
        *(uint4*)&Bs2[row][kc2]   = vb0;
        *(uint4*)&Bs2[row][kc2+4] = vb1;
        __syncthreads();
        #pragma unroll
        for (int sub=0; sub<2; sub++){
            unsigned af[4][4], bf[4][2];
            #pragma unroll
            for (int mt=0;mt<4;mt++){
                int r = wm + mt*16 + gid;
                af[mt][0]=*(unsigned*)&As2[r  ][sub*8+qid];
                af[mt][1]=*(unsigned*)&As2[r+8][sub*8+qid];
                af[mt][2]=*(unsigned*)&As2[r  ][sub*8+4+qid];
                af[mt][3]=*(unsigned*)&As2[r+8][sub*8+4+qid];
            }
            #pragma unroll
            for (int nt=0;nt<4;nt++){
                int cc = wn + nt*8 + gid;
                bf[nt][0]=*(unsigned*)&Bs2[cc][sub*8+qid];
                bf[nt][1]=*(unsigned*)&Bs2[cc][sub*8+4+qid];
            }
            #pragma unroll
            for (int mt=0;mt<4;mt++)
                #pragma unroll
                for (int nt=0;nt<4;nt++)
                    mma_f16(c[mt][nt], af[mt][0],af[mt][1],af[mt][2],af[mt][3],
                            bf[nt][0],bf[nt][1]);
        }
    }
    float lsum = 0.f;
    #pragma unroll
    for (int mt=0;mt<4;mt++){
        int orow = m0 + wm + mt*16 + gid;
        float ds0=0.f, dd0=0.f, ds1=0.f, dd1=0.f;
        #pragma unroll
        for (int nt=0;nt<4;nt++){
            int lcol = wn + nt*8 + qid*2;
            int col = n0 + lcol;
            float2 v0 = make_float2(c[mt][nt][0], c[mt][nt][1]);
            float2 v1 = make_float2(c[mt][nt][2], c[mt][nt][3]);
            if (SIG){
                float b0v = bias[col], b1v = bias[col+1];
                v0.x = 1.f/(1.f+expf(-(v0.x+b0v))); v0.y = 1.f/(1.f+expf(-(v0.y+b1v)));
                v1.x = 1.f/(1.f+expf(-(v1.x+b0v))); v1.y = 1.f/(1.f+expf(-(v1.y+b1v)));
                lsum += v0.x+v0.y+v1.x+v1.y;
            }
            if (DOT){
                float a0=sAs[lcol], a1=sAs[lcol+1], d0=sAd[lcol], d1=sAd[lcol+1];
                ds0 += v0.x*a0 + v0.y*a1;  dd0 += v0.x*d0 + v0.y*d1;
                ds1 += v1.x*a0 + v1.y*a1;  dd1 += v1.x*d0 + v1.y*d1;
            }
            if (Cf){
                *(float2*)&Cf[(size_t)orow*ND + col]     = v0;
                *(float2*)&Cf[(size_t)(orow+8)*ND + col] = v1;
            }
            if (Ch){
                *(__half2*)&Ch[(size_t)orow*ND + col]     = __float22half2_rn(v0);
                *(__half2*)&Ch[(size_t)(orow+8)*ND + col] = __float22half2_rn(v1);
            }
        }
        if (DOT){
            ds0 += __shfl_down_sync(0xffffffffu, ds0, 2, 4); ds0 += __shfl_down_sync(0xffffffffu, ds0, 1, 4);
            dd0 += __shfl_down_sync(0xffffffffu, dd0, 2, 4); dd0 += __shfl_down_sync(0xffffffffu, dd0, 1, 4);
            ds1 += __shfl_down_sync(0xffffffffu, ds1, 2, 4); ds1 += __shfl_down_sync(0xffffffffu, ds1, 1, 4);
            dd1 += __shfl_down_sync(0xffffffffu, dd1, 2, 4); dd1 += __shfl_down_sync(0xffffffffu, dd1, 1, 4);
            if (qid==0){
                int rl = wm + mt*16 + gid;
                if (DOT==1){
                    int hh = wn>>6;                 // warp covers one head half
                    atomicAdd(&sdot[(rl  )*2+hh], ds0);
                    atomicAdd(&sdot[(rl+8)*2+hh], ds1);
                    atomicAdd(&sdot[256+(rl  )*2+hh], dd0);
                    atomicAdd(&sdot[256+(rl+8)*2+hh], dd1);
                } else {
                    atomicAdd(&sdot[rl],   ds0); atomicAdd(&sdot[rl+8],   ds1);
                    atomicAdd(&sdot[256+rl], dd0); atomicAdd(&sdot[256+rl+8], dd1);
                }
            }
        }
    }
    if (DOT){
        __syncthreads();
        if (DOT==1){
            int r = tid>>1, hh = tid&1;
            size_t idx = ((size_t)e*BSq + m0 + r)*8 + (n0>>6) + hh;
            g_es[idx] = sdot[tid];
            g_ed[idx] = sdot[256+tid];
        } else {
            if (tid<128){
                atomicAdd(&g_gs[(size_t)e*BSq + m0 + tid], sdot[tid]);
                atomicAdd(&g_gd[(size_t)e*BSq + m0 + tid], sdot[256+tid]);
            }
        }
    }
    if (SIG){
        sred[tid] = lsum;
        __syncthreads();
        for (int st=128; st>0; st>>=1){ if (tid<st) sred[tid]+=sred[tid+st]; __syncthreads(); }
        if (tid==0) atomicAdd(&g_bwsum, sred[0]);
    }
}

// ---------------- hsum (deputies only, chunked + atomic, fp16 src) ----------------
__global__ void k_hsum(){
    int eb = blockIdx.x + Bq;
    int chunk = blockIdx.y;
    int e = eb>>2, b = eb&3;
    const __half* base = g_hh + ((size_t)e*BSq + ((size_t)b<<10) + chunk*128)*NHq;
    int t = threadIdx.x;
    float acc = 0.f;
    for (int s=0;s<128;s++) acc += __half2float(base[(size_t)s*NHq + t]);
    atomicAdd(&g_hsum[(size_t)eb*NHq + t], acc);
}

// ---------------- attention layer 1 (192 thr, fp16 logits, 2-way gather) ----------
__global__ void __launch_bounds__(192) k_att1(){
    __shared__ unsigned short lst[1024];
    __shared__ unsigned char  ok[1024];
    __shared__ __half wh[6*1024];
    __shared__ float sred[6][8];
    __shared__ float ssum[6];
    __shared__ float es6[6];
    __shared__ float4 sacc[2][96];
    int bs = blockIdx.x, ex = blockIdx.y, b = bs>>10;
    int tid = threadIdx.x, lane = tid&31, wid = tid>>5;
    int c1 = g_cnt[bs*4+0], c2 = g_cnt[bs*4+1], ct = g_cnt[bs*4+2];
    int lo, hi;
    if      (ex==0){ lo=0;  hi=ct; }
    else if (ex==1){ lo=0;  hi=c1; }
    else if (ex==2){ lo=c1; hi=c2; }
    else           { lo=c2; hi=ct; }
    int n = hi-lo;
    __half* h1row = g_h1h + ((size_t)ex*BSq + bs)*NHq;
    if (n==0){
        if (tid<96){
            float4 hv = *(const float4*)&g_hsum[(size_t)((ex<<2)|b)*NHq + tid*4];
            *(__half2*)&h1row[tid*4]   = __float22half2_rn(make_float2(elu1(hv.x*(1.f/Sq)), elu1(hv.y*(1.f/Sq))));
            *(__half2*)&h1row[tid*4+2] = __float22half2_rn(make_float2(elu1(hv.z*(1.f/Sq)), elu1(hv.w*(1.f/Sq))));
        }
        return;
    }
    for (int j=tid;j<n;j+=192) lst[j] = g_lst[(size_t)bs*Sq + lo + j];
    if (tid<6) es6[tid] = g_es[((size_t)ex*BSq + bs)*8 + tid];
    __syncthreads();
    const float* edb = g_ed + ((size_t)ex*BSq + ((size_t)b<<10))*8;
    const unsigned char* rm = (ex>0)? g_rmask + (size_t)(ex-1)*BSq + (b<<10) : nullptr;
    float mx[6];
    #pragma unroll
    for (int h=0;h<6;h++) mx[h] = -1e30f;
    for (int j=tid;j<n;j+=192){
        int nb = lst[j];
        float4 e0 = *(const float4*)&edb[nb*8];
        float2 e1 = *(const float2*)&edb[nb*8+4];
        ok[j] = rm ? rm[nb] : 1;
        float ev[6] = {e0.x,e0.y,e0.z,e0.w,e1.x,e1.y};
        #pragma unroll
        for (int h=0;h<6;h++){
            float e = leaky02(es6[h] + ev[h]);
            wh[h*1024+j] = __float2half(e);
            mx[h] = fmaxf(mx[h], e);
        }
    }
    #pragma unroll
    for (int h=0;h<6;h++){
        #pragma unroll
        for (int o=16;o>0;o>>=1) mx[h] = fmaxf(mx[h], __shfl_xor_sync(0xffffffffu, mx[h], o));
    }
    if (lane==0){
        #pragma unroll
        for (int h=0;h<6;h++) sred[h][wid] = mx[h];
    }
    __syncthreads();
    float mxv[6];
    #pragma unroll
    for (int h=0;h<6;h++){
        float m = sred[h][0];
        #pragma unroll
        for (int wdx=1; wdx<6; wdx++) m = fmaxf(m, sred[h][wdx]);
        mxv[h] = m;
    }
    __syncthreads();
    float sm[6] = {0.f,0.f,0.f,0.f,0.f,0.f};
    for (int j=tid;j<n;j+=192){
        #pragma unroll
        for (int h=0;h<6;h++){
            float ww = expf(__half2float(wh[h*1024+j]) - mxv[h]);
            wh[h*1024+j] = __float2half(ww);
            sm[h] += ww;
        }
    }
    #pragma unroll
    for (int h=0;h<6;h++){
        #pragma unroll
        for (int o=16;o>0;o>>=1) sm[h] += __shfl_xor_sync(0xffffffffu, sm[h], o);
    }
    if (lane==0){
        #pragma unroll
        for (int h=0;h<6;h++) sred[h][wid] = sm[h];
    }
    __syncthreads();
    if (tid<6){
        float s = sred[tid][0];
        #pragma unroll
        for (int wdx=1; wdx<6; wdx++) s += sred[tid][wdx];
        ssum[tid] = s;
    }
    __syncthreads();
    {
        int col = tid % 96, grp = tid / 96;
        int h = col >> 4;
        const __half* hb = g_hh + ((size_t)ex*BSq + ((size_t)b<<10))*NHq;
        float ax=0.f, ay=0.f, az=0.f, aw=0.f;
        for (int j=grp; j<n; j+=2){
            if (!ok[j]) continue;
            float wv = __half2float(wh[h*1024+j]);
            uint2 raw = *(const uint2*)&hb[(size_t)lst[j]*NHq + col*4];
            float2 p0 = __half22float2(*(__half2*)&raw.x);
            float2 p1 = __half22float2(*(__half2*)&raw.y);
            ax += wv*p0.x; ay += wv*p0.y; az += wv*p1.x; aw += wv*p1.y;
        }
        sacc[grp][col] = make_float4(ax,ay,az,aw);
    }
    __syncthreads();
    if (tid<96){
        int h = tid >> 4;
        float inv = 1.f/ssum[h];
        float4 a0 = sacc[0][tid], a1 = sacc[1][tid];
        *(__half2*)&h1row[tid*4]   = __float22half2_rn(make_float2(elu1((a0.x+a1.x)*inv), elu1((a0.y+a1.y)*inv)));
        *(__half2*)&h1row[tid*4+2] = __float22half2_rn(make_float2(elu1((a0.z+a1.z)*inv), elu1((a0.w+a1.w)*inv)));
    }
}

// ---------------- h2sum (deputies only, chunked + atomic, fp16 src) ----------------
__global__ void k_h2sum(){
    int eb = blockIdx.x + Bq;
    int chunk = blockIdx.y;
    int e = eb>>2, b = eb&3;
    const __half* base = g_h2h + ((size_t)e*BSq + ((size_t)b<<10) + chunk*128)*Dq;
    int t = threadIdx.x;
    float acc = 0.f;
    for (int s=0;s<128;s++) acc += __half2float(base[(size_t)s*Dq + t]);
    atomicAdd(&g_h2sum[(size_t)eb*Dq + t], acc);
}

// ---------------- attention layer 2 (fp16 gather, plain stores) ----------------
__global__ void __launch_bounds__(256) k_att2(){
    __shared__ unsigned short lst[1024];
    __shared__ float w[1024];
    __shared__ float red[256];
    __shared__ float4 sacc[4][64];
    int bs = blockIdx.x, ex = blockIdx.y, b = bs>>10;
    int tid = threadIdx.x;
    if (ex>0 && g_rmask[(size_t)(ex-1)*BSq + bs]==0) return;
    float* outb = (ex==0)? g_main : g_depE + (size_t)(ex-1)*BSDq;
    int c1 = g_cnt[bs*4+0], c2 = g_cnt[bs*4+1], ct = g_cnt[bs*4+2];
    int lo, hi;
    if      (ex==0){ lo=0;  hi=ct; }
    else if (ex==1){ lo=0;  hi=c1; }
    else if (ex==2){ lo=c1; hi=c2; }
    else           { lo=c2; hi=ct; }
    int n = hi-lo;
    if (n==0){
        if (tid<64){
            float4 hv = *(const float4*)&g_h2sum[(size_t)((ex<<2)|b)*Dq + tid*4];
            *(float4*)&outb[(size_t)bs*Dq + tid*4] =
                make_float4(hv.x*(1.f/Sq), hv.y*(1.f/Sq), hv.z*(1.f/Sq), hv.w*(1.f/Sq));
        }
        return;
    }
    for (int j=tid;j<n;j+=256) lst[j] = g_lst[(size_t)bs*Sq + lo + j];
    __syncthreads();
    float gsv = g_gs[(size_t)ex*BSq + bs];
    const float* gdb = g_gd + (size_t)ex*BSq + (b<<10);
    float mloc = -1e30f;
    for (int j=tid;j<n;j+=256){
        float e = leaky02(gsv + gdb[lst[j]]);
        w[j]=e;
        mloc = fmaxf(mloc,e);
    }
    red[tid]=mloc; __syncthreads();
    for (int st=128;st>0;st>>=1){ if (tid<st) red[tid]=fmaxf(red[tid],red[tid+st]); __syncthreads(); }
    float m = red[0]; __syncthreads();
    float sloc = 0.f;
    for (int j=tid;j<n;j+=256){ float ww=expf(w[j]-m); w[j]=ww; sloc+=ww; }
    red[tid]=sloc; __syncthreads();
    for (int st=128;st>0;st>>=1){ if (tid<st) red[tid]+=red[tid+st]; __syncthreads(); }
    float inv = 1.f/red[0];
    int grp = tid>>6, q = tid&63;
    const __half* h2b = g_h2h + ((size_t)ex*BSq + ((size_t)b<<10))*Dq;
    float ax=0.f, ay=0.f, az=0.f, aw=0.f;
    for (int j=grp;j<n;j+=4){
        float wv = w[j];
        uint2 raw = *(const uint2*)&h2b[(size_t)lst[j]*Dq + q*4];
        float2 p0 = __half22float2(*(__half2*)&raw.x);
        float2 p1 = __half22float2(*(__half2*)&raw.y);
        ax += wv*p0.x; ay += wv*p0.y; az += wv*p1.x; aw += wv*p1.y;
    }
    sacc[grp][q] = make_float4(ax,ay,az,aw);
    __syncthreads();
    if (tid<64){
        float4 a0=sacc[0][tid], a1=sacc[1][tid], a2=sacc[2][tid], a3=sacc[3][tid];
        *(float4*)&outb[(size_t)bs*Dq + tid*4] =
            make_float4((a0.x+a1.x+a2.x+a3.x)*inv, (a0.y+a1.y+a2.y+a3.y)*inv,
                        (a0.z+a1.z+a2.z+a3.z)*inv, (a0.w+a1.w+a2.w+a3.w)*inv);
    }
}

// ---------------- final blend ----------------
__global__ void k_final(float* __restrict__ out){
    __shared__ unsigned char msk[3];
    int bs = blockIdx.x, d = threadIdx.x;
    if (d<3) msk[d] = g_rmask[d*BSq+bs];
    __syncthreads();
    size_t i = (size_t)bs*Dq + d;
    float dep = 0.f;
    if (msk[0]) dep += g_depE[i];
    if (msk[1]) dep += g_depE[BSDq + i];
    if (msk[2]) dep += g_depE[2*(size_t)BSDq + i];
    float bw = g_bw[i];
    out[i] = bw*g_main[i] + (1.f-bw)*dep;
    if (bs==0 && d==0){
        float mc = g_bwsum * (1.f/(float)BSDq);
        out[BSDq]   = fabsf(mc - 0.6f) * 0.01f;
        out[BSDq+1] = mc;
    }
}

// ---------------- host launcher ----------------
extern "C" void kernel_launch(void* const* d_in, const int* in_sizes, int n_in,
                              void* d_out, int out_size){
    const float* feature  = (const float*)d_in[0];
    const float* adj      = (const float*)d_in[1];
    const float* main_W1  = (const float*)d_in[2];
    const float* main_a1s = (const float*)d_in[3];
    const float* main_a1d = (const float*)d_in[4];
    const float* main_W2  = (const float*)d_in[5];
    const float* main_a2s = (const float*)d_in[6];
    const float* main_a2d = (const float*)d_in[7];
    const float* dep_W1   = (const float*)d_in[8];
    const float* dep_a1s  = (const float*)d_in[9];
    const float* dep_a1d  = (const float*)d_in[10];
    const float* dep_W2   = (const float*)d_in[11];
    const float* dep_a2s  = (const float*)d_in[12];
    const float* dep_a2d  = (const float*)d_in[13];
    const float* router_W = (const float*)d_in[14];
    const float* blend_W  = (const float*)d_in[15];
    const float* blend_b  = (const float*)d_in[16];
    const int*   doc_num  = (const int*)d_in[17];
    const int*   sect_num = (const int*)d_in[18];
    float* out = (float*)d_out;

    __half* feat_h;  cudaGetSymbolAddress((void**)&feat_h,  g_feat_h);
    __half* W1t_h;   cudaGetSymbolAddress((void**)&W1t_h,   g_W1t_h);
    __half* W2t_h;   cudaGetSymbolAddress((void**)&W2t_h,   g_W2t_h);
    __half* bWt_h;   cudaGetSymbolAddress((void**)&bWt_h,   g_bWt_h);
    __half* h1h_p;   cudaGetSymbolAddress((void**)&h1h_p,   g_h1h);
    float*  bw_p;    cudaGetSymbolAddress((void**)&bw_p,    g_bw);
    __half* hh_p;    cudaGetSymbolAddress((void**)&hh_p,    g_hh);
    __half* h2h_p;   cudaGetSymbolAddress((void**)&h2h_p,   g_h2h);

    k_prep<<<dim3(BSq*Dq/256, 6), 256>>>(feature, main_W1, dep_W1, main_W2, dep_W2, blend_W, router_W);
    k_nbr<<<BSq, 256>>>(adj, doc_num, sect_num);

    // blend: sigmoid fused into epilogue (fp32 out)
    k_mmh<Dq, Dq, false, true, 0><<<dim3(2,32,1), 256>>>(feat_h, 0, bWt_h, bw_p, (__half*)0, blend_b,
                                                         (const float*)0,(const float*)0,(const float*)0,(const float*)0);

    // layer-1 GEMM all experts + fused es/ed
    k_mmh<Dq, NHq, true, false, 1><<<dim3(3,32,NEXP), 256>>>(feat_h, 0, W1t_h, (float*)0, hh_p, (const float*)0,
                                                             main_a1s, dep_a1s, main_a1d, dep_a1d);
    k_hsum<<<dim3((NEXP-1)*Bq, 8), NHq>>>();
    k_att1<<<dim3(BSq, NEXP), 192>>>();

    // layer-2 GEMM all experts + fused gs/gd
    k_mmh<NHq, Dq, false, false, 2><<<dim3(2,32,NEXP), 256>>>(h1h_p, (size_t)BSq*NHq, W2t_h, (float*)0, h2h_p, (const float*)0,
                                                              main_a2s, dep_a2s, main_a2d, dep_a2d);
    k_h2sum<<<dim3((NEXP-1)*Bq, 8), Dq>>>();
    k_att2<<<dim3(BSq, NEXP), 256>>>();

    k_final<<<BSq, Dq>>>(out);
}

// round 8
// speedup vs baseline: 2.0063x; 1.0280x over previous
#include <cuda_runtime.h>
#include <cuda_fp16.h>
#include <math.h>

// Fixed shapes
#define Bq 4
#define Sq 1024
#define Dq 256
#define Hq 6
#define HDq 64
#define NHq 384          // H*Hd
#define BSq 4096         // B*S
#define BSDq (BSq*Dq)
#define NEXP 4           // slot 0 = main, 1..3 = deputies

// ---------------- scratch ----------------
__device__ __half g_hh [(size_t)NEXP*BSq*NHq];
__device__ __half g_h1h[(size_t)NEXP*BSq*NHq];
__device__ __half g_h2h[(size_t)NEXP*BSq*Dq];
__device__ float  g_es [NEXP*BSq*8];
__device__ float  g_ed [NEXP*BSq*8];
__device__ float  g_hsum [NEXP*Bq*NHq];
__device__ float  g_h2sum[NEXP*Bq*Dq];
__device__ float  g_gs [NEXP*BSq];
__device__ float  g_gd [NEXP*BSq];
__device__ __half g_feat_h[(size_t)BSq*Dq];
__device__ __half g_W1t_h[(size_t)NEXP*NHq*Dq];  // [e][n][k]
__device__ __half g_W2t_h[(size_t)NEXP*Dq*NHq];  // [e][n][k]
__device__ __half g_bWt_h[(size_t)Dq*Dq];        // [n][k]
__device__ float  g_main[BSDq];
__device__ float  g_depE[3*(size_t)BSDq];
__device__ float  g_bw  [BSDq];
__device__ float  g_bwsum;
__device__ unsigned char  g_rmask[3*BSq];
__device__ unsigned short g_lst[(size_t)BSq*Sq];
__device__ int g_cnt[BSq*4];

__device__ __forceinline__ float leaky02(float x){ return x > 0.f ? x : 0.2f*x; }
__device__ __forceinline__ float elu1(float x){ return x > 0.f ? x : expm1f(x); }
__device__ __forceinline__ void mma_f16(float c[4], unsigned a0,unsigned a1,unsigned a2,unsigned a3,
                                        unsigned b0,unsigned b1){
    asm volatile("mma.sync.aligned.m16n8k16.row.col.f32.f16.f16.f32 "
        "{%0,%1,%2,%3},{%4,%5,%6,%7},{%8,%9},{%0,%1,%2,%3};"
        : "+f"(c[0]),"+f"(c[1]),"+f"(c[2]),"+f"(c[3])
        : "r"(a0),"r"(a1),"r"(a2),"r"(a3),"r"(b0),"r"(b1));
}
#define LDSM4(r0,r1,r2,r3,a) \
    asm volatile("ldmatrix.sync.aligned.m8n8.x4.shared.b16 {%0,%1,%2,%3},[%4];" \
        : "=r"(r0),"=r"(r1),"=r"(r2),"=r"(r3) : "r"(a))

// ---------------- setup: fp16 operand prep + router + zeroing ----------------
__global__ void k_prep(const float* __restrict__ feature,
                       const float* __restrict__ mainW1, const float* __restrict__ depW1,
                       const float* __restrict__ mainW2, const float* __restrict__ depW2,
                       const float* __restrict__ blendW, const float* __restrict__ Wr){
    int task = blockIdx.y;
    int tid  = threadIdx.x;
    int i = blockIdx.x*256 + tid;
    if (task == 0){
        g_feat_h[i] = __float2half(feature[i]);
    } else if (task == 1){
        if (i < NEXP*NHq*Dq){
            int e = i/(NHq*Dq), r = i%(NHq*Dq), n = r/Dq, k = r%Dq;
            int h = n>>6, o = n&63;
            const float* src = (e==0)? mainW1 : depW1 + (size_t)(e-1)*Hq*Dq*HDq;
            g_W1t_h[i] = __float2half(src[(size_t)h*Dq*HDq + (size_t)k*HDq + o]);
        }
    } else if (task == 2){
        if (i < NEXP*Dq*NHq){
            int e = i/(Dq*NHq), r = i%(Dq*NHq), n = r/NHq, k = r%NHq;
            const float* src = (e==0)? mainW2 : depW2 + (size_t)(e-1)*NHq*Dq;
            g_W2t_h[i] = __float2half(src[(size_t)k*Dq + n]);
        }
    } else if (task == 3){
        if (i < Dq*Dq){
            int n = i/Dq, k = i%Dq;
            g_bWt_h[i] = __float2half(blendW[(size_t)k*Dq + n]);
        }
    } else if (task == 4){
        int gw = blockIdx.x*8 + (tid>>5);
        int lane = tid & 31;
        if (gw >= BSq) return;
        const float* xr = feature + (size_t)gw*Dq;
        float a0=0.f,a1=0.f,a2=0.f;
        for (int k=lane;k<Dq;k+=32){
            float xv = xr[k];
            a0 += xv*Wr[k*3+0]; a1 += xv*Wr[k*3+1]; a2 += xv*Wr[k*3+2];
        }
        #pragma unroll
        for (int o=16;o>0;o>>=1){
            a0 += __shfl_down_sync(0xffffffffu,a0,o);
            a1 += __shfl_down_sync(0xffffffffu,a1,o);
            a2 += __shfl_down_sync(0xffffffffu,a2,o);
        }
        if (lane==0){
            float v[3]={a0,a1,a2};
            int ex=0; float mv=v[0];
            #pragma unroll
            for (int e=1;e<3;e++) if (v[e]<=mv){ mv=v[e]; ex=e; }
            #pragma unroll
            for (int e=0;e<3;e++) g_rmask[e*BSq+gw] = (e==ex)?0:1;
        }
    } else {
        if (i < NEXP*BSq){ g_gs[i]=0.f; g_gd[i]=0.f; }
        if (i < NEXP*Bq*NHq) g_hsum[i]=0.f;
        if (i < NEXP*Bq*Dq)  g_h2sum[i]=0.f;
        if (i==0) g_bwsum = 0.f;
    }
}

// ---------------- neighbor lists (warp-shfl scan, 2 syncs) ----------------
__global__ void k_nbr(const float* __restrict__ adj, const int* __restrict__ dnum,
                      const int* __restrict__ snum){
    __shared__ int wtot[8], wpre[8], r1t[8], r2t[8];
    int bs = blockIdx.x, tid = threadIdx.x, lane = tid&31, wid = tid>>5;
    int doc = dnum[0], sect = snum[0];
    int lim1 = Sq - sect - doc, lim2 = Sq - doc;
    const float* arow = adj + (size_t)bs*Sq;
    float4 a = *(const float4*)(arow + tid*4);
    unsigned short loc[4]; int c=0, ca=0, cb=0;
    float av[4] = {a.x,a.y,a.z,a.w};
    #pragma unroll
    for (int i=0;i<4;i++){
        int col = tid*4+i;
        if (av[i] > 0.f){ loc[c++] = (unsigned short)col; ca += (col<lim1); cb += (col<lim2); }
    }
    int scan = c;
    #pragma unroll
    for (int off=1; off<32; off<<=1){
        int v = __shfl_up_sync(0xffffffffu, scan, off);
        if (lane>=off) scan += v;
    }
    int wca = __reduce_add_sync(0xffffffffu, (unsigned)ca);
    int wcb = __reduce_add_sync(0xffffffffu, (unsigned)cb);
    if (lane==31) wtot[wid] = scan;
    if (lane==0){ r1t[wid]=wca; r2t[wid]=wcb; }
    __syncthreads();
    if (tid==0){
        int acc=0, sa=0, sb=0;
        #pragma unroll
        for (int wdx=0; wdx<8; wdx++){
            wpre[wdx]=acc; acc+=wtot[wdx]; sa+=r1t[wdx]; sb+=r2t[wdx];
        }
        g_cnt[bs*4+0]=sa; g_cnt[bs*4+1]=sb; g_cnt[bs*4+2]=acc; g_cnt[bs*4+3]=0;
    }
    __syncthreads();
    int base = wpre[wid] + scan - c;
    for (int i=0;i<c;i++) g_lst[(size_t)bs*Sq + base + i] = loc[i];
}

// ---------------- fp16 tensor-core GEMM (ldmatrix fragments) ----------------
template<int KD, int ND, bool MASK, bool SIG, int DOT>
__global__ void __launch_bounds__(256) k_mmh(const __half* __restrict__ Abase, size_t astride,
                                             const __half* __restrict__ Btbase,
                                             float* __restrict__ Cbase, __half* __restrict__ Chbase,
                                             const float* __restrict__ bias,
                                             const float* __restrict__ asM, const float* __restrict__ asD,
                                             const float* __restrict__ adM, const float* __restrict__ adD){
    int e = blockIdx.z;
    const __half* A  = Abase + astride*e;
    const __half* Bt = Btbase + (size_t)e*ND*KD;
    float* Cf = Cbase ? Cbase + (size_t)e*BSq*ND : (float*)0;
    __half* Ch = Chbase ? Chbase + (size_t)e*BSq*ND : (__half*)0;
    int m0 = blockIdx.y*128, n0 = blockIdx.x*128;
    __shared__ __half2 As2[128][20];
    __shared__ __half2 Bs2[128][20];
    __shared__ float sred[256];
    __shared__ float sAs[128], sAd[128];
    __shared__ float sdot[512];
    int tid=threadIdx.x, lane=tid&31, wid=tid>>5;
    int wm=(wid&1)*64, wn=(wid>>1)*32;
    int gid=lane>>2, qid=lane&3;
    if (DOT){
        if (tid<128){
            const float* as = (e==0)? asM : asD + (size_t)(e-1)*ND;
            const float* ad = (e==0)? adM : adD + (size_t)(e-1)*ND;
            sAs[tid] = as[n0+tid];
            sAd[tid] = ad[n0+tid];
        }
        sdot[tid] = 0.f; sdot[tid+256] = 0.f;
    }
    float c[4][4][4];
    #pragma unroll
    for (int mt=0;mt<4;mt++)
        #pragma unroll
        for (int nt=0;nt<4;nt++)
            #pragma unroll
            for (int r=0;r<4;r++) c[mt][nt][r]=0.f;
    int row = tid>>1;
    int kh  = (tid&1)*16;
    int kc2 = (tid&1)*8;
    bool amask = true;
    if (MASK){ if (e>0 && g_rmask[(size_t)(e-1)*BSq + m0 + row]==0) amask = false; }
    const __half* Ap  = A  + (size_t)(m0+row)*KD + kh;
    const __half* Btp = Bt + (size_t)(n0+row)*KD + kh;

    // ldmatrix lane-address components (halves units; row stride = 40 halves)
    unsigned As_base = (unsigned)__cvta_generic_to_shared(&As2[0][0]);
    unsigned Bs_base = (unsigned)__cvta_generic_to_shared(&Bs2[0][0]);
    int lr8 = lane & 7;
    int a_row = wm + lr8 + ((lane>>3)&1)*8;     // + mt*16
    int a_kof = ((lane>>4)&1)*8;                 // + sub*16
    int b_col = wn + lr8 + ((lane>>4)&1)*8;      // + ntp*16
    int b_kof = ((lane>>3)&1)*8;                 // + sub*16
    unsigned aAddr0 = As_base + (unsigned)(a_row*40 + a_kof)*2u;
    unsigned bAddr0 = Bs_base + (unsigned)(b_col*40 + b_kof)*2u;

    for (int k0=0; k0<KD; k0+=32){
        uint4 va0 = *(const uint4*)(Ap + k0);
        uint4 va1 = *(const uint4*)(Ap + k0 + 8);
        uint4 vb0 = *(const uint4*)(Btp + k0);
        uint4 vb1 = *(const uint4*)(Btp + k0 + 8);
        if (MASK && !amask){ va0 = make_uint4(0,0,0,0); va1 = make_uint4(0,0,0,0); }
        __syncthreads();
        *(uint4*)&As2[row][kc2]   = va0;
        *(uint4*)&As2[row][kc2+4] = va1;
        *(uint4*)&Bs2[row][kc2]   = vb0;
        *(uint4*)&Bs2[row][kc2+4] = vb1;
        __syncthreads();
        #pragma unroll
        for (int sub=0; sub<2; sub++){
            unsigned af[4][4], bf[2][4];
            #pragma unroll
            for (int mt=0;mt<4;mt++){
                unsigned ad = aAddr0 + (unsigned)(mt*16*40 + sub*16)*2u;
                LDSM4(af[mt][0],af[mt][1],af[mt][2],af[mt][3], ad);
            }
            #pragma unroll
            for (int ntp=0;ntp<2;ntp++){
                unsigned bd = bAddr0 + (unsigned)(ntp*16*40 + sub*16)*2u;
                LDSM4(bf[ntp][0],bf[ntp][1],bf[ntp][2],bf[ntp][3], bd);
            }
            #pragma unroll
            for (int mt=0;mt<4;mt++)
                #pragma unroll
                for (int nt=0;nt<4;nt++)
                    mma_f16(c[mt][nt], af[mt][0],af[mt][1],af[mt][2],af[mt][3],
                            bf[nt>>1][(nt&1)*2], bf[nt>>1][(nt&1)*2+1]);
        }
    }
    float lsum = 0.f;
    #pragma unroll
    for (int mt=0;mt<4;mt++){
        int orow = m0 + wm + mt*16 + gid;
        float ds0=0.f, dd0=0.f, ds1=0.f, dd1=0.f;
        #pragma unroll
        for (int nt=0;nt<4;nt++){
            int lcol = wn + nt*8 + qid*2;
            int col = n0 + lcol;
            float2 v0 = make_float2(c[mt][nt][0], c[mt][nt][1]);
            float2 v1 = make_float2(c[mt][nt][2], c[mt][nt][3]);
            if (SIG){
                float b0v = bias[col], b1v = bias[col+1];
                v0.x = 1.f/(1.f+expf(-(v0.x+b0v))); v0.y = 1.f/(1.f+expf(-(v0.y+b1v)));
                v1.x = 1.f/(1.f+expf(-(v1.x+b0v))); v1.y = 1.f/(1.f+expf(-(v1.y+b1v)));
                lsum += v0.x+v0.y+v1.x+v1.y;
            }
            if (DOT){
                float a0=sAs[lcol], a1=sAs[lcol+1], d0=sAd[lcol], d1=sAd[lcol+1];
                ds0 += v0.x*a0 + v0.y*a1;  dd0 += v0.x*d0 + v0.y*d1;
                ds1 += v1.x*a0 + v1.y*a1;  dd1 += v1.x*d0 + v1.y*d1;
            }
            if (Cf){
                *(float2*)&Cf[(size_t)orow*ND + col]     = v0;
                *(float2*)&Cf[(size_t)(orow+8)*ND + col] = v1;
            }
            if (Ch){
                *(__half2*)&Ch[(size_t)orow*ND + col]     = __float22half2_rn(v0);
                *(__half2*)&Ch[(size_t)(orow+8)*ND + col] = __float22half2_rn(v1);
            }
        }
        if (DOT){
            ds0 += __shfl_down_sync(0xffffffffu, ds0, 2, 4); ds0 += __shfl_down_sync(0xffffffffu, ds0, 1, 4);
            dd0 += __shfl_down_sync(0xffffffffu, dd0, 2, 4); dd0 += __shfl_down_sync(0xffffffffu, dd0, 1, 4);
            ds1 += __shfl_down_sync(0xffffffffu, ds1, 2, 4); ds1 += __shfl_down_sync(0xffffffffu, ds1, 1, 4);
            dd1 += __shfl_down_sync(0xffffffffu, dd1, 2, 4); dd1 += __shfl_down_sync(0xffffffffu, dd1, 1, 4);
            if (qid==0){
                int rl = wm + mt*16 + gid;
                if (DOT==1){
                    int hh = wn>>6;
                    atomicAdd(&sdot[(rl  )*2+hh], ds0);
                    atomicAdd(&sdot[(rl+8)*2+hh], ds1);
                    atomicAdd(&sdot[256+(rl  )*2+hh], dd0);
                    atomicAdd(&sdot[256+(rl+8)*2+hh], dd1);
                } else {
                    atomicAdd(&sdot[rl],   ds0); atomicAdd(&sdot[rl+8],   ds1);
                    atomicAdd(&sdot[256+rl], dd0); atomicAdd(&sdot[256+rl+8], dd1);
                }
            }
        }
    }
    if (DOT){
        __syncthreads();
        if (DOT==1){
            int r = tid>>1, hh = tid&1;
            size_t idx = ((size_t)e*BSq + m0 + r)*8 + (n0>>6) + hh;
            g_es[idx] = sdot[tid];
            g_ed[idx] = sdot[256+tid];
        } else {
            if (tid<128){
                atomicAdd(&g_gs[(size_t)e*BSq + m0 + tid], sdot[tid]);
                atomicAdd(&g_gd[(size_t)e*BSq + m0 + tid], sdot[256+tid]);
            }
        }
    }
    if (SIG){
        sred[tid] = lsum;
        __syncthreads();
        for (int st=128; st>0; st>>=1){ if (tid<st) sred[tid]+=sred[tid+st]; __syncthreads(); }
        if (tid==0) atomicAdd(&g_bwsum, sred[0]);
    }
}

// ---------------- hsum (deputies only) ----------------
__global__ void k_hsum(){
    int eb = blockIdx.x + Bq;
    int chunk = blockIdx.y;
    int e = eb>>2, b = eb&3;
    const __half* base = g_hh + ((size_t)e*BSq + ((size_t)b<<10) + chunk*128)*NHq;
    int t = threadIdx.x;
    float acc = 0.f;
    for (int s=0;s<128;s++) acc += __half2float(base[(size_t)s*NHq + t]);
    atomicAdd(&g_hsum[(size_t)eb*NHq + t], acc);
}

// ---------------- attention layer 1 ----------------
__global__ void __launch_bounds__(192) k_att1(){
    __shared__ unsigned short lst[1024];
    __shared__ unsigned char  ok[1024];
    __shared__ __half wh[6*1024];
    __shared__ float sred[6][8];
    __shared__ float ssum[6];
    __shared__ float es6[6];
    __shared__ float4 sacc[2][96];
    int bs = blockIdx.x, ex = blockIdx.y, b = bs>>10;
    int tid = threadIdx.x, lane = tid&31, wid = tid>>5;
    int c1 = g_cnt[bs*4+0], c2 = g_cnt[bs*4+1], ct = g_cnt[bs*4+2];
    int lo, hi;
    if      (ex==0){ lo=0;  hi=ct; }
    else if (ex==1){ lo=0;  hi=c1; }
    else if (ex==2){ lo=c1; hi=c2; }
    else           { lo=c2; hi=ct; }
    int n = hi-lo;
    __half* h1row = g_h1h + ((size_t)ex*BSq + bs)*NHq;
    if (n==0){
        if (tid<96){
            float4 hv = *(const float4*)&g_hsum[(size_t)((ex<<2)|b)*NHq + tid*4];
            *(__half2*)&h1row[tid*4]   = __float22half2_rn(make_float2(elu1(hv.x*(1.f/Sq)), elu1(hv.y*(1.f/Sq))));
            *(__half2*)&h1row[tid*4+2] = __float22half2_rn(make_float2(elu1(hv.z*(1.f/Sq)), elu1(hv.w*(1.f/Sq))));
        }
        return;
    }
    for (int j=tid;j<n;j+=192) lst[j] = g_lst[(size_t)bs*Sq + lo + j];
    if (tid<6) es6[tid] = g_es[((size_t)ex*BSq + bs)*8 + tid];
    __syncthreads();
    const float* edb = g_ed + ((size_t)ex*BSq + ((size_t)b<<10))*8;
    const unsigned char* rm = (ex>0)? g_rmask + (size_t)(ex-1)*BSq + (b<<10) : nullptr;
    float mx[6];
    #pragma unroll
    for (int h=0;h<6;h++) mx[h] = -1e30f;
    for (int j=tid;j<n;j+=192){
        int nb = lst[j];
        float4 e0 = *(const float4*)&edb[nb*8];
        float2 e1 = *(const float2*)&edb[nb*8+4];
        ok[j] = rm ? rm[nb] : 1;
        float ev[6] = {e0.x,e0.y,e0.z,e0.w,e1.x,e1.y};
        #pragma unroll
        for (int h=0;h<6;h++){
            float e = leaky02(es6[h] + ev[h]);
            wh[h*1024+j] = __float2half(e);
            mx[h] = fmaxf(mx[h], e);
        }
    }
    #pragma unroll
    for (int h=0;h<6;h++){
        #pragma unroll
        for (int o=16;o>0;o>>=1) mx[h] = fmaxf(mx[h], __shfl_xor_sync(0xffffffffu, mx[h], o));
    }
    if (lane==0){
        #pragma unroll
        for (int h=0;h<6;h++) sred[h][wid] = mx[h];
    }
    __syncthreads();
    float mxv[6];
    #pragma unroll
    for (int h=0;h<6;h++){
        float m = sred[h][0];
        #pragma unroll
        for (int wdx=1; wdx<6; wdx++) m = fmaxf(m, sred[h][wdx]);
        mxv[h] = m;
    }
    __syncthreads();
    float sm[6] = {0.f,0.f,0.f,0.f,0.f,0.f};
    for (int j=tid;j<n;j+=192){
        #pragma unroll
        for (int h=0;h<6;h++){
            float ww = expf(__half2float(wh[h*1024+j]) - mxv[h]);
            wh[h*1024+j] = __float2half(ww);
            sm[h] += ww;
        }
    }
    #pragma unroll
    for (int h=0;h<6;h++){
        #pragma unroll
        for (int o=16;o>0;o>>=1) sm[h] += __shfl_xor_sync(0xffffffffu, sm[h], o);
    }
    if (lane==0){
        #pragma unroll
        for (int h=0;h<6;h++) sred[h][wid] = sm[h];
    }
    __syncthreads();
    if (tid<6){
        float s = sred[tid][0];
        #pragma unroll
        for (int wdx=1; wdx<6; wdx++) s += sred[tid][wdx];
        ssum[tid] = s;
    }
    __syncthreads();
    {
        int col = tid % 96, grp = tid / 96;
        int h = col >> 4;
        const __half* hb = g_hh + ((size_t)ex*BSq + ((size_t)b<<10))*NHq;
        float ax=0.f, ay=0.f, az=0.f, aw=0.f;
        int j = grp;
        for (; j+2 < n; j += 4){
            float w0 = ok[j]   ? __half2float(wh[h*1024+j])   : 0.f;
            float w1 = ok[j+2] ? __half2float(wh[h*1024+j+2]) : 0.f;
            uint2 r0 = *(const uint2*)&hb[(size_t)lst[j]*NHq   + col*4];
            uint2 r1 = *(const uint2*)&hb[(size_t)lst[j+2]*NHq + col*4];
            float2 p00 = __half22float2(*(__half2*)&r0.x);
            float2 p01 = __half22float2(*(__half2*)&r0.y);
            float2 p10 = __half22float2(*(__half2*)&r1.x);
            float2 p11 = __half22float2(*(__half2*)&r1.y);
            ax += w0*p00.x + w1*p10.x; ay += w0*p00.y + w1*p10.y;
            az += w0*p01.x + w1*p11.x; aw += w0*p01.y + w1*p11.y;
        }
        for (; j < n; j += 2){
            float w0 = ok[j] ? __half2float(wh[h*1024+j]) : 0.f;
            uint2 r0 = *(const uint2*)&hb[(size_t)lst[j]*NHq + col*4];
            float2 p00 = __half22float2(*(__half2*)&r0.x);
            float2 p01 = __half22float2(*(__half2*)&r0.y);
            ax += w0*p00.x; ay += w0*p00.y; az += w0*p01.x; aw += w0*p01.y;
        }
        sacc[grp][col] = make_float4(ax,ay,az,aw);
    }
    __syncthreads();
    if (tid<96){
        int h = tid >> 4;
        float inv = 1.f/ssum[h];
        float4 a0 = sacc[0][tid], a1 = sacc[1][tid];
        *(__half2*)&h1row[tid*4]   = __float22half2_rn(make_float2(elu1((a0.x+a1.x)*inv), elu1((a0.y+a1.y)*inv)));
        *(__half2*)&h1row[tid*4+2] = __float22half2_rn(make_float2(elu1((a0.z+a1.z)*inv), elu1((a0.w+a1.w)*inv)));
    }
}

// ---------------- h2sum (deputies only) ----------------
__global__ void k_h2sum(){
    int eb = blockIdx.x + Bq;
    int chunk = blockIdx.y;
    int e = eb>>2, b = eb&3;
    const __half* base = g_h2h + ((size_t)e*BSq + ((size_t)b<<10) + chunk*128)*Dq;
    int t = threadIdx.x;
    float acc = 0.f;
    for (int s=0;s<128;s++) acc += __half2float(base[(size_t)s*Dq + t]);
    atomicAdd(&g_h2sum[(size_t)eb*Dq + t], acc);
}

// ---------------- attention layer 2 ----------------
__global__ void __launch_bounds__(256) k_att2(){
    __shared__ unsigned short lst[1024];
    __shared__ float w[1024];
    __shared__ float red[256];
    __shared__ float4 sacc[4][64];
    int bs = blockIdx.x, ex = blockIdx.y, b = bs>>10;
    int tid = threadIdx.x;
    if (ex>0 && g_rmask[(size_t)(ex-1)*BSq + bs]==0) return;
    float* outb = (ex==0)? g_main : g_depE + (size_t)(ex-1)*BSDq;
    int c1 = g_cnt[bs*4+0], c2 = g_cnt[bs*4+1], ct = g_cnt[bs*4+2];
    int lo, hi;
    if      (ex==0){ lo=0;  hi=ct; }
    else if (ex==1){ lo=0;  hi=c1; }
    else if (ex==2){ lo=c1; hi=c2; }
    else           { lo=c2; hi=ct; }
    int n = hi-lo;
    if (n==0){
        if (tid<64){
            float4 hv = *(const float4*)&g_h2sum[(size_t)((ex<<2)|b)*Dq + tid*4];
            *(float4*)&outb[(size_t)bs*Dq + tid*4] =
                make_float4(hv.x*(1.f/Sq), hv.y*(1.f/Sq), hv.z*(1.f/Sq), hv.w*(1.f/Sq));
        }
        return;
    }
    for (int j=tid;j<n;j+=256) lst[j] = g_lst[(size_t)bs*Sq + lo + j];
    __syncthreads();
    float gsv = g_gs[(size_t)ex*BSq + bs];
    const float* gdb = g_gd + (size_t)ex*BSq + (b<<10);
    float mloc = -1e30f;
    for (int j=tid;j<n;j+=256){
        float e = leaky02(gsv + gdb[lst[j]]);
        w[j]=e;
        mloc = fmaxf(mloc,e);
    }
    red[tid]=mloc; __syncthreads();
    for (int st=128;st>0;st>>=1){ if (tid<st) red[tid]=fmaxf(red[tid],red[tid+st]); __syncthreads(); }
    float m = red[0]; __syncthreads();
    float sloc = 0.f;
    for (int j=tid;j<n;j+=256){ float ww=expf(w[j]-m); w[j]=ww; sloc+=ww; }
    red[tid]=sloc; __syncthreads();
    for (int st=128;st>0;st>>=1){ if (tid<st) red[tid]+=red[tid+st]; __syncthreads(); }
    float inv = 1.f/red[0];
    int grp = tid>>6, q = tid&63;
    const __half* h2b = g_h2h + ((size_t)ex*BSq + ((size_t)b<<10))*Dq;
    float ax=0.f, ay=0.f, az=0.f, aw=0.f;
    int j = grp;
    for (; j+4 < n; j += 8){
        float w0 = w[j], w1 = w[j+4];
        uint2 r0 = *(const uint2*)&h2b[(size_t)lst[j]*Dq   + q*4];
        uint2 r1 = *(const uint2*)&h2b[(size_t)lst[j+4]*Dq + q*4];
        float2 p00 = __half22float2(*(__half2*)&r0.x);
        float2 p01 = __half22float2(*(__half2*)&r0.y);
        float2 p10 = __half22float2(*(__half2*)&r1.x);
        float2 p11 = __half22float2(*(__half2*)&r1.y);
        ax += w0*p00.x + w1*p10.x; ay += w0*p00.y + w1*p10.y;
        az += w0*p01.x + w1*p11.x; aw += w0*p01.y + w1*p11.y;
    }
    for (; j < n; j += 4){
        float w0 = w[j];
        uint2 r0 = *(const uint2*)&h2b[(size_t)lst[j]*Dq + q*4];
        float2 p00 = __half22float2(*(__half2*)&r0.x);
        float2 p01 = __half22float2(*(__half2*)&r0.y);
        ax += w0*p00.x; ay += w0*p00.y; az += w0*p01.x; aw += w0*p01.y;
    }
    sacc[grp][q] = make_float4(ax,ay,az,aw);
    __syncthreads();
    if (tid<64){
        float4 a0=sacc[0][tid], a1=sacc[1][tid], a2=sacc[2][tid], a3=sacc[3][tid];
        *(float4*)&outb[(size_t)bs*Dq + tid*4] =
            make_float4((a0.x+a1.x+a2.x+a3.x)*inv, (a0.y+a1.y+a2.y+a3.y)*inv,
                        (a0.z+a1.z+a2.z+a3.z)*inv, (a0.w+a1.w+a2.w+a3.w)*inv);
    }
}

// ---------------- final blend ----------------
__global__ void k_final(float* __restrict__ out){
    __shared__ unsigned char msk[3];
    int bs = blockIdx.x, d = threadIdx.x;
    if (d<3) msk[d] = g_rmask[d*BSq+bs];
    __syncthreads();
    size_t i = (size_t)bs*Dq + d;
    float dep = 0.f;
    if (msk[0]) dep += g_depE[i];
    if (msk[1]) dep += g_depE[BSDq + i];
    if (msk[2]) dep += g_depE[2*(size_t)BSDq + i];
    float bw = g_bw[i];
    out[i] = bw*g_main[i] + (1.f-bw)*dep;
    if (bs==0 && d==0){
        float mc = g_bwsum * (1.f/(float)BSDq);
        out[BSDq]   = fabsf(mc - 0.6f) * 0.01f;
        out[BSDq+1] = mc;
    }
}

// ---------------- host launcher ----------------
extern "C" void kernel_launch(void* const* d_in, const int* in_sizes, int n_in,
                              void* d_out, int out_size){
    const float* feature  = (const float*)d_in[0];
    const float* adj      = (const float*)d_in[1];
    const float* main_W1  = (const float*)d_in[2];
    const float* main_a1s = (const float*)d_in[3];
    const float* main_a1d = (const float*)d_in[4];
    const float* main_W2  = (const float*)d_in[5];
    const float* main_a2s = (const float*)d_in[6];
    const float* main_a2d = (const float*)d_in[7];
    const float* dep_W1   = (const float*)d_in[8];
    const float* dep_a1s  = (const float*)d_in[9];
    const float* dep_a1d  = (const float*)d_in[10];
    const float* dep_W2   = (const float*)d_in[11];
    const float* dep_a2s  = (const float*)d_in[12];
    const float* dep_a2d  = (const float*)d_in[13];
    const float* router_W = (const float*)d_in[14];
    const float* blend_W  = (const float*)d_in[15];
    const float* blend_b  = (const float*)d_in[16];
    const int*   doc_num  = (const int*)d_in[17];
    const int*   sect_num = (const int*)d_in[18];
    float* out = (float*)d_out;

    __half* feat_h;  cudaGetSymbolAddress((void**)&feat_h,  g_feat_h);
    __half* W1t_h;   cudaGetSymbolAddress((void**)&W1t_h,   g_W1t_h);
    __half* W2t_h;   cudaGetSymbolAddress((void**)&W2t_h,   g_W2t_h);
    __half* bWt_h;   cudaGetSymbolAddress((void**)&bWt_h,   g_bWt_h);
    __half* h1h_p;   cudaGetSymbolAddress((void**)&h1h_p,   g_h1h);
    float*  bw_p;    cudaGetSymbolAddress((void**)&bw_p,    g_bw);
    __half* hh_p;    cudaGetSymbolAddress((void**)&hh_p,    g_hh);
    __half* h2h_p;   cudaGetSymbolAddress((void**)&h2h_p,   g_h2h);

    k_prep<<<dim3(BSq*Dq/256, 6), 256>>>(feature, main_W1, dep_W1, main_W2, dep_W2, blend_W, router_W);
    k_nbr<<<BSq, 256>>>(adj, doc_num, sect_num);

    k_mmh<Dq, Dq, false, true, 0><<<dim3(2,32,1), 256>>>(feat_h, 0, bWt_h, bw_p, (__half*)0, blend_b,
                                                         (const float*)0,(const float*)0,(const float*)0,(const float*)0);

    k_mmh<Dq, NHq, true, false, 1><<<dim3(3,32,NEXP), 256>>>(feat_h, 0, W1t_h, (float*)0, hh_p, (const float*)0,
                                                             main_a1s, dep_a1s, main_a1d, dep_a1d);
    k_hsum<<<dim3((NEXP-1)*Bq, 8), NHq>>>();
    k_att1<<<dim3(BSq, NEXP), 192>>>();

    k_mmh<NHq, Dq, false, false, 2><<<dim3(2,32,NEXP), 256>>>(h1h_p, (size_t)BSq*NHq, W2t_h, (float*)0, h2h_p, (const float*)0,
                                                              main_a2s, dep_a2s, main_a2d, dep_a2d);
    k_h2sum<<<dim3((NEXP-1)*Bq, 8), Dq>>>();
    k_att2<<<dim3(BSq, NEXP), 256>>>();

    k_final<<<BSq, Dq>>>(out);
}

// round 9
// speedup vs baseline: 2.0609x; 1.0273x over previous
#include <cuda_runtime.h>
#include <cuda_fp16.h>
#include <math.h>

// Fixed shapes
#define Bq 4
#define Sq 1024
#define Dq 256
#define Hq 6
#define HDq 64
#define NHq 384          // H*Hd
#define BSq 4096         // B*S
#define BSDq (BSq*Dq)
#define NEXP 4           // slot 0 = main, 1..3 = deputies

// ---------------- scratch ----------------
__device__ __half g_hh [(size_t)NEXP*BSq*NHq];
__device__ __half g_h1h[(size_t)NEXP*BSq*NHq];
__device__ __half g_h2h[(size_t)NEXP*BSq*Dq];
__device__ float  g_es [NEXP*BSq*8];
__device__ float  g_ed [NEXP*BSq*8];
__device__ float  g_hsum [NEXP*Bq*NHq];
__device__ float  g_h2sum[NEXP*Bq*Dq];
__device__ float  g_gs [NEXP*BSq];
__device__ float  g_gd [NEXP*BSq];
__device__ __half g_feat_h[(size_t)BSq*Dq];
__device__ __half g_W1t_h[(size_t)NEXP*NHq*Dq];  // [e][n][k]
__device__ __half g_W2t_h[(size_t)NEXP*Dq*NHq];  // [e][n][k]
__device__ __half g_bWt_h[(size_t)Dq*Dq];        // [n][k]
__device__ float  g_main[BSDq];
__device__ float  g_depE[3*(size_t)BSDq];
__device__ float  g_bw  [BSDq];
__device__ float  g_bwsum;
__device__ unsigned char  g_rmask[3*BSq];
__device__ unsigned short g_lst[(size_t)BSq*Sq];
__device__ int g_cnt[BSq*4];

__device__ __forceinline__ float leaky02(float x){ return x > 0.f ? x : 0.2f*x; }
__device__ __forceinline__ float elu1(float x){ return x > 0.f ? x : expm1f(x); }
__device__ __forceinline__ void mma_f16(float c[4], unsigned a0,unsigned a1,unsigned a2,unsigned a3,
                                        unsigned b0,unsigned b1){
    asm volatile("mma.sync.aligned.m16n8k16.row.col.f32.f16.f16.f32 "
        "{%0,%1,%2,%3},{%4,%5,%6,%7},{%8,%9},{%0,%1,%2,%3};"
        : "+f"(c[0]),"+f"(c[1]),"+f"(c[2]),"+f"(c[3])
        : "r"(a0),"r"(a1),"r"(a2),"r"(a3),"r"(b0),"r"(b1));
}
#define LDSM4(r0,r1,r2,r3,a) \
    asm volatile("ldmatrix.sync.aligned.m8n8.x4.shared.b16 {%0,%1,%2,%3},[%4];" \
        : "=r"(r0),"=r"(r1),"=r"(r2),"=r"(r3) : "r"(a))
#define CPA16(dst,src,sz) \
    asm volatile("cp.async.cg.shared.global [%0], [%1], 16, %2;" :: "r"(dst),"l"(src),"r"(sz))
#define CPA_COMMIT() asm volatile("cp.async.commit_group;")

// ---------------- setup: fp16 operand prep + router + zeroing ----------------
__global__ void k_prep(const float* __restrict__ feature,
                       const float* __restrict__ mainW1, const float* __restrict__ depW1,
                       const float* __restrict__ mainW2, const float* __restrict__ depW2,
                       const float* __restrict__ blendW, const float* __restrict__ Wr){
    int task = blockIdx.y;
    int tid  = threadIdx.x;
    int i = blockIdx.x*256 + tid;
    if (task == 0){
        g_feat_h[i] = __float2half(feature[i]);
    } else if (task == 1){
        if (i < NEXP*NHq*Dq){
            int e = i/(NHq*Dq), r = i%(NHq*Dq), n = r/Dq, k = r%Dq;
            int h = n>>6, o = n&63;
            const float* src = (e==0)? mainW1 : depW1 + (size_t)(e-1)*Hq*Dq*HDq;
            g_W1t_h[i] = __float2half(src[(size_t)h*Dq*HDq + (size_t)k*HDq + o]);
        }
    } else if (task == 2){
        if (i < NEXP*Dq*NHq){
            int e = i/(Dq*NHq), r = i%(Dq*NHq), n = r/NHq, k = r%NHq;
            const float* src = (e==0)? mainW2 : depW2 + (size_t)(e-1)*NHq*Dq;
            g_W2t_h[i] = __float2half(src[(size_t)k*Dq + n]);
        }
    } else if (task == 3){
        if (i < Dq*Dq){
            int n = i/Dq, k = i%Dq;
            g_bWt_h[i] = __float2half(blendW[(size_t)k*Dq + n]);
        }
    } else if (task == 4){
        int gw = blockIdx.x*8 + (tid>>5);
        int lane = tid & 31;
        if (gw >= BSq) return;
        const float* xr = feature + (size_t)gw*Dq;
        float a0=0.f,a1=0.f,a2=0.f;
        for (int k=lane;k<Dq;k+=32){
            float xv = xr[k];
            a0 += xv*Wr[k*3+0]; a1 += xv*Wr[k*3+1]; a2 += xv*Wr[k*3+2];
        }
        #pragma unroll
        for (int o=16;o>0;o>>=1){
            a0 += __shfl_down_sync(0xffffffffu,a0,o);
            a1 += __shfl_down_sync(0xffffffffu,a1,o);
            a2 += __shfl_down_sync(0xffffffffu,a2,o);
        }
        if (lane==0){
            float v[3]={a0,a1,a2};
            int ex=0; float mv=v[0];
            #pragma unroll
            for (int e=1;e<3;e++) if (v[e]<=mv){ mv=v[e]; ex=e; }
            #pragma unroll
            for (int e=0;e<3;e++) g_rmask[e*BSq+gw] = (e==ex)?0:1;
        }
    } else {
        if (i < NEXP*BSq){ g_gs[i]=0.f; g_gd[i]=0.f; }
        if (i < NEXP*Bq*NHq) g_hsum[i]=0.f;
        if (i < NEXP*Bq*Dq)  g_h2sum[i]=0.f;
        if (i==0) g_bwsum = 0.f;
    }
}

// ---------------- neighbor lists (warp-shfl scan, 2 syncs) ----------------
__global__ void k_nbr(const float* __restrict__ adj, const int* __restrict__ dnum,
                      const int* __restrict__ snum){
    __shared__ int wtot[8], wpre[8], r1t[8], r2t[8];
    int bs = blockIdx.x, tid = threadIdx.x, lane = tid&31, wid = tid>>5;
    int doc = dnum[0], sect = snum[0];
    int lim1 = Sq - sect - doc, lim2 = Sq - doc;
    const float* arow = adj + (size_t)bs*Sq;
    float4 a = *(const float4*)(arow + tid*4);
    unsigned short loc[4]; int c=0, ca=0, cb=0;
    float av[4] = {a.x,a.y,a.z,a.w};
    #pragma unroll
    for (int i=0;i<4;i++){
        int col = tid*4+i;
        if (av[i] > 0.f){ loc[c++] = (unsigned short)col; ca += (col<lim1); cb += (col<lim2); }
    }
    int scan = c;
    #pragma unroll
    for (int off=1; off<32; off<<=1){
        int v = __shfl_up_sync(0xffffffffu, scan, off);
        if (lane>=off) scan += v;
    }
    int wca = __reduce_add_sync(0xffffffffu, (unsigned)ca);
    int wcb = __reduce_add_sync(0xffffffffu, (unsigned)cb);
    if (lane==31) wtot[wid] = scan;
    if (lane==0){ r1t[wid]=wca; r2t[wid]=wcb; }
    __syncthreads();
    if (tid==0){
        int acc=0, sa=0, sb=0;
        #pragma unroll
        for (int wdx=0; wdx<8; wdx++){
            wpre[wdx]=acc; acc+=wtot[wdx]; sa+=r1t[wdx]; sb+=r2t[wdx];
        }
        g_cnt[bs*4+0]=sa; g_cnt[bs*4+1]=sb; g_cnt[bs*4+2]=acc; g_cnt[bs*4+3]=0;
    }
    __syncthreads();
    int base = wpre[wid] + scan - c;
    for (int i=0;i<c;i++) g_lst[(size_t)bs*Sq + base + i] = loc[i];
}

// ---------------- fp16 tensor-core GEMM (cp.async 2-stage + ldmatrix) ----------------
template<int KD, int ND, bool MASK, bool SIG, int DOT>
__global__ void __launch_bounds__(256) k_mmh(const __half* __restrict__ Abase, size_t astride,
                                             const __half* __restrict__ Btbase,
                                             float* __restrict__ Cbase, __half* __restrict__ Chbase,
                                             const float* __restrict__ bias,
                                             const float* __restrict__ asM, const float* __restrict__ asD,
                                             const float* __restrict__ adM, const float* __restrict__ adD){
    int e = blockIdx.z;
    const __half* A  = Abase + astride*e;
    const __half* Bt = Btbase + (size_t)e*ND*KD;
    float* Cf = Cbase ? Cbase + (size_t)e*BSq*ND : (float*)0;
    __half* Ch = Chbase ? Chbase + (size_t)e*BSq*ND : (__half*)0;
    int m0 = blockIdx.y*128, n0 = blockIdx.x*128;
    __shared__ __half2 As2[2][128][20];
    __shared__ __half2 Bs2[2][128][20];
    __shared__ float sred[256];
    __shared__ float sAs[128], sAd[128];
    __shared__ float sdot[512];
    int tid=threadIdx.x, lane=tid&31, wid=tid>>5;
    int wm=(wid&1)*64, wn=(wid>>1)*32;
    int gid=lane>>2, qid=lane&3;
    if (DOT){
        if (tid<128){
            const float* as = (e==0)? asM : asD + (size_t)(e-1)*ND;
            const float* ad = (e==0)? adM : adD + (size_t)(e-1)*ND;
            sAs[tid] = as[n0+tid];
            sAd[tid] = ad[n0+tid];
        }
        sdot[tid] = 0.f; sdot[tid+256] = 0.f;
    }
    float c[4][4][4];
    #pragma unroll
    for (int mt=0;mt<4;mt++)
        #pragma unroll
        for (int nt=0;nt<4;nt++)
            #pragma unroll
            for (int r=0;r<4;r++) c[mt][nt][r]=0.f;
    int row = tid>>1;
    int kh  = (tid&1)*16;      // halves offset within 32-k tile
    int kc2 = (tid&1)*8;       // half2 offset in smem row
    bool amask = true;
    if (MASK){ if (e>0 && g_rmask[(size_t)(e-1)*BSq + m0 + row]==0) amask = false; }
    const __half* Ap  = A  + (size_t)(m0+row)*KD + kh;
    const __half* Btp = Bt + (size_t)(n0+row)*KD + kh;
    int szA = (MASK && !amask) ? 0 : 16;

    unsigned As_base = (unsigned)__cvta_generic_to_shared(&As2[0][0][0]);
    unsigned Bs_base = (unsigned)__cvta_generic_to_shared(&Bs2[0][0][0]);
    const unsigned STG_B = 128u*20u*4u;   // bytes per stage (10240)
    unsigned dstA = As_base + (unsigned)(row*20 + kc2)*4u;
    unsigned dstB = Bs_base + (unsigned)(row*20 + kc2)*4u;

#define PREFETCH(P, K0) { \
    CPA16(dstA + (P)*STG_B,      Ap  + (K0),     szA); \
    CPA16(dstA + (P)*STG_B + 16, Ap  + (K0) + 8, szA); \
    CPA16(dstB + (P)*STG_B,      Btp + (K0),     16); \
    CPA16(dstB + (P)*STG_B + 16, Btp + (K0) + 8, 16); \
    CPA_COMMIT(); }

    // ldmatrix lane-address components (halves units; row stride = 40 halves)
    int lr8 = lane & 7;
    int a_row = wm + lr8 + ((lane>>3)&1)*8;
    int a_kof = ((lane>>4)&1)*8;
    int b_col = wn + lr8 + ((lane>>4)&1)*8;
    int b_kof = ((lane>>3)&1)*8;
    unsigned aAddr0 = As_base + (unsigned)(a_row*40 + a_kof)*2u;
    unsigned bAddr0 = Bs_base + (unsigned)(b_col*40 + b_kof)*2u;

    const int NT = KD/32;
    PREFETCH(0, 0);
    #pragma unroll 2
    for (int it=0; it<NT; it++){
        if (it+1 < NT){
            PREFETCH((it+1)&1, (it+1)*32);
            asm volatile("cp.async.wait_group 1;");
        } else {
            asm volatile("cp.async.wait_group 0;");
        }
        __syncthreads();
        unsigned stOff = (unsigned)(it&1)*STG_B;
        #pragma unroll
        for (int sub=0; sub<2; sub++){
            unsigned af[4][4], bf[2][4];
            #pragma unroll
            for (int mt=0;mt<4;mt++){
                unsigned ad = aAddr0 + stOff + (unsigned)(mt*16*40 + sub*16)*2u;
                LDSM4(af[mt][0],af[mt][1],af[mt][2],af[mt][3], ad);
            }
            #pragma unroll
            for (int ntp=0;ntp<2;ntp++){
                unsigned bd = bAddr0 + stOff + (unsigned)(ntp*16*40 + sub*16)*2u;
                LDSM4(bf[ntp][0],bf[ntp][1],bf[ntp][2],bf[ntp][3], bd);
            }
            #pragma unroll
            for (int mt=0;mt<4;mt++)
                #pragma unroll
                for (int nt=0;nt<4;nt++)
                    mma_f16(c[mt][nt], af[mt][0],af[mt][1],af[mt][2],af[mt][3],
                            bf[nt>>1][(nt&1)*2], bf[nt>>1][(nt&1)*2+1]);
        }
        __syncthreads();
    }
#undef PREFETCH
    float lsum = 0.f;
    #pragma unroll
    for (int mt=0;mt<4;mt++){
        int orow = m0 + wm + mt*16 + gid;
        float ds0=0.f, dd0=0.f, ds1=0.f, dd1=0.f;
        #pragma unroll
        for (int nt=0;nt<4;nt++){
            int lcol = wn + nt*8 + qid*2;
            int col = n0 + lcol;
            float2 v0 = make_float2(c[mt][nt][0], c[mt][nt][1]);
            float2 v1 = make_float2(c[mt][nt][2], c[mt][nt][3]);
            if (SIG){
                float b0v = bias[col], b1v = bias[col+1];
                v0.x = 1.f/(1.f+expf(-(v0.x+b0v))); v0.y = 1.f/(1.f+expf(-(v0.y+b1v)));
                v1.x = 1.f/(1.f+expf(-(v1.x+b0v))); v1.y = 1.f/(1.f+expf(-(v1.y+b1v)));
                lsum += v0.x+v0.y+v1.x+v1.y;
            }
            if (DOT){
                float a0=sAs[lcol], a1=sAs[lcol+1], d0=sAd[lcol], d1=sAd[lcol+1];
                ds0 += v0.x*a0 + v0.y*a1;  dd0 += v0.x*d0 + v0.y*d1;
                ds1 += v1.x*a0 + v1.y*a1;  dd1 += v1.x*d0 + v1.y*d1;
            }
            if (Cf){
                *(float2*)&Cf[(size_t)orow*ND + col]     = v0;
                *(float2*)&Cf[(size_t)(orow+8)*ND + col] = v1;
            }
            if (Ch){
                *(__half2*)&Ch[(size_t)orow*ND + col]     = __float22half2_rn(v0);
                *(__half2*)&Ch[(size_t)(orow+8)*ND + col] = __float22half2_rn(v1);
            }
        }
        if (DOT){
            ds0 += __shfl_down_sync(0xffffffffu, ds0, 2, 4); ds0 += __shfl_down_sync(0xffffffffu, ds0, 1, 4);
            dd0 += __shfl_down_sync(0xffffffffu, dd0, 2, 4); dd0 += __shfl_down_sync(0xffffffffu, dd0, 1, 4);
            ds1 += __shfl_down_sync(0xffffffffu, ds1, 2, 4); ds1 += __shfl_down_sync(0xffffffffu, ds1, 1, 4);
            dd1 += __shfl_down_sync(0xffffffffu, dd1, 2, 4); dd1 += __shfl_down_sync(0xffffffffu, dd1, 1, 4);
            if (qid==0){
                int rl = wm + mt*16 + gid;
                if (DOT==1){
                    int hh = wn>>6;
                    atomicAdd(&sdot[(rl  )*2+hh], ds0);
                    atomicAdd(&sdot[(rl+8)*2+hh], ds1);
                    atomicAdd(&sdot[256+(rl  )*2+hh], dd0);
                    atomicAdd(&sdot[256+(rl+8)*2+hh], dd1);
                } else {
                    atomicAdd(&sdot[rl],   ds0); atomicAdd(&sdot[rl+8],   ds1);
                    atomicAdd(&sdot[256+rl], dd0); atomicAdd(&sdot[256+rl+8], dd1);
                }
            }
        }
    }
    if (DOT){
        __syncthreads();
        if (DOT==1){
            int r = tid>>1, hh = tid&1;
            size_t idx = ((size_t)e*BSq + m0 + r)*8 + (n0>>6) + hh;
            g_es[idx] = sdot[tid];
            g_ed[idx] = sdot[256+tid];
        } else {
            if (tid<128){
                atomicAdd(&g_gs[(size_t)e*BSq + m0 + tid], sdot[tid]);
                atomicAdd(&g_gd[(size_t)e*BSq + m0 + tid], sdot[256+tid]);
            }
        }
    }
    if (SIG){
        sred[tid] = lsum;
        __syncthreads();
        for (int st=128; st>0; st>>=1){ if (tid<st) sred[tid]+=sred[tid+st]; __syncthreads(); }
        if (tid==0) atomicAdd(&g_bwsum, sred[0]);
    }
}

// ---------------- hsum (deputies only) ----------------
__global__ void k_hsum(){
    int eb = blockIdx.x + Bq;
    int chunk = blockIdx.y;
    int e = eb>>2, b = eb&3;
    const __half* base = g_hh + ((size_t)e*BSq + ((size_t)b<<10) + chunk*128)*NHq;
    int t = threadIdx.x;
    float acc = 0.f;
    for (int s=0;s<128;s++) acc += __half2float(base[(size_t)s*NHq + t]);
    atomicAdd(&g_hsum[(size_t)eb*NHq + t], acc);
}

// ---------------- attention layer 1 ----------------
__global__ void __launch_bounds__(192) k_att1(){
    __shared__ unsigned short lst[1024];
    __shared__ unsigned char  ok[1024];
    __shared__ __half wh[6*1024];
    __shared__ float sred[6][8];
    __shared__ float ssum[6];
    __shared__ float es6[6];
    __shared__ float4 sacc[2][96];
    int bs = blockIdx.x, ex = blockIdx.y, b = bs>>10;
    int tid = threadIdx.x, lane = tid&31, wid = tid>>5;
    int c1 = g_cnt[bs*4+0], c2 = g_cnt[bs*4+1], ct = g_cnt[bs*4+2];
    int lo, hi;
    if      (ex==0){ lo=0;  hi=ct; }
    else if (ex==1){ lo=0;  hi=c1; }
    else if (ex==2){ lo=c1; hi=c2; }
    else           { lo=c2; hi=ct; }
    int n = hi-lo;
    __half* h1row = g_h1h + ((size_t)ex*BSq + bs)*NHq;
    if (n==0){
        if (tid<96){
            float4 hv = *(const float4*)&g_hsum[(size_t)((ex<<2)|b)*NHq + tid*4];
            *(__half2*)&h1row[tid*4]   = __float22half2_rn(make_float2(elu1(hv.x*(1.f/Sq)), elu1(hv.y*(1.f/Sq))));
            *(__half2*)&h1row[tid*4+2] = __float22half2_rn(make_float2(elu1(hv.z*(1.f/Sq)), elu1(hv.w*(1.f/Sq))));
        }
        return;
    }
    for (int j=tid;j<n;j+=192) lst[j] = g_lst[(size_t)bs*Sq + lo + j];
    if (tid<6) es6[tid] = g_es[((size_t)ex*BSq + bs)*8 + tid];
    __syncthreads();
    const float* edb = g_ed + ((size_t)ex*BSq + ((size_t)b<<10))*8;
    const unsigned char* rm = (ex>0)? g_rmask + (size_t)(ex-1)*BSq + (b<<10) : nullptr;
    float mx[6];
    #pragma unroll
    for (int h=0;h<6;h++) mx[h] = -1e30f;
    for (int j=tid;j<n;j+=192){
        int nb = lst[j];
        float4 e0 = *(const float4*)&edb[nb*8];
        float2 e1 = *(const float2*)&edb[nb*8+4];
        ok[j] = rm ? rm[nb] : 1;
        float ev[6] = {e0.x,e0.y,e0.z,e0.w,e1.x,e1.y};
        #pragma unroll
        for (int h=0;h<6;h++){
            float e = leaky02(es6[h] + ev[h]);
            wh[h*1024+j] = __float2half(e);
            mx[h] = fmaxf(mx[h], e);
        }
    }
    #pragma unroll
    for (int h=0;h<6;h++){
        #pragma unroll
        for (int o=16;o>0;o>>=1) mx[h] = fmaxf(mx[h], __shfl_xor_sync(0xffffffffu, mx[h], o));
    }
    if (lane==0){
        #pragma unroll
        for (int h=0;h<6;h++) sred[h][wid] = mx[h];
    }
    __syncthreads();
    float mxv[6];
    #pragma unroll
    for (int h=0;h<6;h++){
        float m = sred[h][0];
        #pragma unroll
        for (int wdx=1; wdx<6; wdx++) m = fmaxf(m, sred[h][wdx]);
        mxv[h] = m;
    }
    __syncthreads();
    float sm[6] = {0.f,0.f,0.f,0.f,0.f,0.f};
    for (int j=tid;j<n;j+=192){
        #pragma unroll
        for (int h=0;h<6;h++){
            float ww = expf(__half2float(wh[h*1024+j]) - mxv[h]);
            wh[h*1024+j] = __float2half(ww);
            sm[h] += ww;
        }
    }
    #pragma unroll
    for (int h=0;h<6;h++){
        #pragma unroll
        for (int o=16;o>0;o>>=1) sm[h] += __shfl_xor_sync(0xffffffffu, sm[h], o);
    }
    if (lane==0){
        #pragma unroll
        for (int h=0;h<6;h++) sred[h][wid] = sm[h];
    }
    __syncthreads();
    if (tid<6){
        float s = sred[tid][0];
        #pragma unroll
        for (int wdx=1; wdx<6; wdx++) s += sred[tid][wdx];
        ssum[tid] = s;
    }
    __syncthreads();
    {
        int col = tid % 96, grp = tid / 96;
        int h = col >> 4;
        const __half* hb = g_hh + ((size_t)ex*BSq + ((size_t)b<<10))*NHq;
        float ax=0.f, ay=0.f, az=0.f, aw=0.f;
        int j = grp;
        for (; j+2 < n; j += 4){
            float w0 = ok[j]   ? __half2float(wh[h*1024+j])   : 0.f;
            float w1 = ok[j+2] ? __half2float(wh[h*1024+j+2]) : 0.f;
            uint2 r0 = *(const uint2*)&hb[(size_t)lst[j]*NHq   + col*4];
            uint2 r1 = *(const uint2*)&hb[(size_t)lst[j+2]*NHq + col*4];
            float2 p00 = __half22float2(*(__half2*)&r0.x);
            float2 p01 = __half22float2(*(__half2*)&r0.y);
            float2 p10 = __half22float2(*(__half2*)&r1.x);
            float2 p11 = __half22float2(*(__half2*)&r1.y);
            ax += w0*p00.x + w1*p10.x; ay += w0*p00.y + w1*p10.y;
            az += w0*p01.x + w1*p11.x; aw += w0*p01.y + w1*p11.y;
        }
        for (; j < n; j += 2){
            float w0 = ok[j] ? __half2float(wh[h*1024+j]) : 0.f;
            uint2 r0 = *(const uint2*)&hb[(size_t)lst[j]*NHq + col*4];
            float2 p00 = __half22float2(*(__half2*)&r0.x);
            float2 p01 = __half22float2(*(__half2*)&r0.y);
            ax += w0*p00.x; ay += w0*p00.y; az += w0*p01.x; aw += w0*p01.y;
        }
        sacc[grp][col] = make_float4(ax,ay,az,aw);
    }
    __syncthreads();
    if (tid<96){
        int h = tid >> 4;
        float inv = 1.f/ssum[h];
        float4 a0 = sacc[0][tid], a1 = sacc[1][tid];
        *(__half2*)&h1row[tid*4]   = __float22half2_rn(make_float2(elu1((a0.x+a1.x)*inv), elu1((a0.y+a1.y)*inv)));
        *(__half2*)&h1row[tid*4+2] = __float22half2_rn(make_float2(elu1((a0.z+a1.z)*inv), elu1((a0.w+a1.w)*inv)));
    }
}

// ---------------- h2sum (deputies only) ----------------
__global__ void k_h2sum(){
    int eb = blockIdx.x + Bq;
    int chunk = blockIdx.y;
    int e = eb>>2, b = eb&3;
    const __half* base = g_h2h + ((size_t)e*BSq + ((size_t)b<<10) + chunk*128)*Dq;
    int t = threadIdx.x;
    float acc = 0.f;
    for (int s=0;s<128;s++) acc += __half2float(base[(size_t)s*Dq + t]);
    atomicAdd(&g_h2sum[(size_t)eb*Dq + t], acc);
}

// ---------------- attention layer 2 ----------------
__global__ void __launch_bounds__(256) k_att2(){
    __shared__ unsigned short lst[1024];
    __shared__ float w[1024];
    __shared__ float red[256];
    __shared__ float4 sacc[4][64];
    int bs = blockIdx.x, ex = blockIdx.y, b = bs>>10;
    int tid = threadIdx.x;
    if (ex>0 && g_rmask[(size_t)(ex-1)*BSq + bs]==0) return;
    float* outb = (ex==0)? g_main : g_depE + (size_t)(ex-1)*BSDq;
    int c1 = g_cnt[bs*4+0], c2 = g_cnt[bs*4+1], ct = g_cnt[bs*4+2];
    int lo, hi;
    if      (ex==0){ lo=0;  hi=ct; }
    else if (ex==1){ lo=0;  hi=c1; }
    else if (ex==2){ lo=c1; hi=c2; }
    else           { lo=c2; hi=ct; }
    int n = hi-lo;
    if (n==0){
        if (tid<64){
            float4 hv = *(const float4*)&g_h2sum[(size_t)((ex<<2)|b)*Dq + tid*4];
            *(float4*)&outb[(size_t)bs*Dq + tid*4] =
                make_float4(hv.x*(1.f/Sq), hv.y*(1.f/Sq), hv.z*(1.f/Sq), hv.w*(1.f/Sq));
        }
        return;
    }
    for (int j=tid;j<n;j+=256) lst[j] = g_lst[(size_t)bs*Sq + lo + j];
    __syncthreads();
    float gsv = g_gs[(size_t)ex*BSq + bs];
    const float* gdb = g_gd + (size_t)ex*BSq + (b<<10);
    float mloc = -1e30f;
    for (int j=tid;j<n;j+=256){
        float e = leaky02(gsv + gdb[lst[j]]);
        w[j]=e;
        mloc = fmaxf(mloc,e);
    }
    red[tid]=mloc; __syncthreads();
    for (int st=128;st>0;st>>=1){ if (tid<st) red[tid]=fmaxf(red[tid],red[tid+st]); __syncthreads(); }
    float m = red[0]; __syncthreads();
    float sloc = 0.f;
    for (int j=tid;j<n;j+=256){ float ww=expf(w[j]-m); w[j]=ww; sloc+=ww; }
    red[tid]=sloc; __syncthreads();
    for (int st=128;st>0;st>>=1){ if (tid<st) red[tid]+=red[tid+st]; __syncthreads(); }
    float inv = 1.f/red[0];
    int grp = tid>>6, q = tid&63;
    const __half* h2b = g_h2h + ((size_t)ex*BSq + ((size_t)b<<10))*Dq;
    float ax=0.f, ay=0.f, az=0.f, aw=0.f;
    int j = grp;
    for (; j+4 < n; j += 8){
        float w0 = w[j], w1 = w[j+4];
        uint2 r0 = *(const uint2*)&h2b[(size_t)lst[j]*Dq   + q*4];
        uint2 r1 = *(const uint2*)&h2b[(size_t)lst[j+4]*Dq + q*4];
        float2 p00 = __half22float2(*(__half2*)&r0.x);
        float2 p01 = __half22float2(*(__half2*)&r0.y);
        float2 p10 = __half22float2(*(__half2*)&r1.x);
        float2 p11 = __half22float2(*(__half2*)&r1.y);
        ax += w0*p00.x + w1*p10.x; ay += w0*p00.y + w1*p10.y;
        az += w0*p01.x + w1*p11.x; aw += w0*p01.y + w1*p11.y;
    }
    for (; j < n; j += 4){
        float w0 = w[j];
        uint2 r0 = *(const uint2*)&h2b[(size_t)lst[j]*Dq + q*4];
        float2 p00 = __half22float2(*(__half2*)&r0.x);
        float2 p01 = __half22float2(*(__half2*)&r0.y);
        ax += w0*p00.x; ay += w0*p00.y; az += w0*p01.x; aw += w0*p01.y;
    }
    sacc[grp][q] = make_float4(ax,ay,az,aw);
    __syncthreads();
    if (tid<64){
        float4 a0=sacc[0][tid], a1=sacc[1][tid], a2=sacc[2][tid], a3=sacc[3][tid];
        *(float4*)&outb[(size_t)bs*Dq + tid*4] =
            make_float4((a0.x+a1.x+a2.x+a3.x)*inv, (a0.y+a1.y+a2.y+a3.y)*inv,
                        (a0.z+a1.z+a2.z+a3.z)*inv, (a0.w+a1.w+a2.w+a3.w)*inv);
    }
}

// ---------------- final blend ----------------
__global__ void k_final(float* __restrict__ out){
    __shared__ unsigned char msk[3];
    int bs = blockIdx.x, d = threadIdx.x;
    if (d<3) msk[d] = g_rmask[d*BSq+bs];
    __syncthreads();
    size_t i = (size_t)bs*Dq + d;
    float dep = 0.f;
    if (msk[0]) dep += g_depE[i];
    if (msk[1]) dep += g_depE[BSDq + i];
    if (msk[2]) dep += g_depE[2*(size_t)BSDq + i];
    float bw = g_bw[i];
    out[i] = bw*g_main[i] + (1.f-bw)*dep;
    if (bs==0 && d==0){
        float mc = g_bwsum * (1.f/(float)BSDq);
        out[BSDq]   = fabsf(mc - 0.6f) * 0.01f;
        out[BSDq+1] = mc;
    }
}

// ---------------- host launcher ----------------
extern "C" void kernel_launch(void* const* d_in, const int* in_sizes, int n_in,
                              void* d_out, int out_size){
    const float* feature  = (const float*)d_in[0];
    const float* adj      = (const float*)d_in[1];
    const float* main_W1  = (const float*)d_in[2];
    const float* main_a1s = (const float*)d_in[3];
    const float* main_a1d = (const float*)d_in[4];
    const float* main_W2  = (const float*)d_in[5];
    const float* main_a2s = (const float*)d_in[6];
    const float* main_a2d = (const float*)d_in[7];
    const float* dep_W1   = (const float*)d_in[8];
    const float* dep_a1s  = (const float*)d_in[9];
    const float* dep_a1d  = (const float*)d_in[10];
    const float* dep_W2   = (const float*)d_in[11];
    const float* dep_a2s  = (const float*)d_in[12];
    const float* dep_a2d  = (const float*)d_in[13];
    const float* router_W = (const float*)d_in[14];
    const float* blend_W  = (const float*)d_in[15];
    const float* blend_b  = (const float*)d_in[16];
    const int*   doc_num  = (const int*)d_in[17];
    const int*   sect_num = (const int*)d_in[18];
    float* out = (float*)d_out;

    __half* feat_h;  cudaGetSymbolAddress((void**)&feat_h,  g_feat_h);
    __half* W1t_h;   cudaGetSymbolAddress((void**)&W1t_h,   g_W1t_h);
    __half* W2t_h;   cudaGetSymbolAddress((void**)&W2t_h,   g_W2t_h);
    __half* bWt_h;   cudaGetSymbolAddress((void**)&bWt_h,   g_bWt_h);
    __half* h1h_p;   cudaGetSymbolAddress((void**)&h1h_p,   g_h1h);
    float*  bw_p;    cudaGetSymbolAddress((void**)&bw_p,    g_bw);
    __half* hh_p;    cudaGetSymbolAddress((void**)&hh_p,    g_hh);
    __half* h2h_p;   cudaGetSymbolAddress((void**)&h2h_p,   g_h2h);

    k_prep<<<dim3(BSq*Dq/256, 6), 256>>>(feature, main_W1, dep_W1, main_W2, dep_W2, blend_W, router_W);
    k_nbr<<<BSq, 256>>>(adj, doc_num, sect_num);

    k_mmh<Dq, Dq, false, true, 0><<<dim3(2,32,1), 256>>>(feat_h, 0, bWt_h, bw_p, (__half*)0, blend_b,
                                                         (const float*)0,(const float*)0,(const float*)0,(const float*)0);

    k_mmh<Dq, NHq, true, false, 1><<<dim3(3,32,NEXP), 256>>>(feat_h, 0, W1t_h, (float*)0, hh_p, (const float*)0,
                                                             main_a1s, dep_a1s, main_a1d, dep_a1d);
    k_hsum<<<dim3((NEXP-1)*Bq, 8), NHq>>>();
    k_att1<<<dim3(BSq, NEXP), 192>>>();

    k_mmh<NHq, Dq, false, false, 2><<<dim3(2,32,NEXP), 256>>>(h1h_p, (size_t)BSq*NHq, W2t_h, (float*)0, h2h_p, (const float*)0,
                                                              main_a2s, dep_a2s, main_a2d, dep_a2d);
    k_h2sum<<<dim3((NEXP-1)*Bq, 8), Dq>>>();
    k_att2<<<dim3(BSq, NEXP), 256>>>();

    k_final<<<BSq, Dq>>>(out);
}

// round 10
// speedup vs baseline: 2.1428x; 1.0397x over previous
#include <cuda_runtime.h>
#include <cuda_fp16.h>
#include <math.h>

// Fixed shapes
#define Bq 4
#define Sq 1024
#define Dq 256
#define Hq 6
#define HDq 64
#define NHq 384          // H*Hd
#define BSq 4096         // B*S
#define BSDq (BSq*Dq)
#define NEXP 4           // slot 0 = main, 1..3 = deputies

// ---------------- scratch ----------------
__device__ __half g_hh [(size_t)NEXP*BSq*NHq];
__device__ __half g_h1h[(size_t)NEXP*BSq*NHq];
__device__ __half g_h2h[(size_t)NEXP*BSq*Dq];
__device__ float  g_es [NEXP*BSq*8];
__device__ float  g_ed [NEXP*BSq*8];
__device__ float  g_hsum [NEXP*Bq*NHq];
__device__ float  g_h2sum[NEXP*Bq*Dq];
__device__ float  g_gs [NEXP*BSq];
__device__ float  g_gd [NEXP*BSq];
__device__ __half g_feat_h[(size_t)BSq*Dq];
__device__ __half g_W1t_h[(size_t)NEXP*NHq*Dq];  // [e][n][k]
__device__ __half g_W2t_h[(size_t)NEXP*Dq*NHq];  // [e][n][k]
__device__ __half g_bWt_h[(size_t)Dq*Dq];        // [n][k]
__device__ float  g_main[BSDq];
__device__ float  g_depE[3*(size_t)BSDq];
__device__ float  g_bw  [BSDq];
__device__ float  g_bwsum;
__device__ unsigned char  g_rmask[3*BSq];
__device__ unsigned short g_lst[(size_t)BSq*Sq];
__device__ int g_cnt[BSq*4];

__device__ __forceinline__ float leaky02(float x){ return x > 0.f ? x : 0.2f*x; }
__device__ __forceinline__ float elu1(float x){ return x > 0.f ? x : expm1f(x); }
__device__ __forceinline__ void mma_f16(float c[4], unsigned a0,unsigned a1,unsigned a2,unsigned a3,
                                        unsigned b0,unsigned b1){
    asm volatile("mma.sync.aligned.m16n8k16.row.col.f32.f16.f16.f32 "
        "{%0,%1,%2,%3},{%4,%5,%6,%7},{%8,%9},{%0,%1,%2,%3};"
        : "+f"(c[0]),"+f"(c[1]),"+f"(c[2]),"+f"(c[3])
        : "r"(a0),"r"(a1),"r"(a2),"r"(a3),"r"(b0),"r"(b1));
}
#define LDSM4(r0,r1,r2,r3,a) \
    asm volatile("ldmatrix.sync.aligned.m8n8.x4.shared.b16 {%0,%1,%2,%3},[%4];" \
        : "=r"(r0),"=r"(r1),"=r"(r2),"=r"(r3) : "r"(a))
#define CPA16(dst,src,sz) \
    asm volatile("cp.async.cg.shared.global [%0], [%1], 16, %2;" :: "r"(dst),"l"(src),"r"(sz))
#define CPA_COMMIT() asm volatile("cp.async.commit_group;")

// ---------------- setup: fp16 operand prep + router + zeroing ----------------
__global__ void k_prep(const float* __restrict__ feature,
                       const float* __restrict__ mainW1, const float* __restrict__ depW1,
                       const float* __restrict__ mainW2, const float* __restrict__ depW2,
                       const float* __restrict__ blendW, const float* __restrict__ Wr){
    int task = blockIdx.y;
    int tid  = threadIdx.x;
    int i = blockIdx.x*256 + tid;
    if (task == 0){
        g_feat_h[i] = __float2half(feature[i]);
    } else if (task == 1){
        if (i < NEXP*NHq*Dq){
            int e = i/(NHq*Dq), r = i%(NHq*Dq), n = r/Dq, k = r%Dq;
            int h = n>>6, o = n&63;
            const float* src = (e==0)? mainW1 : depW1 + (size_t)(e-1)*Hq*Dq*HDq;
            g_W1t_h[i] = __float2half(src[(size_t)h*Dq*HDq + (size_t)k*HDq + o]);
        }
    } else if (task == 2){
        if (i < NEXP*Dq*NHq){
            int e = i/(Dq*NHq), r = i%(Dq*NHq), n = r/NHq, k = r%NHq;
            const float* src = (e==0)? mainW2 : depW2 + (size_t)(e-1)*NHq*Dq;
            g_W2t_h[i] = __float2half(src[(size_t)k*Dq + n]);
        }
    } else if (task == 3){
        if (i < Dq*Dq){
            int n = i/Dq, k = i%Dq;
            g_bWt_h[i] = __float2half(blendW[(size_t)k*Dq + n]);
        }
    } else if (task == 4){
        int gw = blockIdx.x*8 + (tid>>5);
        int lane = tid & 31;
        if (gw >= BSq) return;
        const float* xr = feature + (size_t)gw*Dq;
        float a0=0.f,a1=0.f,a2=0.f;
        for (int k=lane;k<Dq;k+=32){
            float xv = xr[k];
            a0 += xv*Wr[k*3+0]; a1 += xv*Wr[k*3+1]; a2 += xv*Wr[k*3+2];
        }
        #pragma unroll
        for (int o=16;o>0;o>>=1){
            a0 += __shfl_down_sync(0xffffffffu,a0,o);
            a1 += __shfl_down_sync(0xffffffffu,a1,o);
            a2 += __shfl_down_sync(0xffffffffu,a2,o);
        }
        if (lane==0){
            float v[3]={a0,a1,a2};
            int ex=0; float mv=v[0];
            #pragma unroll
            for (int e=1;e<3;e++) if (v[e]<=mv){ mv=v[e]; ex=e; }
            #pragma unroll
            for (int e=0;e<3;e++) g_rmask[e*BSq+gw] = (e==ex)?0:1;
        }
    } else {
        if (i < NEXP*BSq){ g_gs[i]=0.f; g_gd[i]=0.f; }
        if (i < NEXP*Bq*NHq) g_hsum[i]=0.f;
        if (i < NEXP*Bq*Dq)  g_h2sum[i]=0.f;
        if (i==0) g_bwsum = 0.f;
    }
}

// ---------------- neighbor lists (warp-shfl scan) ----------------
__global__ void k_nbr(const float* __restrict__ adj, const int* __restrict__ dnum,
                      const int* __restrict__ snum){
    __shared__ int wtot[8], wpre[8], r1t[8], r2t[8];
    int bs = blockIdx.x, tid = threadIdx.x, lane = tid&31, wid = tid>>5;
    int doc = dnum[0], sect = snum[0];
    int lim1 = Sq - sect - doc, lim2 = Sq - doc;
    const float* arow = adj + (size_t)bs*Sq;
    float4 a = *(const float4*)(arow + tid*4);
    unsigned short loc[4]; int c=0, ca=0, cb=0;
    float av[4] = {a.x,a.y,a.z,a.w};
    #pragma unroll
    for (int i=0;i<4;i++){
        int col = tid*4+i;
        if (av[i] > 0.f){ loc[c++] = (unsigned short)col; ca += (col<lim1); cb += (col<lim2); }
    }
    int scan = c;
    #pragma unroll
    for (int off=1; off<32; off<<=1){
        int v = __shfl_up_sync(0xffffffffu, scan, off);
        if (lane>=off) scan += v;
    }
    int wca = __reduce_add_sync(0xffffffffu, (unsigned)ca);
    int wcb = __reduce_add_sync(0xffffffffu, (unsigned)cb);
    if (lane==31) wtot[wid] = scan;
    if (lane==0){ r1t[wid]=wca; r2t[wid]=wcb; }
    __syncthreads();
    if (tid==0){
        int acc=0, sa=0, sb=0;
        #pragma unroll
        for (int wdx=0; wdx<8; wdx++){
            wpre[wdx]=acc; acc+=wtot[wdx]; sa+=r1t[wdx]; sb+=r2t[wdx];
        }
        g_cnt[bs*4+0]=sa; g_cnt[bs*4+1]=sb; g_cnt[bs*4+2]=acc; g_cnt[bs*4+3]=0;
    }
    __syncthreads();
    int base = wpre[wid] + scan - c;
    for (int i=0;i<c;i++) g_lst[(size_t)bs*Sq + base + i] = loc[i];
}

// ---------------- fp16 GEMM: 128x64 tile, 8 warps (4m x 2n), cp.async 2-stage ----------
// DOT=1: block covers one 64-col head -> plain g_es/g_ed store.
// DOT=2: 4 n-blocks share a row -> atomicAdd into g_gs/g_gd.
template<int KD, int ND, bool MASK, bool SIG, int DOT>
__global__ void __launch_bounds__(256) k_mmh(const __half* __restrict__ Abase, size_t astride,
                                             const __half* __restrict__ Btbase,
                                             float* __restrict__ Cbase, __half* __restrict__ Chbase,
                                             const float* __restrict__ bias,
                                             const float* __restrict__ asM, const float* __restrict__ asD,
                                             const float* __restrict__ adM, const float* __restrict__ adD){
    int e = blockIdx.z;
    const __half* A  = Abase + astride*e;
    const __half* Bt = Btbase + (size_t)e*ND*KD;
    float* Cf = Cbase ? Cbase + (size_t)e*BSq*ND : (float*)0;
    __half* Ch = Chbase ? Chbase + (size_t)e*BSq*ND : (__half*)0;
    int m0 = blockIdx.y*128, n0 = blockIdx.x*64;
    __shared__ __half2 As2[2][128][20];
    __shared__ __half2 Bs2[2][64][20];
    __shared__ float sred[256];
    __shared__ float sAs[64], sAd[64];
    __shared__ float sdot[256];          // [row] ds (0..127), dd (128..255)
    int tid=threadIdx.x, lane=tid&31, wid=tid>>5;
    int wm=(wid&3)*32, wn=(wid>>2)*32;
    int gid=lane>>2, qid=lane&3;
    if (DOT){
        if (tid<64){
            const float* as = (e==0)? asM : asD + (size_t)(e-1)*ND;
            const float* ad = (e==0)? adM : adD + (size_t)(e-1)*ND;
            sAs[tid] = as[n0+tid];
            sAd[tid] = ad[n0+tid];
        }
        sdot[tid] = 0.f;
        if (tid<128) sdot[tid+128] = 0.f;  // hmm: sdot is 256; ds in [0,128), dd in [128,256)
    }
    float c[2][4][4];
    #pragma unroll
    for (int mt=0;mt<2;mt++)
        #pragma unroll
        for (int nt=0;nt<4;nt++)
            #pragma unroll
            for (int r=0;r<4;r++) c[mt][nt][r]=0.f;
    int rowA = tid>>1;
    int khA  = (tid&1)*16;
    int kcA  = (tid&1)*8;
    int rowB = tid>>2;
    int khB  = (tid&3)*8;
    int kcB  = (tid&3)*4;
    bool amask = true;
    if (MASK){ if (e>0 && g_rmask[(size_t)(e-1)*BSq + m0 + rowA]==0) amask = false; }
    const __half* Ap  = A  + (size_t)(m0+rowA)*KD + khA;
    const __half* Btp = Bt + (size_t)(n0+rowB)*KD + khB;
    int szA = (MASK && !amask) ? 0 : 16;

    unsigned As_base = (unsigned)__cvta_generic_to_shared(&As2[0][0][0]);
    unsigned Bs_base = (unsigned)__cvta_generic_to_shared(&Bs2[0][0][0]);
    const unsigned STG_A = 128u*20u*4u;   // 10240
    const unsigned STG_B = 64u*20u*4u;    // 5120
    unsigned dstA = As_base + (unsigned)(rowA*20 + kcA)*4u;
    unsigned dstB = Bs_base + (unsigned)(rowB*20 + kcB)*4u;

#define PREFETCH(P, K0) { \
    CPA16(dstA + (P)*STG_A,      Ap  + (K0),     szA); \
    CPA16(dstA + (P)*STG_A + 16, Ap  + (K0) + 8, szA); \
    CPA16(dstB + (P)*STG_B,      Btp + (K0),     16); \
    CPA_COMMIT(); }

    // ldmatrix lane-address components (row stride = 40 halves)
    int lr8 = lane & 7;
    int a_row = wm + lr8 + ((lane>>3)&1)*8;      // + mt*16
    int a_kof = ((lane>>4)&1)*8;                 // + sub*16
    int b_col = wn + lr8 + ((lane>>4)&1)*8;      // + ntp*16
    int b_kof = ((lane>>3)&1)*8;                 // + sub*16
    unsigned aAddr0 = As_base + (unsigned)(a_row*40 + a_kof)*2u;
    unsigned bAddr0 = Bs_base + (unsigned)(b_col*40 + b_kof)*2u;

    const int NT = KD/32;
    PREFETCH(0, 0);
    #pragma unroll 2
    for (int it=0; it<NT; it++){
        if (it+1 < NT){
            PREFETCH((it+1)&1, (it+1)*32);
            asm volatile("cp.async.wait_group 1;");
        } else {
            asm volatile("cp.async.wait_group 0;");
        }
        __syncthreads();
        unsigned stA = (unsigned)(it&1)*STG_A;
        unsigned stB = (unsigned)(it&1)*STG_B;
        #pragma unroll
        for (int sub=0; sub<2; sub++){
            unsigned af[2][4], bf[2][4];
            #pragma unroll
            for (int mt=0;mt<2;mt++){
                unsigned ad = aAddr0 + stA + (unsigned)(mt*16*40 + sub*16)*2u;
                LDSM4(af[mt][0],af[mt][1],af[mt][2],af[mt][3], ad);
            }
            #pragma unroll
            for (int ntp=0;ntp<2;ntp++){
                unsigned bd = bAddr0 + stB + (unsigned)(ntp*16*40 + sub*16)*2u;
                LDSM4(bf[ntp][0],bf[ntp][1],bf[ntp][2],bf[ntp][3], bd);
            }
            #pragma unroll
            for (int mt=0;mt<2;mt++)
                #pragma unroll
                for (int nt=0;nt<4;nt++)
                    mma_f16(c[mt][nt], af[mt][0],af[mt][1],af[mt][2],af[mt][3],
                            bf[nt>>1][(nt&1)*2], bf[nt>>1][(nt&1)*2+1]);
        }
        __syncthreads();
    }
#undef PREFETCH
    float lsum = 0.f;
    #pragma unroll
    for (int mt=0;mt<2;mt++){
        int orow = m0 + wm + mt*16 + gid;
        float ds0=0.f, dd0=0.f, ds1=0.f, dd1=0.f;
        #pragma unroll
        for (int nt=0;nt<4;nt++){
            int lcol = wn + nt*8 + qid*2;
            int col = n0 + lcol;
            float2 v0 = make_float2(c[mt][nt][0], c[mt][nt][1]);
            float2 v1 = make_float2(c[mt][nt][2], c[mt][nt][3]);
            if (SIG){
                float b0v = bias[col], b1v = bias[col+1];
                v0.x = 1.f/(1.f+expf(-(v0.x+b0v))); v0.y = 1.f/(1.f+expf(-(v0.y+b1v)));
                v1.x = 1.f/(1.f+expf(-(v1.x+b0v))); v1.y = 1.f/(1.f+expf(-(v1.y+b1v)));
                lsum += v0.x+v0.y+v1.x+v1.y;
            }
            if (DOT){
                float a0=sAs[lcol], a1=sAs[lcol+1], d0=sAd[lcol], d1=sAd[lcol+1];
                ds0 += v0.x*a0 + v0.y*a1;  dd0 += v0.x*d0 + v0.y*d1;
                ds1 += v1.x*a0 + v1.y*a1;  dd1 += v1.x*d0 + v1.y*d1;
            }
            if (Cf){
                *(float2*)&Cf[(size_t)orow*ND + col]     = v0;
                *(float2*)&Cf[(size_t)(orow+8)*ND + col] = v1;
            }
            if (Ch){
                *(__half2*)&Ch[(size_t)orow*ND + col]     = __float22half2_rn(v0);
                *(__half2*)&Ch[(size_t)(orow+8)*ND + col] = __float22half2_rn(v1);
            }
        }
        if (DOT){
            ds0 += __shfl_down_sync(0xffffffffu, ds0, 2, 4); ds0 += __shfl_down_sync(0xffffffffu, ds0, 1, 4);
            dd0 += __shfl_down_sync(0xffffffffu, dd0, 2, 4); dd0 += __shfl_down_sync(0xffffffffu, dd0, 1, 4);
            ds1 += __shfl_down_sync(0xffffffffu, ds1, 2, 4); ds1 += __shfl_down_sync(0xffffffffu, ds1, 1, 4);
            dd1 += __shfl_down_sync(0xffffffffu, dd1, 2, 4); dd1 += __shfl_down_sync(0xffffffffu, dd1, 1, 4);
            if (qid==0){
                int rl = wm + mt*16 + gid;
                atomicAdd(&sdot[rl],     ds0); atomicAdd(&sdot[rl+8],     ds1);
                atomicAdd(&sdot[128+rl], dd0); atomicAdd(&sdot[128+rl+8], dd1);
            }
        }
    }
    if (DOT){
        __syncthreads();
        if (tid<128){
            if (DOT==1){
                size_t idx = ((size_t)e*BSq + m0 + tid)*8 + (n0>>6);
                g_es[idx] = sdot[tid];
                g_ed[idx] = sdot[128+tid];
            } else {
                atomicAdd(&g_gs[(size_t)e*BSq + m0 + tid], sdot[tid]);
                atomicAdd(&g_gd[(size_t)e*BSq + m0 + tid], sdot[128+tid]);
            }
        }
    }
    if (SIG){
        sred[tid] = lsum;
        __syncthreads();
        for (int st=128; st>0; st>>=1){ if (tid<st) sred[tid]+=sred[tid+st]; __syncthreads(); }
        if (tid==0) atomicAdd(&g_bwsum, sred[0]);
    }
}

// ---------------- hsum (deputies only) ----------------
__global__ void k_hsum(){
    int eb = blockIdx.x + Bq;
    int chunk = blockIdx.y;
    int e = eb>>2, b = eb&3;
    const __half* base = g_hh + ((size_t)e*BSq + ((size_t)b<<10) + chunk*128)*NHq;
    int t = threadIdx.x;
    float acc = 0.f;
    for (int s=0;s<128;s++) acc += __half2float(base[(size_t)s*NHq + t]);
    atomicAdd(&g_hsum[(size_t)eb*NHq + t], acc);
}

// ---------------- attention layer 1 ----------------
__global__ void __launch_bounds__(192) k_att1(){
    __shared__ unsigned short lst[1024];
    __shared__ unsigned char  ok[1024];
    __shared__ __half wh[6*1024];
    __shared__ float sred[6][8];
    __shared__ float ssum[6];
    __shared__ float es6[6];
    __shared__ float4 sacc[2][96];
    int bs = blockIdx.x, ex = blockIdx.y, b = bs>>10;
    int tid = threadIdx.x, lane = tid&31, wid = tid>>5;
    int c1 = g_cnt[bs*4+0], c2 = g_cnt[bs*4+1], ct = g_cnt[bs*4+2];
    int lo, hi;
    if      (ex==0){ lo=0;  hi=ct; }
    else if (ex==1){ lo=0;  hi=c1; }
    else if (ex==2){ lo=c1; hi=c2; }
    else           { lo=c2; hi=ct; }
    int n = hi-lo;
    __half* h1row = g_h1h + ((size_t)ex*BSq + bs)*NHq;
    if (n==0){
        if (tid<96){
            float4 hv = *(const float4*)&g_hsum[(size_t)((ex<<2)|b)*NHq + tid*4];
            *(__half2*)&h1row[tid*4]   = __float22half2_rn(make_float2(elu1(hv.x*(1.f/Sq)), elu1(hv.y*(1.f/Sq))));
            *(__half2*)&h1row[tid*4+2] = __float22half2_rn(make_float2(elu1(hv.z*(1.f/Sq)), elu1(hv.w*(1.f/Sq))));
        }
        return;
    }
    for (int j=tid;j<n;j+=192) lst[j] = g_lst[(size_t)bs*Sq + lo + j];
    if (tid<6) es6[tid] = g_es[((size_t)ex*BSq + bs)*8 + tid];
    __syncthreads();
    const float* edb = g_ed + ((size_t)ex*BSq + ((size_t)b<<10))*8;
    const unsigned char* rm = (ex>0)? g_rmask + (size_t)(ex-1)*BSq + (b<<10) : nullptr;
    float mx[6];
    #pragma unroll
    for (int h=0;h<6;h++) mx[h] = -1e30f;
    for (int j=tid;j<n;j+=192){
        int nb = lst[j];
        float4 e0 = *(const float4*)&edb[nb*8];
        float2 e1 = *(const float2*)&edb[nb*8+4];
        ok[j] = rm ? rm[nb] : 1;
        float ev[6] = {e0.x,e0.y,e0.z,e0.w,e1.x,e1.y};
        #pragma unroll
        for (int h=0;h<6;h++){
            float e = leaky02(es6[h] + ev[h]);
            wh[h*1024+j] = __float2half(e);
            mx[h] = fmaxf(mx[h], e);
        }
    }
    #pragma unroll
    for (int h=0;h<6;h++){
        #pragma unroll
        for (int o=16;o>0;o>>=1) mx[h] = fmaxf(mx[h], __shfl_xor_sync(0xffffffffu, mx[h], o));
    }
    if (lane==0){
        #pragma unroll
        for (int h=0;h<6;h++) sred[h][wid] = mx[h];
    }
    __syncthreads();
    float mxv[6];
    #pragma unroll
    for (int h=0;h<6;h++){
        float m = sred[h][0];
        #pragma unroll
        for (int wdx=1; wdx<6; wdx++) m = fmaxf(m, sred[h][wdx]);
        mxv[h] = m;
    }
    __syncthreads();
    float sm[6] = {0.f,0.f,0.f,0.f,0.f,0.f};
    for (int j=tid;j<n;j+=192){
        #pragma unroll
        for (int h=0;h<6;h++){
            float ww = expf(__half2float(wh[h*1024+j]) - mxv[h]);
            wh[h*1024+j] = __float2half(ww);
            sm[h] += ww;
        }
    }
    #pragma unroll
    for (int h=0;h<6;h++){
        #pragma unroll
        for (int o=16;o>0;o>>=1) sm[h] += __shfl_xor_sync(0xffffffffu, sm[h], o);
    }
    if (lane==0){
        #pragma unroll
        for (int h=0;h<6;h++) sred[h][wid] = sm[h];
    }
    __syncthreads();
    if (tid<6){
        float s = sred[tid][0];
        #pragma unroll
        for (int wdx=1; wdx<6; wdx++) s += sred[tid][wdx];
        ssum[tid] = s;
    }
    __syncthreads();
    {
        int col = tid % 96, grp = tid / 96;
        int h = col >> 4;
        const __half* hb = g_hh + ((size_t)ex*BSq + ((size_t)b<<10))*NHq;
        float ax=0.f, ay=0.f, az=0.f, aw=0.f;
        int j = grp;
        for (; j+2 < n; j += 4){
            float w0 = ok[j]   ? __half2float(wh[h*1024+j])   : 0.f;
            float w1 = ok[j+2] ? __half2float(wh[h*1024+j+2]) : 0.f;
            uint2 r0 = *(const uint2*)&hb[(size_t)lst[j]*NHq   + col*4];
            uint2 r1 = *(const uint2*)&hb[(size_t)lst[j+2]*NHq + col*4];
            float2 p00 = __half22float2(*(__half2*)&r0.x);
            float2 p01 = __half22float2(*(__half2*)&r0.y);
            float2 p10 = __half22float2(*(__half2*)&r1.x);
            float2 p11 = __half22float2(*(__half2*)&r1.y);
            ax += w0*p00.x + w1*p10.x; ay += w0*p00.y + w1*p10.y;
            az += w0*p01.x + w1*p11.x; aw += w0*p01.y + w1*p11.y;
        }
        for (; j < n; j += 2){
            float w0 = ok[j] ? __half2float(wh[h*1024+j]) : 0.f;
            uint2 r0 = *(const uint2*)&hb[(size_t)lst[j]*NHq + col*4];
            float2 p00 = __half22float2(*(__half2*)&r0.x);
            float2 p01 = __half22float2(*(__half2*)&r0.y);
            ax += w0*p00.x; ay += w0*p00.y; az += w0*p01.x; aw += w0*p01.y;
        }
        sacc[grp][col] = make_float4(ax,ay,az,aw);
    }
    __syncthreads();
    if (tid<96){
        int h = tid >> 4;
        float inv = 1.f/ssum[h];
        float4 a0 = sacc[0][tid], a1 = sacc[1][tid];
        *(__half2*)&h1row[tid*4]   = __float22half2_rn(make_float2(elu1((a0.x+a1.x)*inv), elu1((a0.y+a1.y)*inv)));
        *(__half2*)&h1row[tid*4+2] = __float22half2_rn(make_float2(elu1((a0.z+a1.z)*inv), elu1((a0.w+a1.w)*inv)));
    }
}

// ---------------- h2sum (deputies only) ----------------
__global__ void k_h2sum(){
    int eb = blockIdx.x + Bq;
    int chunk = blockIdx.y;
    int e = eb>>2, b = eb&3;
    const __half* base = g_h2h + ((size_t)e*BSq + ((size_t)b<<10) + chunk*128)*Dq;
    int t = threadIdx.x;
    float acc = 0.f;
    for (int s=0;s<128;s++) acc += __half2float(base[(size_t)s*Dq + t]);
    atomicAdd(&g_h2sum[(size_t)eb*Dq + t], acc);
}

// ---------------- attention layer 2 ----------------
__global__ void __launch_bounds__(256) k_att2(){
    __shared__ unsigned short lst[1024];
    __shared__ float w[1024];
    __shared__ float red[256];
    __shared__ float4 sacc[4][64];
    int bs = blockIdx.x, ex = blockIdx.y, b = bs>>10;
    int tid = threadIdx.x;
    if (ex>0 && g_rmask[(size_t)(ex-1)*BSq + bs]==0) return;
    float* outb = (ex==0)? g_main : g_depE + (size_t)(ex-1)*BSDq;
    int c1 = g_cnt[bs*4+0], c2 = g_cnt[bs*4+1], ct = g_cnt[bs*4+2];
    int lo, hi;
    if      (ex==0){ lo=0;  hi=ct; }
    else if (ex==1){ lo=0;  hi=c1; }
    else if (ex==2){ lo=c1; hi=c2; }
    else           { lo=c2; hi=ct; }
    int n = hi-lo;
    if (n==0){
        if (tid<64){
            float4 hv = *(const float4*)&g_h2sum[(size_t)((ex<<2)|b)*Dq + tid*4];
            *(float4*)&outb[(size_t)bs*Dq + tid*4] =
                make_float4(hv.x*(1.f/Sq), hv.y*(1.f/Sq), hv.z*(1.f/Sq), hv.w*(1.f/Sq));
        }
        return;
    }
    for (int j=tid;j<n;j+=256) lst[j] = g_lst[(size_t)bs*Sq + lo + j];
    __syncthreads();
    float gsv = g_gs[(size_t)ex*BSq + bs];
    const float* gdb = g_gd + (size_t)ex*BSq + (b<<10);
    float mloc = -1e30f;
    for (int j=tid;j<n;j+=256){
        float e = leaky02(gsv + gdb[lst[j]]);
        w[j]=e;
        mloc = fmaxf(mloc,e);
    }
    red[tid]=mloc; __syncthreads();
    for (int st=128;st>0;st>>=1){ if (tid<st) red[tid]=fmaxf(red[tid],red[tid+st]); __syncthreads(); }
    float m = red[0]; __syncthreads();
    float sloc = 0.f;
    for (int j=tid;j<n;j+=256){ float ww=expf(w[j]-m); w[j]=ww; sloc+=ww; }
    red[tid]=sloc; __syncthreads();
    for (int st=128;st>0;st>>=1){ if (tid<st) red[tid]+=red[tid+st]; __syncthreads(); }
    float inv = 1.f/red[0];
    int grp = tid>>6, q = tid&63;
    const __half* h2b = g_h2h + ((size_t)ex*BSq + ((size_t)b<<10))*Dq;
    float ax=0.f, ay=0.f, az=0.f, aw=0.f;
    int j = grp;
    for (; j+4 < n; j += 8){
        float w0 = w[j], w1 = w[j+4];
        uint2 r0 = *(const uint2*)&h2b[(size_t)lst[j]*Dq   + q*4];
        uint2 r1 = *(const uint2*)&h2b[(size_t)lst[j+4]*Dq + q*4];
        float2 p00 = __half22float2(*(__half2*)&r0.x);
        float2 p01 = __half22float2(*(__half2*)&r0.y);
        float2 p10 = __half22float2(*(__half2*)&r1.x);
        float2 p11 = __half22float2(*(__half2*)&r1.y);
        ax += w0*p00.x + w1*p10.x; ay += w0*p00.y + w1*p10.y;
        az += w0*p01.x + w1*p11.x; aw += w0*p01.y + w1*p11.y;
    }
    for (; j < n; j += 4){
        float w0 = w[j];
        uint2 r0 = *(const uint2*)&h2b[(size_t)lst[j]*Dq + q*4];
        float2 p00 = __half22float2(*(__half2*)&r0.x);
        float2 p01 = __half22float2(*(__half2*)&r0.y);
        ax += w0*p00.x; ay += w0*p00.y; az += w0*p01.x; aw += w0*p01.y;
    }
    sacc[grp][q] = make_float4(ax,ay,az,aw);
    __syncthreads();
    if (tid<64){
        float4 a0=sacc[0][tid], a1=sacc[1][tid], a2=sacc[2][tid], a3=sacc[3][tid];
        *(float4*)&outb[(size_t)bs*Dq + tid*4] =
            make_float4((a0.x+a1.x+a2.x+a3.x)*inv, (a0.y+a1.y+a2.y+a3.y)*inv,
                        (a0.z+a1.z+a2.z+a3.z)*inv, (a0.w+a1.w+a2.w+a3.w)*inv);
    }
}

// ---------------- final blend ----------------
__global__ void k_final(float* __restrict__ out){
    __shared__ unsigned char msk[3];
    int bs = blockIdx.x, d = threadIdx.x;
    if (d<3) msk[d] = g_rmask[d*BSq+bs];
    __syncthreads();
    size_t i = (size_t)bs*Dq + d;
    float dep = 0.f;
    if (msk[0]) dep += g_depE[i];
    if (msk[1]) dep += g_depE[BSDq + i];
    if (msk[2]) dep += g_depE[2*(size_t)BSDq + i];
    float bw = g_bw[i];
    out[i] = bw*g_main[i] + (1.f-bw)*dep;
    if (bs==0 && d==0){
        float mc = g_bwsum * (1.f/(float)BSDq);
        out[BSDq]   = fabsf(mc - 0.6f) * 0.01f;
        out[BSDq+1] = mc;
    }
}

// ---------------- host launcher ----------------
extern "C" void kernel_launch(void* const* d_in, const int* in_sizes, int n_in,
                              void* d_out, int out_size){
    const float* feature  = (const float*)d_in[0];
    const float* adj      = (const float*)d_in[1];
    const float* main_W1  = (const float*)d_in[2];
    const float* main_a1s = (const float*)d_in[3];
    const float* main_a1d = (const float*)d_in[4];
    const float* main_W2  = (const float*)d_in[5];
    const float* main_a2s = (const float*)d_in[6];
    const float* main_a2d = (const float*)d_in[7];
    const float* dep_W1   = (const float*)d_in[8];
    const float* dep_a1s  = (const float*)d_in[9];
    const float* dep_a1d  = (const float*)d_in[10];
    const float* dep_W2   = (const float*)d_in[11];
    const float* dep_a2s  = (const float*)d_in[12];
    const float* dep_a2d  = (const float*)d_in[13];
    const float* router_W = (const float*)d_in[14];
    const float* blend_W  = (const float*)d_in[15];
    const float* blend_b  = (const float*)d_in[16];
    const int*   doc_num  = (const int*)d_in[17];
    const int*   sect_num = (const int*)d_in[18];
    float* out = (float*)d_out;

    __half* feat_h;  cudaGetSymbolAddress((void**)&feat_h,  g_feat_h);
    __half* W1t_h;   cudaGetSymbolAddress((void**)&W1t_h,   g_W1t_h);
    __half* W2t_h;   cudaGetSymbolAddress((void**)&W2t_h,   g_W2t_h);
    __half* bWt_h;   cudaGetSymbolAddress((void**)&bWt_h,   g_bWt_h);
    __half* h1h_p;   cudaGetSymbolAddress((void**)&h1h_p,   g_h1h);
    float*  bw_p;    cudaGetSymbolAddress((void**)&bw_p,    g_bw);
    __half* hh_p;    cudaGetSymbolAddress((void**)&hh_p,    g_hh);
    __half* h2h_p;   cudaGetSymbolAddress((void**)&h2h_p,   g_h2h);

    k_prep<<<dim3(BSq*Dq/256, 6), 256>>>(feature, main_W1, dep_W1, main_W2, dep_W2, blend_W, router_W);
    k_nbr<<<BSq, 256>>>(adj, doc_num, sect_num);

    k_mmh<Dq, Dq, false, true, 0><<<dim3(4,32,1), 256>>>(feat_h, 0, bWt_h, bw_p, (__half*)0, blend_b,
                                                         (const float*)0,(const float*)0,(const float*)0,(const float*)0);

    k_mmh<Dq, NHq, true, false, 1><<<dim3(6,32,NEXP), 256>>>(feat_h, 0, W1t_h, (float*)0, hh_p, (const float*)0,
                                                             main_a1s, dep_a1s, main_a1d, dep_a1d);
    k_hsum<<<dim3((NEXP-1)*Bq, 8), NHq>>>();
    k_att1<<<dim3(BSq, NEXP), 192>>>();

    k_mmh<NHq, Dq, false, false, 2><<<dim3(4,32,NEXP), 256>>>(h1h_p, (size_t)BSq*NHq, W2t_h, (float*)0, h2h_p, (const float*)0,
                                                              main_a2s, dep_a2s, main_a2d, dep_a2d);
    k_h2sum<<<dim3((NEXP-1)*Bq, 8), Dq>>>();
    k_att2<<<dim3(BSq, NEXP), 256>>>();

    k_final<<<BSq, Dq>>>(out);
}

// round 11
// speedup vs baseline: 2.3502x; 1.0968x over previous
#include <cuda_runtime.h>
#include <cuda_fp16.h>
#include <math.h>

// Fixed shapes
#define Bq 4
#define Sq 1024
#define Dq 256
#define Hq 6
#define HDq 64
#define NHq 384          // H*Hd
#define BSq 4096         // B*S
#define BSDq (BSq*Dq)
#define NEXP 4           // slot 0 = main, 1..3 = deputies

// ---------------- scratch ----------------
__device__ __half g_hh [(size_t)NEXP*BSq*NHq];
__device__ __half g_h1h[(size_t)NEXP*BSq*NHq];
__device__ __half g_h2h[(size_t)NEXP*BSq*Dq];
__device__ float  g_es [NEXP*BSq*8];
__device__ float  g_ed [NEXP*BSq*8];
__device__ float  g_hsum [NEXP*Bq*NHq];
__device__ float  g_h2sum[NEXP*Bq*Dq];
__device__ float  g_gs [NEXP*BSq];
__device__ float  g_gd [NEXP*BSq];
__device__ __half g_feat_h[(size_t)BSq*Dq];
__device__ __half g_W1t_h[(size_t)NEXP*NHq*Dq];  // [e][n][k]
__device__ __half g_W2t_h[(size_t)NEXP*Dq*NHq];  // [e][n][k]
__device__ __half g_bWt_h[(size_t)Dq*Dq];        // [n][k]
__device__ float  g_main[BSDq];
__device__ float  g_depE[3*(size_t)BSDq];
__device__ float  g_bw  [BSDq];
__device__ float  g_bwsum;
__device__ unsigned char  g_rmask[3*BSq];
__device__ unsigned short g_lst[(size_t)BSq*Sq];
__device__ int g_cnt[BSq*4];

__device__ __forceinline__ float leaky02(float x){ return x > 0.f ? x : 0.2f*x; }
__device__ __forceinline__ float elu1(float x){ return x > 0.f ? x : expm1f(x); }
__device__ __forceinline__ void mma_f16(float c[4], unsigned a0,unsigned a1,unsigned a2,unsigned a3,
                                        unsigned b0,unsigned b1){
    asm volatile("mma.sync.aligned.m16n8k16.row.col.f32.f16.f16.f32 "
        "{%0,%1,%2,%3},{%4,%5,%6,%7},{%8,%9},{%0,%1,%2,%3};"
        : "+f"(c[0]),"+f"(c[1]),"+f"(c[2]),"+f"(c[3])
        : "r"(a0),"r"(a1),"r"(a2),"r"(a3),"r"(b0),"r"(b1));
}
#define LDSM4(r0,r1,r2,r3,a) \
    asm volatile("ldmatrix.sync.aligned.m8n8.x4.shared.b16 {%0,%1,%2,%3},[%4];" \
        : "=r"(r0),"=r"(r1),"=r"(r2),"=r"(r3) : "r"(a))
#define CPA16(dst,src,sz) \
    asm volatile("cp.async.cg.shared.global [%0], [%1], 16, %2;" :: "r"(dst),"l"(src),"r"(sz))
#define CPA_COMMIT() asm volatile("cp.async.commit_group;")

// ---------------- setup: fp16 operand prep + router + zeroing ----------------
__global__ void k_prep(const float* __restrict__ feature,
                       const float* __restrict__ mainW1, const float* __restrict__ depW1,
                       const float* __restrict__ mainW2, const float* __restrict__ depW2,
                       const float* __restrict__ blendW, const float* __restrict__ Wr){
    int task = blockIdx.y;
    int tid  = threadIdx.x;
    int i = blockIdx.x*256 + tid;
    if (task == 0){
        g_feat_h[i] = __float2half(feature[i]);
    } else if (task == 1){
        if (i < NEXP*NHq*Dq){
            int e = i/(NHq*Dq), r = i%(NHq*Dq), n = r/Dq, k = r%Dq;
            int h = n>>6, o = n&63;
            const float* src = (e==0)? mainW1 : depW1 + (size_t)(e-1)*Hq*Dq*HDq;
            g_W1t_h[i] = __float2half(src[(size_t)h*Dq*HDq + (size_t)k*HDq + o]);
        }
    } else if (task == 2){
        if (i < NEXP*Dq*NHq){
            int e = i/(Dq*NHq), r = i%(Dq*NHq), n = r/NHq, k = r%NHq;
            const float* src = (e==0)? mainW2 : depW2 + (size_t)(e-1)*NHq*Dq;
            g_W2t_h[i] = __float2half(src[(size_t)k*Dq + n]);
        }
    } else if (task == 3){
        if (i < Dq*Dq){
            int n = i/Dq, k = i%Dq;
            g_bWt_h[i] = __float2half(blendW[(size_t)k*Dq + n]);
        }
    } else if (task == 4){
        int gw = blockIdx.x*8 + (tid>>5);
        int lane = tid & 31;
        if (gw >= BSq) return;
        const float* xr = feature + (size_t)gw*Dq;
        float a0=0.f,a1=0.f,a2=0.f;
        for (int k=lane;k<Dq;k+=32){
            float xv = xr[k];
            a0 += xv*Wr[k*3+0]; a1 += xv*Wr[k*3+1]; a2 += xv*Wr[k*3+2];
        }
        #pragma unroll
        for (int o=16;o>0;o>>=1){
            a0 += __shfl_down_sync(0xffffffffu,a0,o);
            a1 += __shfl_down_sync(0xffffffffu,a1,o);
            a2 += __shfl_down_sync(0xffffffffu,a2,o);
        }
        if (lane==0){
            float v[3]={a0,a1,a2};
            int ex=0; float mv=v[0];
            #pragma unroll
            for (int e=1;e<3;e++) if (v[e]<=mv){ mv=v[e]; ex=e; }
            #pragma unroll
            for (int e=0;e<3;e++) g_rmask[e*BSq+gw] = (e==ex)?0:1;
        }
    } else {
        if (i < NEXP*BSq){ g_gs[i]=0.f; g_gd[i]=0.f; }
        if (i < NEXP*Bq*NHq) g_hsum[i]=0.f;
        if (i < NEXP*Bq*Dq)  g_h2sum[i]=0.f;
        if (i==0) g_bwsum = 0.f;
    }
}

// ---------------- neighbor lists (warp-shfl scan) ----------------
__global__ void k_nbr(const float* __restrict__ adj, const int* __restrict__ dnum,
                      const int* __restrict__ snum){
    __shared__ int wtot[8], wpre[8], r1t[8], r2t[8];
    int bs = blockIdx.x, tid = threadIdx.x, lane = tid&31, wid = tid>>5;
    int doc = dnum[0], sect = snum[0];
    int lim1 = Sq - sect - doc, lim2 = Sq - doc;
    const float* arow = adj + (size_t)bs*Sq;
    float4 a = *(const float4*)(arow + tid*4);
    unsigned short loc[4]; int c=0, ca=0, cb=0;
    float av[4] = {a.x,a.y,a.z,a.w};
    #pragma unroll
    for (int i=0;i<4;i++){
        int col = tid*4+i;
        if (av[i] > 0.f){ loc[c++] = (unsigned short)col; ca += (col<lim1); cb += (col<lim2); }
    }
    int scan = c;
    #pragma unroll
    for (int off=1; off<32; off<<=1){
        int v = __shfl_up_sync(0xffffffffu, scan, off);
        if (lane>=off) scan += v;
    }
    int wca = __reduce_add_sync(0xffffffffu, (unsigned)ca);
    int wcb = __reduce_add_sync(0xffffffffu, (unsigned)cb);
    if (lane==31) wtot[wid] = scan;
    if (lane==0){ r1t[wid]=wca; r2t[wid]=wcb; }
    __syncthreads();
    if (tid==0){
        int acc=0, sa=0, sb=0;
        #pragma unroll
        for (int wdx=0; wdx<8; wdx++){
            wpre[wdx]=acc; acc+=wtot[wdx]; sa+=r1t[wdx]; sb+=r2t[wdx];
        }
        g_cnt[bs*4+0]=sa; g_cnt[bs*4+1]=sb; g_cnt[bs*4+2]=acc; g_cnt[bs*4+3]=0;
    }
    __syncthreads();
    int base = wpre[wid] + scan - c;
    for (int i=0;i<c;i++) g_lst[(size_t)bs*Sq + base + i] = loc[i];
}

// ---------------- fp16 GEMM: 128x64 tile, 3-stage cp.async, 1 sync/iter ----------
// DOT=1: block = one 64-col head -> g_es/g_ed plain store; + fused hsum (e>0).
// DOT=2: atomicAdd g_gs/g_gd; + fused h2sum (e>0).
template<int KD, int ND, bool MASK, bool SIG, int DOT>
__global__ void __launch_bounds__(256) k_mmh(const __half* __restrict__ Abase, size_t astride,
                                             const __half* __restrict__ Btbase,
                                             float* __restrict__ Cbase, __half* __restrict__ Chbase,
                                             const float* __restrict__ bias,
                                             const float* __restrict__ asM, const float* __restrict__ asD,
                                             const float* __restrict__ adM, const float* __restrict__ adD){
    int e = blockIdx.z;
    const __half* A  = Abase + astride*e;
    const __half* Bt = Btbase + (size_t)e*ND*KD;
    float* Cf = Cbase ? Cbase + (size_t)e*BSq*ND : (float*)0;
    __half* Ch = Chbase ? Chbase + (size_t)e*BSq*ND : (__half*)0;
    int m0 = blockIdx.y*128, n0 = blockIdx.x*64;
    __shared__ __half2 As2[3][128][20];
    __shared__ __half2 Bs2[3][64][20];
    __shared__ float sred[256];
    __shared__ float sAs[64], sAd[64];
    __shared__ float sdot[256];          // ds (0..127), dd (128..255)
    __shared__ float scol[64];
    int tid=threadIdx.x, lane=tid&31, wid=tid>>5;
    int wm=(wid&3)*32, wn=(wid>>2)*32;
    int gid=lane>>2, qid=lane&3;
    bool docs = (DOT!=0) && (e>0);       // fused column sums (deputies only)
    if (DOT){
        if (tid<64){
            const float* as = (e==0)? asM : asD + (size_t)(e-1)*ND;
            const float* ad = (e==0)? adM : adD + (size_t)(e-1)*ND;
            sAs[tid] = as[n0+tid];
            sAd[tid] = ad[n0+tid];
            scol[tid] = 0.f;
        }
        sdot[tid] = 0.f;
    }
    float c[2][4][4];
    #pragma unroll
    for (int mt=0;mt<2;mt++)
        #pragma unroll
        for (int nt=0;nt<4;nt++)
            #pragma unroll
            for (int r=0;r<4;r++) c[mt][nt][r]=0.f;
    int rowA = tid>>1;
    int khA  = (tid&1)*16;
    int kcA  = (tid&1)*8;
    int rowB = tid>>2;
    int khB  = (tid&3)*8;
    int kcB  = (tid&3)*4;
    bool amask = true;
    if (MASK){ if (e>0 && g_rmask[(size_t)(e-1)*BSq + m0 + rowA]==0) amask = false; }
    const __half* Ap  = A  + (size_t)(m0+rowA)*KD + khA;
    const __half* Btp = Bt + (size_t)(n0+rowB)*KD + khB;
    int szA = (MASK && !amask) ? 0 : 16;

    unsigned As_base = (unsigned)__cvta_generic_to_shared(&As2[0][0][0]);
    unsigned Bs_base = (unsigned)__cvta_generic_to_shared(&Bs2[0][0][0]);
    const unsigned STG_A = 128u*20u*4u;   // 10240
    const unsigned STG_B = 64u*20u*4u;    // 5120
    unsigned dstA = As_base + (unsigned)(rowA*20 + kcA)*4u;
    unsigned dstB = Bs_base + (unsigned)(rowB*20 + kcB)*4u;

#define PREFETCH(P, K0) { \
    CPA16(dstA + (unsigned)(P)*STG_A,      Ap  + (K0),     szA); \
    CPA16(dstA + (unsigned)(P)*STG_A + 16, Ap  + (K0) + 8, szA); \
    CPA16(dstB + (unsigned)(P)*STG_B,      Btp + (K0),     16); \
    CPA_COMMIT(); }

    int lr8 = lane & 7;
    int a_row = wm + lr8 + ((lane>>3)&1)*8;      // + mt*16
    int a_kof = ((lane>>4)&1)*8;                 // + sub*16
    int b_col = wn + lr8 + ((lane>>4)&1)*8;      // + ntp*16
    int b_kof = ((lane>>3)&1)*8;                 // + sub*16
    unsigned aAddr0 = As_base + (unsigned)(a_row*40 + a_kof)*2u;
    unsigned bAddr0 = Bs_base + (unsigned)(b_col*40 + b_kof)*2u;

    const int NT = KD/32;
    PREFETCH(0, 0);
    PREFETCH(1, 32);
    int stage = 0, pstage = 2;
    for (int it=0; it<NT; it++){
        if (it+2 < NT) asm volatile("cp.async.wait_group 1;");
        else           asm volatile("cp.async.wait_group 0;");
        __syncthreads();
        if (it+2 < NT){
            PREFETCH(pstage, (it+2)*32);
            pstage = (pstage+1 == 3) ? 0 : pstage+1;
        }
        unsigned stA = (unsigned)stage*STG_A;
        unsigned stB = (unsigned)stage*STG_B;
        stage = (stage+1 == 3) ? 0 : stage+1;
        #pragma unroll
        for (int sub=0; sub<2; sub++){
            unsigned af[2][4], bf[2][4];
            #pragma unroll
            for (int mt=0;mt<2;mt++){
                unsigned ad = aAddr0 + stA + (unsigned)(mt*16*40 + sub*16)*2u;
                LDSM4(af[mt][0],af[mt][1],af[mt][2],af[mt][3], ad);
            }
            #pragma unroll
            for (int ntp=0;ntp<2;ntp++){
                unsigned bd = bAddr0 + stB + (unsigned)(ntp*16*40 + sub*16)*2u;
                LDSM4(bf[ntp][0],bf[ntp][1],bf[ntp][2],bf[ntp][3], bd);
            }
            #pragma unroll
            for (int mt=0;mt<2;mt++)
                #pragma unroll
                for (int nt=0;nt<4;nt++)
                    mma_f16(c[mt][nt], af[mt][0],af[mt][1],af[mt][2],af[mt][3],
                            bf[nt>>1][(nt&1)*2], bf[nt>>1][(nt&1)*2+1]);
        }
    }
#undef PREFETCH
    float lsum = 0.f;
    float colp[8];
    #pragma unroll
    for (int i=0;i<8;i++) colp[i]=0.f;
    #pragma unroll
    for (int mt=0;mt<2;mt++){
        int orow = m0 + wm + mt*16 + gid;
        float ds0=0.f, dd0=0.f, ds1=0.f, dd1=0.f;
        #pragma unroll
        for (int nt=0;nt<4;nt++){
            int lcol = wn + nt*8 + qid*2;
            int col = n0 + lcol;
            float2 v0 = make_float2(c[mt][nt][0], c[mt][nt][1]);
            float2 v1 = make_float2(c[mt][nt][2], c[mt][nt][3]);
            if (SIG){
                float b0v = bias[col], b1v = bias[col+1];
                v0.x = 1.f/(1.f+expf(-(v0.x+b0v))); v0.y = 1.f/(1.f+expf(-(v0.y+b1v)));
                v1.x = 1.f/(1.f+expf(-(v1.x+b0v))); v1.y = 1.f/(1.f+expf(-(v1.y+b1v)));
                lsum += v0.x+v0.y+v1.x+v1.y;
            }
            if (DOT){
                float a0=sAs[lcol], a1=sAs[lcol+1], d0=sAd[lcol], d1=sAd[lcol+1];
                ds0 += v0.x*a0 + v0.y*a1;  dd0 += v0.x*d0 + v0.y*d1;
                ds1 += v1.x*a0 + v1.y*a1;  dd1 += v1.x*d0 + v1.y*d1;
                if (docs){
                    colp[nt*2]   += v0.x + v1.x;
                    colp[nt*2+1] += v0.y + v1.y;
                }
            }
            if (Cf){
                *(float2*)&Cf[(size_t)orow*ND + col]     = v0;
                *(float2*)&Cf[(size_t)(orow+8)*ND + col] = v1;
            }
            if (Ch){
                *(__half2*)&Ch[(size_t)orow*ND + col]     = __float22half2_rn(v0);
                *(__half2*)&Ch[(size_t)(orow+8)*ND + col] = __float22half2_rn(v1);
            }
        }
        if (DOT){
            ds0 += __shfl_down_sync(0xffffffffu, ds0, 2, 4); ds0 += __shfl_down_sync(0xffffffffu, ds0, 1, 4);
            dd0 += __shfl_down_sync(0xffffffffu, dd0, 2, 4); dd0 += __shfl_down_sync(0xffffffffu, dd0, 1, 4);
            ds1 += __shfl_down_sync(0xffffffffu, ds1, 2, 4); ds1 += __shfl_down_sync(0xffffffffu, ds1, 1, 4);
            dd1 += __shfl_down_sync(0xffffffffu, dd1, 2, 4); dd1 += __shfl_down_sync(0xffffffffu, dd1, 1, 4);
            if (qid==0){
                int rl = wm + mt*16 + gid;
                atomicAdd(&sdot[rl],     ds0); atomicAdd(&sdot[rl+8],     ds1);
                atomicAdd(&sdot[128+rl], dd0); atomicAdd(&sdot[128+rl+8], dd1);
            }
        }
    }
    if (docs){
        // reduce colp over the 8 gid rows (lanes stride 4, same qid)
        #pragma unroll
        for (int i=0;i<8;i++){
            colp[i] += __shfl_down_sync(0xffffffffu, colp[i], 16);
            colp[i] += __shfl_down_sync(0xffffffffu, colp[i], 8);
            colp[i] += __shfl_down_sync(0xffffffffu, colp[i], 4);
        }
        if (lane < 4){
            #pragma unroll
            for (int nt=0;nt<4;nt++){
                atomicAdd(&scol[wn + nt*8 + qid*2],     colp[nt*2]);
                atomicAdd(&scol[wn + nt*8 + qid*2 + 1], colp[nt*2+1]);
            }
        }
    }
    if (DOT){
        __syncthreads();
        if (tid<128){
            if (DOT==1){
                size_t idx = ((size_t)e*BSq + m0 + tid)*8 + (n0>>6);
                g_es[idx] = sdot[tid];
                g_ed[idx] = sdot[128+tid];
            } else {
                atomicAdd(&g_gs[(size_t)e*BSq + m0 + tid], sdot[tid]);
                atomicAdd(&g_gd[(size_t)e*BSq + m0 + tid], sdot[128+tid]);
            }
        }
        if (docs && tid<64){
            int eb = e*Bq + (m0>>10);
            if (DOT==1) atomicAdd(&g_hsum [(size_t)eb*NHq + n0 + tid], scol[tid]);
            else        atomicAdd(&g_h2sum[(size_t)eb*Dq  + n0 + tid], scol[tid]);
        }
    }
    if (SIG){
        sred[tid] = lsum;
        __syncthreads();
        for (int st=128; st>0; st>>=1){ if (tid<st) sred[tid]+=sred[tid+st]; __syncthreads(); }
        if (tid==0) atomicAdd(&g_bwsum, sred[0]);
    }
}

// ---------------- attention layer 1 ----------------
__global__ void __launch_bounds__(192) k_att1(){
    __shared__ unsigned short lst[1024];
    __shared__ unsigned char  ok[1024];
    __shared__ __half wh[6*1024];
    __shared__ float sred[6][8];
    __shared__ float ssum[6];
    __shared__ float es6[6];
    __shared__ float4 sacc[2][96];
    int bs = blockIdx.x, ex = blockIdx.y, b = bs>>10;
    int tid = threadIdx.x, lane = tid&31, wid = tid>>5;
    int c1 = g_cnt[bs*4+0], c2 = g_cnt[bs*4+1], ct = g_cnt[bs*4+2];
    int lo, hi;
    if      (ex==0){ lo=0;  hi=ct; }
    else if (ex==1){ lo=0;  hi=c1; }
    else if (ex==2){ lo=c1; hi=c2; }
    else           { lo=c2; hi=ct; }
    int n = hi-lo;
    __half* h1row = g_h1h + ((size_t)ex*BSq + bs)*NHq;
    if (n==0){
        if (tid<96){
            float4 hv = *(const float4*)&g_hsum[(size_t)((ex<<2)|b)*NHq + tid*4];
            *(__half2*)&h1row[tid*4]   = __float22half2_rn(make_float2(elu1(hv.x*(1.f/Sq)), elu1(hv.y*(1.f/Sq))));
            *(__half2*)&h1row[tid*4+2] = __float22half2_rn(make_float2(elu1(hv.z*(1.f/Sq)), elu1(hv.w*(1.f/Sq))));
        }
        return;
    }
    for (int j=tid;j<n;j+=192) lst[j] = g_lst[(size_t)bs*Sq + lo + j];
    if (tid<6) es6[tid] = g_es[((size_t)ex*BSq + bs)*8 + tid];
    __syncthreads();
    const float* edb = g_ed + ((size_t)ex*BSq + ((size_t)b<<10))*8;
    const unsigned char* rm = (ex>0)? g_rmask + (size_t)(ex-1)*BSq + (b<<10) : nullptr;
    float mx[6];
    #pragma unroll
    for (int h=0;h<6;h++) mx[h] = -1e30f;
    for (int j=tid;j<n;j+=192){
        int nb = lst[j];
        float4 e0 = *(const float4*)&edb[nb*8];
        float2 e1 = *(const float2*)&edb[nb*8+4];
        ok[j] = rm ? rm[nb] : 1;
        float ev[6] = {e0.x,e0.y,e0.z,e0.w,e1.x,e1.y};
        #pragma unroll
        for (int h=0;h<6;h++){
            float e = leaky02(es6[h] + ev[h]);
            wh[h*1024+j] = __float2half(e);
            mx[h] = fmaxf(mx[h], e);
        }
    }
    #pragma unroll
    for (int h=0;h<6;h++){
        #pragma unroll
        for (int o=16;o>0;o>>=1) mx[h] = fmaxf(mx[h], __shfl_xor_sync(0xffffffffu, mx[h], o));
    }
    if (lane==0){
        #pragma unroll
        for (int h=0;h<6;h++) sred[h][wid] = mx[h];
    }
    __syncthreads();
    float mxv[6];
    #pragma unroll
    for (int h=0;h<6;h++){
        float m = sred[h][0];
        #pragma unroll
        for (int wdx=1; wdx<6; wdx++) m = fmaxf(m, sred[h][wdx]);
        mxv[h] = m;
    }
    __syncthreads();
    float sm[6] = {0.f,0.f,0.f,0.f,0.f,0.f};
    for (int j=tid;j<n;j+=192){
        #pragma unroll
        for (int h=0;h<6;h++){
            float ww = expf(__half2float(wh[h*1024+j]) - mxv[h]);
            wh[h*1024+j] = __float2half(ww);
            sm[h] += ww;
        }
    }
    #pragma unroll
    for (int h=0;h<6;h++){
        #pragma unroll
        for (int o=16;o>0;o>>=1) sm[h] += __shfl_xor_sync(0xffffffffu, sm[h], o);
    }
    if (lane==0){
        #pragma unroll
        for (int h=0;h<6;h++) sred[h][wid] = sm[h];
    }
    __syncthreads();
    if (tid<6){
        float s = sred[tid][0];
        #pragma unroll
        for (int wdx=1; wdx<6; wdx++) s += sred[tid][wdx];
        ssum[tid] = s;
    }
    __syncthreads();
    {
        int col = tid % 96, grp = tid / 96;
        int h = col >> 4;
        const __half* hb = g_hh + ((size_t)ex*BSq + ((size_t)b<<10))*NHq;
        float ax=0.f, ay=0.f, az=0.f, aw=0.f;
        if (ex==0){
            int j = grp;
            for (; j+2 < n; j += 4){
                float w0 = __half2float(wh[h*1024+j]);
                float w1 = __half2float(wh[h*1024+j+2]);
                uint2 r0 = *(const uint2*)&hb[(size_t)lst[j]*NHq   + col*4];
                uint2 r1 = *(const uint2*)&hb[(size_t)lst[j+2]*NHq + col*4];
                float2 p00 = __half22float2(*(__half2*)&r0.x);
                float2 p01 = __half22float2(*(__half2*)&r0.y);
                float2 p10 = __half22float2(*(__half2*)&r1.x);
                float2 p11 = __half22float2(*(__half2*)&r1.y);
                ax += w0*p00.x + w1*p10.x; ay += w0*p00.y + w1*p10.y;
                az += w0*p01.x + w1*p11.x; aw += w0*p01.y + w1*p11.y;
            }
            for (; j < n; j += 2){
                float w0 = __half2float(wh[h*1024+j]);
                uint2 r0 = *(const uint2*)&hb[(size_t)lst[j]*NHq + col*4];
                float2 p00 = __half22float2(*(__half2*)&r0.x);
                float2 p01 = __half22float2(*(__half2*)&r0.y);
                ax += w0*p00.x; ay += w0*p00.y; az += w0*p01.x; aw += w0*p01.y;
            }
        } else {
            for (int j=grp; j<n; j+=2){
                if (!ok[j]) continue;   // uniform across grp-group: real load skip
                float w0 = __half2float(wh[h*1024+j]);
                uint2 r0 = *(const uint2*)&hb[(size_t)lst[j]*NHq + col*4];
                float2 p00 = __half22float2(*(__half2*)&r0.x);
                float2 p01 = __half22float2(*(__half2*)&r0.y);
                ax += w0*p00.x; ay += w0*p00.y; az += w0*p01.x; aw += w0*p01.y;
            }
        }
        sacc[grp][col] = make_float4(ax,ay,az,aw);
    }
    __syncthreads();
    if (tid<96){
        int h = tid >> 4;
        float inv = 1.f/ssum[h];
        float4 a0 = sacc[0][tid], a1 = sacc[1][tid];
        *(__half2*)&h1row[tid*4]   = __float22half2_rn(make_float2(elu1((a0.x+a1.x)*inv), elu1((a0.y+a1.y)*inv)));
        *(__half2*)&h1row[tid*4+2] = __float22half2_rn(make_float2(elu1((a0.z+a1.z)*inv), elu1((a0.w+a1.w)*inv)));
    }
}

// ---------------- attention layer 2 ----------------
__global__ void __launch_bounds__(256) k_att2(){
    __shared__ unsigned short lst[1024];
    __shared__ float w[1024];
    __shared__ float red[256];
    __shared__ float4 sacc[4][64];
    int bs = blockIdx.x, ex = blockIdx.y, b = bs>>10;
    int tid = threadIdx.x;
    if (ex>0 && g_rmask[(size_t)(ex-1)*BSq + bs]==0) return;
    float* outb = (ex==0)? g_main : g_depE + (size_t)(ex-1)*BSDq;
    int c1 = g_cnt[bs*4+0], c2 = g_cnt[bs*4+1], ct = g_cnt[bs*4+2];
    int lo, hi;
    if      (ex==0){ lo=0;  hi=ct; }
    else if (ex==1){ lo=0;  hi=c1; }
    else if (ex==2){ lo=c1; hi=c2; }
    else           { lo=c2; hi=ct; }
    int n = hi-lo;
    if (n==0){
        if (tid<64){
            float4 hv = *(const float4*)&g_h2sum[(size_t)((ex<<2)|b)*Dq + tid*4];
            *(float4*)&outb[(size_t)bs*Dq + tid*4] =
                make_float4(hv.x*(1.f/Sq), hv.y*(1.f/Sq), hv.z*(1.f/Sq), hv.w*(1.f/Sq));
        }
        return;
    }
    for (int j=tid;j<n;j+=256) lst[j] = g_lst[(size_t)bs*Sq + lo + j];
    __syncthreads();
    float gsv = g_gs[(size_t)ex*BSq + bs];
    const float* gdb = g_gd + (size_t)ex*BSq + (b<<10);
    float mloc = -1e30f;
    for (int j=tid;j<n;j+=256){
        float e = leaky02(gsv + gdb[lst[j]]);
        w[j]=e;
        mloc = fmaxf(mloc,e);
    }
    red[tid]=mloc; __syncthreads();
    for (int st=128;st>0;st>>=1){ if (tid<st) red[tid]=fmaxf(red[tid],red[tid+st]); __syncthreads(); }
    float m = red[0]; __syncthreads();
    float sloc = 0.f;
    for (int j=tid;j<n;j+=256){ float ww=expf(w[j]-m); w[j]=ww; sloc+=ww; }
    red[tid]=sloc; __syncthreads();
    for (int st=128;st>0;st>>=1){ if (tid<st) red[tid]+=red[tid+st]; __syncthreads(); }
    float inv = 1.f/red[0];
    int grp = tid>>6, q = tid&63;
    const __half* h2b = g_h2h + ((size_t)ex*BSq + ((size_t)b<<10))*Dq;
    float ax=0.f, ay=0.f, az=0.f, aw=0.f;
    int j = grp;
    for (; j+4 < n; j += 8){
        float w0 = w[j], w1 = w[j+4];
        uint2 r0 = *(const uint2*)&h2b[(size_t)lst[j]*Dq   + q*4];
        uint2 r1 = *(const uint2*)&h2b[(size_t)lst[j+4]*Dq + q*4];
        float2 p00 = __half22float2(*(__half2*)&r0.x);
        float2 p01 = __half22float2(*(__half2*)&r0.y);
        float2 p10 = __half22float2(*(__half2*)&r1.x);
        float2 p11 = __half22float2(*(__half2*)&r1.y);
        ax += w0*p00.x + w1*p10.x; ay += w0*p00.y + w1*p10.y;
        az += w0*p01.x + w1*p11.x; aw += w0*p01.y + w1*p11.y;
    }
    for (; j < n; j += 4){
        float w0 = w[j];
        uint2 r0 = *(const uint2*)&h2b[(size_t)lst[j]*Dq + q*4];
        float2 p00 = __half22float2(*(__half2*)&r0.x);
        float2 p01 = __half22float2(*(__half2*)&r0.y);
        ax += w0*p00.x; ay += w0*p00.y; az += w0*p01.x; aw += w0*p01.y;
    }
    sacc[grp][q] = make_float4(ax,ay,az,aw);
    __syncthreads();
    if (tid<64){
        float4 a0=sacc[0][tid], a1=sacc[1][tid], a2=sacc[2][tid], a3=sacc[3][tid];
        *(float4*)&outb[(size_t)bs*Dq + tid*4] =
            make_float4((a0.x+a1.x+a2.x+a3.x)*inv, (a0.y+a1.y+a2.y+a3.y)*inv,
                        (a0.z+a1.z+a2.z+a3.z)*inv, (a0.w+a1.w+a2.w+a3.w)*inv);
    }
}

// ---------------- final blend ----------------
__global__ void k_final(float* __restrict__ out){
    __shared__ unsigned char msk[3];
    int bs = blockIdx.x, d = threadIdx.x;
    if (d<3) msk[d] = g_rmask[d*BSq+bs];
    __syncthreads();
    size_t i = (size_t)bs*Dq + d;
    float dep = 0.f;
    if (msk[0]) dep += g_depE[i];
    if (msk[1]) dep += g_depE[BSDq + i];
    if (msk[2]) dep += g_depE[2*(size_t)BSDq + i];
    float bw = g_bw[i];
    out[i] = bw*g_main[i] + (1.f-bw)*dep;
    if (bs==0 && d==0){
        float mc = g_bwsum * (1.f/(float)BSDq);
        out[BSDq]   = fabsf(mc - 0.6f) * 0.01f;
        out[BSDq+1] = mc;
    }
}

// ---------------- host launcher ----------------
extern "C" void kernel_launch(void* const* d_in, const int* in_sizes, int n_in,
                              void* d_out, int out_size){
    const float* feature  = (const float*)d_in[0];
    const float* adj      = (const float*)d_in[1];
    const float* main_W1  = (const float*)d_in[2];
    const float* main_a1s = (const float*)d_in[3];
    const float* main_a1d = (const float*)d_in[4];
    const float* main_W2  = (const float*)d_in[5];
    const float* main_a2s = (const float*)d_in[6];
    const float* main_a2d = (const float*)d_in[7];
    const float* dep_W1   = (const float*)d_in[8];
    const float* dep_a1s  = (const float*)d_in[9];
    const float* dep_a1d  = (const float*)d_in[10];
    const float* dep_W2   = (const float*)d_in[11];
    const float* dep_a2s  = (const float*)d_in[12];
    const float* dep_a2d  = (const float*)d_in[13];
    const float* router_W = (const float*)d_in[14];
    const float* blend_W  = (const float*)d_in[15];
    const float* blend_b  = (const float*)d_in[16];
    const int*   doc_num  = (const int*)d_in[17];
    const int*   sect_num = (const int*)d_in[18];
    float* out = (float*)d_out;

    __half* feat_h;  cudaGetSymbolAddress((void**)&feat_h,  g_feat_h);
    __half* W1t_h;   cudaGetSymbolAddress((void**)&W1t_h,   g_W1t_h);
    __half* W2t_h;   cudaGetSymbolAddress((void**)&W2t_h,   g_W2t_h);
    __half* bWt_h;   cudaGetSymbolAddress((void**)&bWt_h,   g_bWt_h);
    __half* h1h_p;   cudaGetSymbolAddress((void**)&h1h_p,   g_h1h);
    float*  bw_p;    cudaGetSymbolAddress((void**)&bw_p,    g_bw);
    __half* hh_p;    cudaGetSymbolAddress((void**)&hh_p,    g_hh);
    __half* h2h_p;   cudaGetSymbolAddress((void**)&h2h_p,   g_h2h);

    k_prep<<<dim3(BSq*Dq/256, 6), 256>>>(feature, main_W1, dep_W1, main_W2, dep_W2, blend_W, router_W);
    k_nbr<<<BSq, 256>>>(adj, doc_num, sect_num);

    k_mmh<Dq, Dq, false, true, 0><<<dim3(4,32,1), 256>>>(feat_h, 0, bWt_h, bw_p, (__half*)0, blend_b,
                                                         (const float*)0,(const float*)0,(const float*)0,(const float*)0);

    k_mmh<Dq, NHq, true, false, 1><<<dim3(6,32,NEXP), 256>>>(feat_h, 0, W1t_h, (float*)0, hh_p, (const float*)0,
                                                             main_a1s, dep_a1s, main_a1d, dep_a1d);
    k_att1<<<dim3(BSq, NEXP), 192>>>();

    k_mmh<NHq, Dq, false, false, 2><<<dim3(4,32,NEXP), 256>>>(h1h_p, (size_t)BSq*NHq, W2t_h, (float*)0, h2h_p, (const float*)0,
                                                              main_a2s, dep_a2s, main_a2d, dep_a2d);
    k_att2<<<dim3(BSq, NEXP), 256>>>();

    k_final<<<BSq, Dq>>>(out);
}

// round 13
// speedup vs baseline: 2.3791x; 1.0123x over previous
#include <cuda_runtime.h>
#include <cuda_fp16.h>
#include <math.h>

// Fixed shapes
#define Bq 4
#define Sq 1024
#define Dq 256
#define Hq 6
#define HDq 64
#define NHq 384          // H*Hd
#define BSq 4096         // B*S
#define BSDq (BSq*Dq)
#define NEXP 4           // slot 0 = main, 1..3 = deputies

// ---------------- scratch ----------------
__device__ __half g_hh [(size_t)NEXP*BSq*NHq];
__device__ __half g_h1h[(size_t)NEXP*BSq*NHq];
__device__ __half g_h2h[(size_t)NEXP*BSq*Dq];
__device__ float  g_es [NEXP*BSq*8];
__device__ __half g_edh[NEXP*BSq*8];             // packed fp16 ed (6 used of 8)
__device__ float  g_hsum [NEXP*Bq*NHq];
__device__ float  g_h2sum[NEXP*Bq*Dq];
__device__ float  g_gs [NEXP*BSq];
__device__ float  g_gd [NEXP*BSq];
__device__ __half g_feat_h[(size_t)BSq*Dq];
__device__ __half g_W1t_h[(size_t)NEXP*NHq*Dq];  // [e][n][k]
__device__ __half g_W2t_h[(size_t)NEXP*Dq*NHq];  // [e][n][k]
__device__ __half g_bWt_h[(size_t)Dq*Dq];        // [n][k]
__device__ float  g_main[BSDq];
__device__ float  g_depE[3*(size_t)BSDq];
__device__ float  g_bw  [BSDq];
__device__ float  g_bwsum;
__device__ unsigned char  g_rmask[3*BSq];
__device__ unsigned short g_lst[(size_t)BSq*Sq];
__device__ int g_cnt[BSq*4];

__device__ __forceinline__ float leaky02(float x){ return x > 0.f ? x : 0.2f*x; }
__device__ __forceinline__ float elu1(float x){ return x > 0.f ? x : expm1f(x); }
__device__ __forceinline__ void mma_f16(float c[4], unsigned a0,unsigned a1,unsigned a2,unsigned a3,
                                        unsigned b0,unsigned b1){
    asm volatile("mma.sync.aligned.m16n8k16.row.col.f32.f16.f16.f32 "
        "{%0,%1,%2,%3},{%4,%5,%6,%7},{%8,%9},{%0,%1,%2,%3};"
        : "+f"(c[0]),"+f"(c[1]),"+f"(c[2]),"+f"(c[3])
        : "r"(a0),"r"(a1),"r"(a2),"r"(a3),"r"(b0),"r"(b1));
}
#define LDSM4(r0,r1,r2,r3,a) \
    asm volatile("ldmatrix.sync.aligned.m8n8.x4.shared.b16 {%0,%1,%2,%3},[%4];" \
        : "=r"(r0),"=r"(r1),"=r"(r2),"=r"(r3) : "r"(a))
#define CPA16(dst,src,sz) \
    asm volatile("cp.async.cg.shared.global [%0], [%1], 16, %2;" :: "r"(dst),"l"(src),"r"(sz))
#define CPA_COMMIT() asm volatile("cp.async.commit_group;")

// ---------------- setup: prep (coalesced transposes) + router + zero + nbr ----------
__global__ void k_prep(const float* __restrict__ feature,
                       const float* __restrict__ mainW1, const float* __restrict__ depW1,
                       const float* __restrict__ mainW2, const float* __restrict__ depW2,
                       const float* __restrict__ blendW, const float* __restrict__ Wr,
                       const float* __restrict__ adj, const int* __restrict__ dnum,
                       const int* __restrict__ snum){
    __shared__ float tile[32][33];
    __shared__ int wtot[8], wpre[8], r1t[8], r2t[8];
    int task = blockIdx.y;
    int tid  = threadIdx.x;
    int i = blockIdx.x*256 + tid;
    int c = tid & 31, ty = tid >> 5;
    if (task == 0){
        g_feat_h[i] = __float2half(feature[i]);
    } else if (task == 1){
        // W1t: per (e,h): transpose [Dq x 64] -> [64 x Dq]; 384 tiles of 32x32
        int t = blockIdx.x;
        if (t >= NEXP*Hq*16) return;
        int e = t/(Hq*16), r1 = t%(Hq*16), h = r1/16, r2 = r1%16;
        int k0 = (r2>>1)*32, o0 = (r2&1)*32;
        const float* src = ((e==0)? mainW1 : depW1 + (size_t)(e-1)*Hq*Dq*HDq) + (size_t)h*Dq*HDq;
        #pragma unroll
        for (int rr=0;rr<4;rr++){
            int kr = ty + rr*8;
            tile[kr][c] = src[(size_t)(k0+kr)*HDq + o0 + c];
        }
        __syncthreads();
        __half* dst = g_W1t_h + (size_t)e*NHq*Dq;
        #pragma unroll
        for (int rr=0;rr<4;rr++){
            int orow = ty + rr*8;
            dst[(size_t)(h*64 + o0 + orow)*Dq + k0 + c] = __float2half(tile[c][orow]);
        }
    } else if (task == 2){
        // W2t: per e: transpose [NHq x Dq] -> [Dq x NHq]; 384 tiles
        int t = blockIdx.x;
        if (t >= NEXP*96) return;
        int e = t/96, r1 = t%96;
        int k0 = (r1>>3)*32, n0 = (r1&7)*32;
        const float* src = (e==0)? mainW2 : depW2 + (size_t)(e-1)*NHq*Dq;
        #pragma unroll
        for (int rr=0;rr<4;rr++){
            int kr = ty + rr*8;
            tile[kr][c] = src[(size_t)(k0+kr)*Dq + n0 + c];
        }
        __syncthreads();
        __half* dst = g_W2t_h + (size_t)e*Dq*NHq;
        #pragma unroll
        for (int rr=0;rr<4;rr++){
            int orow = ty + rr*8;
            dst[(size_t)(n0 + orow)*NHq + k0 + c] = __float2half(tile[c][orow]);
        }
    } else if (task == 3){
        int t = blockIdx.x;
        if (t >= 64) return;
        int k0 = (t>>3)*32, n0 = (t&7)*32;
        #pragma unroll
        for (int rr=0;rr<4;rr++){
            int kr = ty + rr*8;
            tile[kr][c] = blendW[(size_t)(k0+kr)*Dq + n0 + c];
        }
        __syncthreads();
        #pragma unroll
        for (int rr=0;rr<4;rr++){
            int orow = ty + rr*8;
            g_bWt_h[(size_t)(n0 + orow)*Dq + k0 + c] = __float2half(tile[c][orow]);
        }
    } else if (task == 4){
        int gw = blockIdx.x*8 + ty;
        if (gw >= BSq) return;
        const float* xr = feature + (size_t)gw*Dq;
        float a0=0.f,a1=0.f,a2=0.f;
        for (int k=c;k<Dq;k+=32){
            float xv = xr[k];
            a0 += xv*Wr[k*3+0]; a1 += xv*Wr[k*3+1]; a2 += xv*Wr[k*3+2];
        }
        #pragma unroll
        for (int o=16;o>0;o>>=1){
            a0 += __shfl_down_sync(0xffffffffu,a0,o);
            a1 += __shfl_down_sync(0xffffffffu,a1,o);
            a2 += __shfl_down_sync(0xffffffffu,a2,o);
        }
        if (c==0){
            float v[3]={a0,a1,a2};
            int ex=0; float mv=v[0];
            #pragma unroll
            for (int e=1;e<3;e++) if (v[e]<=mv){ mv=v[e]; ex=e; }
            #pragma unroll
            for (int e=0;e<3;e++) g_rmask[e*BSq+gw] = (e==ex)?0:1;
        }
    } else if (task == 5){
        if (i < NEXP*BSq){ g_gs[i]=0.f; g_gd[i]=0.f; }
        if (i < NEXP*Bq*NHq) g_hsum[i]=0.f;
        if (i < NEXP*Bq*Dq)  g_h2sum[i]=0.f;
        if (i==0) g_bwsum = 0.f;
    } else {
        // neighbor lists (one block per bs row)
        int bs = blockIdx.x, lane = c, wid = ty;
        int doc = dnum[0], sect = snum[0];
        int lim1 = Sq - sect - doc, lim2 = Sq - doc;
        const float* arow = adj + (size_t)bs*Sq;
        float4 a = *(const float4*)(arow + tid*4);
        unsigned short loc[4]; int cc=0, ca=0, cb=0;
        float av[4] = {a.x,a.y,a.z,a.w};
        #pragma unroll
        for (int ii=0;ii<4;ii++){
            int col = tid*4+ii;
            if (av[ii] > 0.f){ loc[cc++] = (unsigned short)col; ca += (col<lim1); cb += (col<lim2); }
        }
        int scan = cc;
        #pragma unroll
        for (int off=1; off<32; off<<=1){
            int v = __shfl_up_sync(0xffffffffu, scan, off);
            if (lane>=off) scan += v;
        }
        int wca = __reduce_add_sync(0xffffffffu, (unsigned)ca);
        int wcb = __reduce_add_sync(0xffffffffu, (unsigned)cb);
        if (lane==31) wtot[wid] = scan;
        if (lane==0){ r1t[wid]=wca; r2t[wid]=wcb; }
        __syncthreads();
        if (tid==0){
            int acc=0, sa=0, sb=0;
            #pragma unroll
            for (int wdx=0; wdx<8; wdx++){
                wpre[wdx]=acc; acc+=wtot[wdx]; sa+=r1t[wdx]; sb+=r2t[wdx];
            }
            g_cnt[bs*4+0]=sa; g_cnt[bs*4+1]=sb; g_cnt[bs*4+2]=acc; g_cnt[bs*4+3]=0;
        }
        __syncthreads();
        int base = wpre[wid] + scan - cc;
        for (int ii=0;ii<cc;ii++) g_lst[(size_t)bs*Sq + base + ii] = loc[ii];
    }
}

// ---------------- fp16 GEMM: 128x64 tile, 3-stage cp.async, 1 sync/iter ----------
template<int KD, int ND, bool MASK, bool SIG, int DOT>
__global__ void __launch_bounds__(256) k_mmh(const __half* __restrict__ Abase, size_t astride,
                                             const __half* __restrict__ Btbase,
                                             float* __restrict__ Cbase, __half* __restrict__ Chbase,
                                             const float* __restrict__ bias,
                                             const float* __restrict__ asM, const float* __restrict__ asD,
                                             const float* __restrict__ adM, const float* __restrict__ adD){
    int e = blockIdx.z;
    const __half* A  = Abase + astride*e;
    const __half* Bt = Btbase + (size_t)e*ND*KD;
    float* Cf = Cbase ? Cbase + (size_t)e*BSq*ND : (float*)0;
    __half* Ch = Chbase ? Chbase + (size_t)e*BSq*ND : (__half*)0;
    int m0 = blockIdx.y*128, n0 = blockIdx.x*64;
    __shared__ __half2 As2[3][128][20];
    __shared__ __half2 Bs2[3][64][20];
    __shared__ float sred[256];
    __shared__ float sAs[64], sAd[64];
    __shared__ float sdot[256];
    __shared__ float scol[64];
    int tid=threadIdx.x, lane=tid&31, wid=tid>>5;
    int wm=(wid&3)*32, wn=(wid>>2)*32;
    int gid=lane>>2, qid=lane&3;
    bool docs = (DOT!=0) && (e>0);
    if (DOT){
        if (tid<64){
            const float* as = (e==0)? asM : asD + (size_t)(e-1)*ND;
            const float* ad = (e==0)? adM : adD + (size_t)(e-1)*ND;
            sAs[tid] = as[n0+tid];
            sAd[tid] = ad[n0+tid];
            scol[tid] = 0.f;
        }
        sdot[tid] = 0.f;
    }
    float c[2][4][4];
    #pragma unroll
    for (int mt=0;mt<2;mt++)
        #pragma unroll
        for (int nt=0;nt<4;nt++)
            #pragma unroll
            for (int r=0;r<4;r++) c[mt][nt][r]=0.f;
    int rowA = tid>>1;
    int khA  = (tid&1)*16;
    int kcA  = (tid&1)*8;
    int rowB = tid>>2;
    int khB  = (tid&3)*8;
    int kcB  = (tid&3)*4;
    bool amask = true;
    if (MASK){ if (e>0 && g_rmask[(size_t)(e-1)*BSq + m0 + rowA]==0) amask = false; }
    const __half* Ap  = A  + (size_t)(m0+rowA)*KD + khA;
    const __half* Btp = Bt + (size_t)(n0+rowB)*KD + khB;
    int szA = (MASK && !amask) ? 0 : 16;

    unsigned As_base = (unsigned)__cvta_generic_to_shared(&As2[0][0][0]);
    unsigned Bs_base = (unsigned)__cvta_generic_to_shared(&Bs2[0][0][0]);
    const unsigned STG_A = 128u*20u*4u;
    const unsigned STG_B = 64u*20u*4u;
    unsigned dstA = As_base + (unsigned)(rowA*20 + kcA)*4u;
    unsigned dstB = Bs_base + (unsigned)(rowB*20 + kcB)*4u;

#define PREFETCH(P, K0) { \
    CPA16(dstA + (unsigned)(P)*STG_A,      Ap  + (K0),     szA); \
    CPA16(dstA + (unsigned)(P)*STG_A + 16, Ap  + (K0) + 8, szA); \
    CPA16(dstB + (unsigned)(P)*STG_B,      Btp + (K0),     16); \
    CPA_COMMIT(); }

    int lr8 = lane & 7;
    int a_row = wm + lr8 + ((lane>>3)&1)*8;
    int a_kof = ((lane>>4)&1)*8;
    int b_col = wn + lr8 + ((lane>>4)&1)*8;
    int b_kof = ((lane>>3)&1)*8;
    unsigned aAddr0 = As_base + (unsigned)(a_row*40 + a_kof)*2u;
    unsigned bAddr0 = Bs_base + (unsigned)(b_col*40 + b_kof)*2u;

    const int NT = KD/32;
    PREFETCH(0, 0);
    PREFETCH(1, 32);
    int stage = 0, pstage = 2;
    for (int it=0; it<NT; it++){
        if (it+2 < NT) asm volatile("cp.async.wait_group 1;");
        else           asm volatile("cp.async.wait_group 0;");
        __syncthreads();
        if (it+2 < NT){
            PREFETCH(pstage, (it+2)*32);
            pstage = (pstage+1 == 3) ? 0 : pstage+1;
        }
        unsigned stA = (unsigned)stage*STG_A;
        unsigned stB = (unsigned)stage*STG_B;
        stage = (stage+1 == 3) ? 0 : stage+1;
        #pragma unroll
        for (int sub=0; sub<2; sub++){
            unsigned af[2][4], bf[2][4];
            #pragma unroll
            for (int mt=0;mt<2;mt++){
                unsigned ad = aAddr0 + stA + (unsigned)(mt*16*40 + sub*16)*2u;
                LDSM4(af[mt][0],af[mt][1],af[mt][2],af[mt][3], ad);
            }
            #pragma unroll
            for (int ntp=0;ntp<2;ntp++){
                unsigned bd = bAddr0 + stB + (unsigned)(ntp*16*40 + sub*16)*2u;
                LDSM4(bf[ntp][0],bf[ntp][1],bf[ntp][2],bf[ntp][3], bd);
            }
            #pragma unroll
            for (int mt=0;mt<2;mt++)
                #pragma unroll
                for (int nt=0;nt<4;nt++)
                    mma_f16(c[mt][nt], af[mt][0],af[mt][1],af[mt][2],af[mt][3],
                            bf[nt>>1][(nt&1)*2], bf[nt>>1][(nt&1)*2+1]);
        }
    }
#undef PREFETCH
    float lsum = 0.f;
    float colp[8];
    #pragma unroll
    for (int i=0;i<8;i++) colp[i]=0.f;
    #pragma unroll
    for (int mt=0;mt<2;mt++){
        int orow = m0 + wm + mt*16 + gid;
        float ds0=0.f, dd0=0.f, ds1=0.f, dd1=0.f;
        #pragma unroll
        for (int nt=0;nt<4;nt++){
            int lcol = wn + nt*8 + qid*2;
            int col = n0 + lcol;
            float2 v0 = make_float2(c[mt][nt][0], c[mt][nt][1]);
            float2 v1 = make_float2(c[mt][nt][2], c[mt][nt][3]);
            if (SIG){
                float b0v = bias[col], b1v = bias[col+1];
                v0.x = 1.f/(1.f+expf(-(v0.x+b0v))); v0.y = 1.f/(1.f+expf(-(v0.y+b1v)));
                v1.x = 1.f/(1.f+expf(-(v1.x+b0v))); v1.y = 1.f/(1.f+expf(-(v1.y+b1v)));
                lsum += v0.x+v0.y+v1.x+v1.y;
            }
            if (DOT){
                float a0=sAs[lcol], a1=sAs[lcol+1], d0=sAd[lcol], d1=sAd[lcol+1];
                ds0 += v0.x*a0 + v0.y*a1;  dd0 += v0.x*d0 + v0.y*d1;
                ds1 += v1.x*a0 + v1.y*a1;  dd1 += v1.x*d0 + v1.y*d1;
                if (docs){
                    colp[nt*2]   += v0.x + v1.x;
                    colp[nt*2+1] += v0.y + v1.y;
                }
            }
            if (Cf){
                *(float2*)&Cf[(size_t)orow*ND + col]     = v0;
                *(float2*)&Cf[(size_t)(orow+8)*ND + col] = v1;
            }
            if (Ch){
                *(__half2*)&Ch[(size_t)orow*ND + col]     = __float22half2_rn(v0);
                *(__half2*)&Ch[(size_t)(orow+8)*ND + col] = __float22half2_rn(v1);
            }
        }
        if (DOT){
            ds0 += __shfl_down_sync(0xffffffffu, ds0, 2, 4); ds0 += __shfl_down_sync(0xffffffffu, ds0, 1, 4);
            dd0 += __shfl_down_sync(0xffffffffu, dd0, 2, 4); dd0 += __shfl_down_sync(0xffffffffu, dd0, 1, 4);
            ds1 += __shfl_down_sync(0xffffffffu, ds1, 2, 4); ds1 += __shfl_down_sync(0xffffffffu, ds1, 1, 4);
            dd1 += __shfl_down_sync(0xffffffffu, dd1, 2, 4); dd1 += __shfl_down_sync(0xffffffffu, dd1, 1, 4);
            if (qid==0){
                int rl = wm + mt*16 + gid;
                atomicAdd(&sdot[rl],     ds0); atomicAdd(&sdot[rl+8],     ds1);
                atomicAdd(&sdot[128+rl], dd0); atomicAdd(&sdot[128+rl+8], dd1);
            }
        }
    }
    if (docs){
        #pragma unroll
        for (int i=0;i<8;i++){
            colp[i] += __shfl_down_sync(0xffffffffu, colp[i], 16);
            colp[i] += __shfl_down_sync(0xffffffffu, colp[i], 8);
            colp[i] += __shfl_down_sync(0xffffffffu, colp[i], 4);
        }
        if (lane < 4){
            #pragma unroll
            for (int nt=0;nt<4;nt++){
                atomicAdd(&scol[wn + nt*8 + qid*2],     colp[nt*2]);
                atomicAdd(&scol[wn + nt*8 + qid*2 + 1], colp[nt*2+1]);
            }
        }
    }
    if (DOT){
        __syncthreads();
        if (tid<128){
            if (DOT==1){
                size_t idx = ((size_t)e*BSq + m0 + tid)*8 + (n0>>6);
                g_es[idx]  = sdot[tid];
                g_edh[idx] = __float2half(sdot[128+tid]);
            } else {
                atomicAdd(&g_gs[(size_t)e*BSq + m0 + tid], sdot[tid]);
                atomicAdd(&g_gd[(size_t)e*BSq + m0 + tid], sdot[128+tid]);
            }
        }
        if (docs && tid<64){
            int eb = e*Bq + (m0>>10);
            if (DOT==1) atomicAdd(&g_hsum [(size_t)eb*NHq + n0 + tid], scol[tid]);
            else        atomicAdd(&g_h2sum[(size_t)eb*Dq  + n0 + tid], scol[tid]);
        }
    }
    if (SIG){
        sred[tid] = lsum;
        __syncthreads();
        for (int st=128; st>0; st>>=1){ if (tid<st) sred[tid]+=sred[tid+st]; __syncthreads(); }
        if (tid==0) atomicAdd(&g_bwsum, sred[0]);
    }
}

// ---------------- attention layer 1 ----------------
__global__ void __launch_bounds__(192) k_att1(){
    __shared__ unsigned short lst[1024];
    __shared__ unsigned char  ok[1024];
    __shared__ __half wh[6*1024];
    __shared__ float sred[6][8];
    __shared__ float ssum[6];
    __shared__ float es6[6];
    __shared__ float4 sacc[2][96];
    int bs = blockIdx.x, ex = blockIdx.y, b = bs>>10;
    int tid = threadIdx.x, lane = tid&31, wid = tid>>5;
    int c1 = g_cnt[bs*4+0], c2 = g_cnt[bs*4+1], ct = g_cnt[bs*4+2];
    int lo, hi;
    if      (ex==0){ lo=0;  hi=ct; }
    else if (ex==1){ lo=0;  hi=c1; }
    else if (ex==2){ lo=c1; hi=c2; }
    else           { lo=c2; hi=ct; }
    int n = hi-lo;
    __half* h1row = g_h1h + ((size_t)ex*BSq + bs)*NHq;
    if (n==0){
        if (tid<96){
            float4 hv = *(const float4*)&g_hsum[(size_t)((ex<<2)|b)*NHq + tid*4];
            *(__half2*)&h1row[tid*4]   = __float22half2_rn(make_float2(elu1(hv.x*(1.f/Sq)), elu1(hv.y*(1.f/Sq))));
            *(__half2*)&h1row[tid*4+2] = __float22half2_rn(make_float2(elu1(hv.z*(1.f/Sq)), elu1(hv.w*(1.f/Sq))));
        }
        return;
    }
    for (int j=tid;j<n;j+=192) lst[j] = g_lst[(size_t)bs*Sq + lo + j];
    if (tid<6) es6[tid] = g_es[((size_t)ex*BSq + bs)*8 + tid];
    __syncthreads();
    const __half* edb = g_edh + ((size_t)ex*BSq + ((size_t)b<<10))*8;
    const unsigned char* rm = (ex>0)? g_rmask + (size_t)(ex-1)*BSq + (b<<10) : nullptr;
    float mx[6];
    #pragma unroll
    for (int h=0;h<6;h++) mx[h] = -1e30f;
    for (int j=tid;j<n;j+=192){
        int nb = lst[j];
        uint4 raw = *(const uint4*)&edb[nb*8];
        ok[j] = rm ? rm[nb] : 1;
        float2 q0 = __half22float2(*(__half2*)&raw.x);
        float2 q1 = __half22float2(*(__half2*)&raw.y);
        float2 q2 = __half22float2(*(__half2*)&raw.z);
        float ev[6] = {q0.x,q0.y,q1.x,q1.y,q2.x,q2.y};
        #pragma unroll
        for (int h=0;h<6;h++){
            float e = leaky02(es6[h] + ev[h]);
            wh[h*1024+j] = __float2half(e);
            mx[h] = fmaxf(mx[h], e);
        }
    }
    #pragma unroll
    for (int h=0;h<6;h++){
        #pragma unroll
        for (int o=16;o>0;o>>=1) mx[h] = fmaxf(mx[h], __shfl_xor_sync(0xffffffffu, mx[h], o));
    }
    if (lane==0){
        #pragma unroll
        for (int h=0;h<6;h++) sred[h][wid] = mx[h];
    }
    __syncthreads();
    float mxv[6];
    #pragma unroll
    for (int h=0;h<6;h++){
        float m = sred[h][0];
        #pragma unroll
        for (int wdx=1; wdx<6; wdx++) m = fmaxf(m, sred[h][wdx]);
        mxv[h] = m;
    }
    __syncthreads();
    float sm[6] = {0.f,0.f,0.f,0.f,0.f,0.f};
    for (int j=tid;j<n;j+=192){
        #pragma unroll
        for (int h=0;h<6;h++){
            float ww = expf(__half2float(wh[h*1024+j]) - mxv[h]);
            wh[h*1024+j] = __float2half(ww);
            sm[h] += ww;
        }
    }
    #pragma unroll
    for (int h=0;h<6;h++){
        #pragma unroll
        for (int o=16;o>0;o>>=1) sm[h] += __shfl_xor_sync(0xffffffffu, sm[h], o);
    }
    if (lane==0){
        #pragma unroll
        for (int h=0;h<6;h++) sred[h][wid] = sm[h];
    }
    __syncthreads();
    if (tid<6){
        float s = sred[tid][0];
        #pragma unroll
        for (int wdx=1; wdx<6; wdx++) s += sred[tid][wdx];
        ssum[tid] = s;
    }
    __syncthreads();
    {
        int col = tid % 96, grp = tid / 96;
        int h = col >> 4;
        const __half* hb = g_hh + ((size_t)ex*BSq + ((size_t)b<<10))*NHq;
        float ax=0.f, ay=0.f, az=0.f, aw=0.f;
        if (ex==0){
            int j = grp;
            for (; j+2 < n; j += 4){
                float w0 = __half2float(wh[h*1024+j]);
                float w1 = __half2float(wh[h*1024+j+2]);
                uint2 r0 = *(const uint2*)&hb[(size_t)lst[j]*NHq   + col*4];
                uint2 r1 = *(const uint2*)&hb[(size_t)lst[j+2]*NHq + col*4];
                float2 p00 = __half22float2(*(__half2*)&r0.x);
                float2 p01 = __half22float2(*(__half2*)&r0.y);
                float2 p10 = __half22float2(*(__half2*)&r1.x);
                float2 p11 = __half22float2(*(__half2*)&r1.y);
                ax += w0*p00.x + w1*p10.x; ay += w0*p00.y + w1*p10.y;
                az += w0*p01.x + w1*p11.x; aw += w0*p01.y + w1*p11.y;
            }
            for (; j < n; j += 2){
                float w0 = __half2float(wh[h*1024+j]);
                uint2 r0 = *(const uint2*)&hb[(size_t)lst[j]*NHq + col*4];
                float2 p00 = __half22float2(*(__half2*)&r0.x);
                float2 p01 = __half22float2(*(__half2*)&r0.y);
                ax += w0*p00.x; ay += w0*p00.y; az += w0*p01.x; aw += w0*p01.y;
            }
        } else {
            for (int j=grp; j<n; j+=2){
                if (!ok[j]) continue;
                float w0 = __half2float(wh[h*1024+j]);
                uint2 r0 = *(const uint2*)&hb[(size_t)lst[j]*NHq + col*4];
                float2 p00 = __half22float2(*(__half2*)&r0.x);
                float2 p01 = __half22float2(*(__half2*)&r0.y);
                ax += w0*p00.x; ay += w0*p00.y; az += w0*p01.x; aw += w0*p01.y;
            }
        }
        sacc[grp][col] = make_float4(ax,ay,az,aw);
    }
    __syncthreads();
    if (tid<96){
        int h = tid >> 4;
        float inv = 1.f/ssum[h];
        float4 a0 = sacc[0][tid], a1 = sacc[1][tid];
        *(__half2*)&h1row[tid*4]   = __float22half2_rn(make_float2(elu1((a0.x+a1.x)*inv), elu1((a0.y+a1.y)*inv)));
        *(__half2*)&h1row[tid*4+2] = __float22half2_rn(make_float2(elu1((a0.z+a1.z)*inv), elu1((a0.w+a1.w)*inv)));
    }
}

// ---------------- attention layer 2 ----------------
__global__ void __launch_bounds__(256) k_att2(){
    __shared__ unsigned short lst[1024];
    __shared__ float w[1024];
    __shared__ float red[256];
    __shared__ float4 sacc[4][64];
    int bs = blockIdx.x, ex = blockIdx.y, b = bs>>10;
    int tid = threadIdx.x;
    if (ex>0 && g_rmask[(size_t)(ex-1)*BSq + bs]==0) return;
    float* outb = (ex==0)? g_main : g_depE + (size_t)(ex-1)*BSDq;
    int c1 = g_cnt[bs*4+0], c2 = g_cnt[bs*4+1], ct = g_cnt[bs*4+2];
    int lo, hi;
    if      (ex==0){ lo=0;  hi=ct; }
    else if (ex==1){ lo=0;  hi=c1; }
    else if (ex==2){ lo=c1; hi=c2; }
    else           { lo=c2; hi=ct; }
    int n = hi-lo;
    if (n==0){
        if (tid<64){
            float4 hv = *(const float4*)&g_h2sum[(size_t)((ex<<2)|b)*Dq + tid*4];
            *(float4*)&outb[(size_t)bs*Dq + tid*4] =
                make_float4(hv.x*(1.f/Sq), hv.y*(1.f/Sq), hv.z*(1.f/Sq), hv.w*(1.f/Sq));
        }
        return;
    }
    for (int j=tid;j<n;j+=256) lst[j] = g_lst[(size_t)bs*Sq + lo + j];
    __syncthreads();
    float gsv = g_gs[(size_t)ex*BSq + bs];
    const float* gdb = g_gd + (size_t)ex*BSq + (b<<10);
    float mloc = -1e30f;
    for (int j=tid;j<n;j+=256){
        float e = leaky02(gsv + gdb[lst[j]]);
        w[j]=e;
        mloc = fmaxf(mloc,e);
    }
    red[tid]=mloc; __syncthreads();
    for (int st=128;st>0;st>>=1){ if (tid<st) red[tid]=fmaxf(red[tid],red[tid+st]); __syncthreads(); }
    float m = red[0]; __syncthreads();
    float sloc = 0.f;
    for (int j=tid;j<n;j+=256){ float ww=expf(w[j]-m); w[j]=ww; sloc+=ww; }
    red[tid]=sloc; __syncthreads();
    for (int st=128;st>0;st>>=1){ if (tid<st) red[tid]+=red[tid+st]; __syncthreads(); }
    float inv = 1.f/red[0];
    int grp = tid>>6, q = tid&63;
    const __half* h2b = g_h2h + ((size_t)ex*BSq + ((size_t)b<<10))*Dq;
    float ax=0.f, ay=0.f, az=0.f, aw=0.f;
    int j = grp;
    for (; j+4 < n; j += 8){
        float w0 = w[j], w1 = w[j+4];
        uint2 r0 = *(const uint2*)&h2b[(size_t)lst[j]*Dq   + q*4];
        uint2 r1 = *(const uint2*)&h2b[(size_t)lst[j+4]*Dq + q*4];
        float2 p00 = __half22float2(*(__half2*)&r0.x);
        float2 p01 = __half22float2(*(__half2*)&r0.y);
        float2 p10 = __half22float2(*(__half2*)&r1.x);
        float2 p11 = __half22float2(*(__half2*)&r1.y);
        ax += w0*p00.x + w1*p10.x; ay += w0*p00.y + w1*p10.y;
        az += w0*p01.x + w1*p11.x; aw += w0*p01.y + w1*p11.y;
    }
    for (; j < n; j += 4){
        float w0 = w[j];
        uint2 r0 = *(const uint2*)&h2b[(size_t)lst[j]*Dq + q*4];
        float2 p00 = __half22float2(*(__half2*)&r0.x);
        float2 p01 = __half22float2(*(__half2*)&r0.y);
        ax += w0*p00.x; ay += w0*p00.y; az += w0*p01.x; aw += w0*p01.y;
    }
    sacc[grp][q] = make_float4(ax,ay,az,aw);
    __syncthreads();
    if (tid<64){
        float4 a0=sacc[0][tid], a1=sacc[1][tid], a2=sacc[2][tid], a3=sacc[3][tid];
        *(float4*)&outb[(size_t)bs*Dq + tid*4] =
            make_float4((a0.x+a1.x+a2.x+a3.x)*inv, (a0.y+a1.y+a2.y+a3.y)*inv,
                        (a0.z+a1.z+a2.z+a3.z)*inv, (a0.w+a1.w+a2.w+a3.w)*inv);
    }
}

// ---------------- final blend ----------------
__global__ void k_final(float* __restrict__ out){
    __shared__ unsigned char msk[3];
    int bs = blockIdx.x, d = threadIdx.x;
    if (d<3) msk[d] = g_rmask[d*BSq+bs];
    __syncthreads();
    size_t i = (size_t)bs*Dq + d;
    float dep = 0.f;
    if (msk[0]) dep += g_depE[i];
    if (msk[1]) dep += g_depE[BSDq + i];
    if (msk[2]) dep += g_depE[2*(size_t)BSDq + i];
    float bw = g_bw[i];
    out[i] = bw*g_main[i] + (1.f-bw)*dep;
    if (bs==0 && d==0){
        float mc = g_bwsum * (1.f/(float)BSDq);
        out[BSDq]   = fabsf(mc - 0.6f) * 0.01f;
        out[BSDq+1] = mc;
    }
}

// ---------------- host launcher ----------------
extern "C" void kernel_launch(void* const* d_in, const int* in_sizes, int n_in,
                              void* d_out, int out_size){
    const float* feature  = (const float*)d_in[0];
    const float* adj      = (const float*)d_in[1];
    const float* main_W1  = (const float*)d_in[2];
    const float* main_a1s = (const float*)d_in[3];
    const float* main_a1d = (const float*)d_in[4];
    const float* main_W2  = (const float*)d_in[5];
    const float* main_a2s = (const float*)d_in[6];
    const float* main_a2d = (const float*)d_in[7];
    const float* dep_W1   = (const float*)d_in[8];
    const float* dep_a1s  = (const float*)d_in[9];
    const float* dep_a1d  = (const float*)d_in[10];
    const float* dep_W2   = (const float*)d_in[11];
    const float* dep_a2s  = (const float*)d_in[12];
    const float* dep_a2d  = (const float*)d_in[13];
    const float* router_W = (const float*)d_in[14];
    const float* blend_W  = (const float*)d_in[15];
    const float* blend_b  = (const float*)d_in[16];
    const int*   doc_num  = (const int*)d_in[17];
    const int*   sect_num = (const int*)d_in[18];
    float* out = (float*)d_out;

    __half* feat_h;  cudaGetSymbolAddress((void**)&feat_h,  g_feat_h);
    __half* W1t_h;   cudaGetSymbolAddress((void**)&W1t_h,   g_W1t_h);
    __half* W2t_h;   cudaGetSymbolAddress((void**)&W2t_h,   g_W2t_h);
    __half* bWt_h;   cudaGetSymbolAddress((void**)&bWt_h,   g_bWt_h);
    __half* h1h_p;   cudaGetSymbolAddress((void**)&h1h_p,   g_h1h);
    float*  bw_p;    cudaGetSymbolAddress((void**)&bw_p,    g_bw);
    __half* hh_p;    cudaGetSymbolAddress((void**)&hh_p,    g_hh);
    __half* h2h_p;   cudaGetSymbolAddress((void**)&h2h_p,   g_h2h);

    k_prep<<<dim3(BSq*Dq/256, 7), 256>>>(feature, main_W1, dep_W1, main_W2, dep_W2,
                                         blend_W, router_W, adj, doc_num, sect_num);

    k_mmh<Dq, Dq, false, true, 0><<<dim3(4,32,1), 256>>>(feat_h, 0, bWt_h, bw_p, (__half*)0, blend_b,
                                                         (const float*)0,(const float*)0,(const float*)0,(const float*)0);

    k_mmh<Dq, NHq, true, false, 1><<<dim3(6,32,NEXP), 256>>>(feat_h, 0, W1t_h, (float*)0, hh_p, (const float*)0,
                                                             main_a1s, dep_a1s, main_a1d, dep_a1d);
    k_att1<<<dim3(BSq, NEXP), 192>>>();

    k_mmh<NHq, Dq, false, false, 2><<<dim3(4,32,NEXP), 256>>>(h1h_p, (size_t)BSq*NHq, W2t_h, (float*)0, h2h_p, (const float*)0,
                                                              main_a2s, dep_a2s, main_a2d, dep_a2d);
    k_att2<<<dim3(BSq, NEXP), 256>>>();

    k_final<<<BSq, Dq>>>(out);
}